// round 7
// baseline (speedup 1.0000x reference)
#include <cuda_runtime.h>

// Problem constants (fixed by setup_inputs)
#define Bq 16
#define LTxt 512
#define Dm 1024
#define Ntok 4096
#define Hh 16
#define DH 64
#define LMAX 256
#define LN_EPS 1e-5f

// ---------------- scratch (__device__ globals; no allocs allowed) ----------------
__device__ float g_Q[Ntok * Dm];        // 16 MB
__device__ float g_K[Bq * LTxt * Dm];   // 32 MB
__device__ float g_V[Bq * LTxt * Dm];   // 32 MB
__device__ float g_ctx[Ntok * Dm];      // 16 MB
__device__ float g_f1[Ntok * Dm];       // 16 MB (attn_out result, LN in-place)
__device__ float g_f2[Ntok * Dm];       // 16 MB (proj result)

// ---------------- SGEMM: C[M x N] = A[M x K] * B[N x K]^T + bias[N] -------------
// 128x128 tile, BK=8, 256 threads, 8x8 microtile. M%128==0, N%128==0, K%8==0.
__global__ __launch_bounds__(256, 2)
void sgemm_nt(const float* __restrict__ A, const float* __restrict__ Bw,
              const float* __restrict__ bias, float* __restrict__ C,
              int M, int Nn, int K) {
    __shared__ float As[8][132];
    __shared__ float Bs[8][132];

    const int tid = threadIdx.x;
    const int bm = blockIdx.y * 128;
    const int bn = blockIdx.x * 128;

    const int lr = tid >> 1;            // 0..127 : row within tile
    const int lc = (tid & 1) << 2;      // 0 or 4 : k offset
    const float* Aptr = A + (size_t)(bm + lr) * K + lc;
    const float* Bptr = Bw + (size_t)(bn + lr) * K + lc;

    const int tx = (tid & 15) << 2;     // col base 0..60
    const int ty = (tid >> 4) << 2;     // row base 0..60

    float acc[8][8];
#pragma unroll
    for (int i = 0; i < 8; i++)
#pragma unroll
        for (int j = 0; j < 8; j++) acc[i][j] = 0.f;

    for (int k0 = 0; k0 < K; k0 += 8) {
        // issue global loads before the barrier: overlaps with previous tile compute
        float4 av = *(const float4*)(Aptr + k0);
        float4 bv = *(const float4*)(Bptr + k0);
        __syncthreads();
        As[lc + 0][lr] = av.x; As[lc + 1][lr] = av.y;
        As[lc + 2][lr] = av.z; As[lc + 3][lr] = av.w;
        Bs[lc + 0][lr] = bv.x; Bs[lc + 1][lr] = bv.y;
        Bs[lc + 2][lr] = bv.z; Bs[lc + 3][lr] = bv.w;
        __syncthreads();
#pragma unroll
        for (int kk = 0; kk < 8; kk++) {
            float4 a0 = *(const float4*)(&As[kk][ty]);
            float4 a1 = *(const float4*)(&As[kk][ty + 64]);
            float4 b0 = *(const float4*)(&Bs[kk][tx]);
            float4 b1 = *(const float4*)(&Bs[kk][tx + 64]);
            float ar[8] = {a0.x, a0.y, a0.z, a0.w, a1.x, a1.y, a1.z, a1.w};
            float br[8] = {b0.x, b0.y, b0.z, b0.w, b1.x, b1.y, b1.z, b1.w};
#pragma unroll
            for (int i = 0; i < 8; i++)
#pragma unroll
                for (int j = 0; j < 8; j++)
                    acc[i][j] += ar[i] * br[j];
        }
    }

    const float4 bb0 = *(const float4*)(bias + bn + tx);
    const float4 bb1 = *(const float4*)(bias + bn + tx + 64);
    const float bbr[8] = {bb0.x, bb0.y, bb0.z, bb0.w, bb1.x, bb1.y, bb1.z, bb1.w};
#pragma unroll
    for (int i = 0; i < 8; i++) {
        int row = bm + ty + ((i < 4) ? i : 60 + i);   // i>=4 -> 64+(i-4)
        float* cp = C + (size_t)row * Nn + bn;
        float4 o0 = make_float4(acc[i][0] + bbr[0], acc[i][1] + bbr[1],
                                acc[i][2] + bbr[2], acc[i][3] + bbr[3]);
        float4 o1 = make_float4(acc[i][4] + bbr[4], acc[i][5] + bbr[5],
                                acc[i][6] + bbr[6], acc[i][7] + bbr[7]);
        *(float4*)(cp + tx)      = o0;
        *(float4*)(cp + tx + 64) = o1;
    }
}

// ---------------- Attention: one CTA per (qtile=64, head, batch) -----------------
#define SC_STRIDE 516   // 512 + 4 pad: softmax reads conflict-free
#define KV_PAD 68       // 64 + 4 pad: float4 stores aligned, 2-phase float2 reads

__global__ __launch_bounds__(256, 1)
void attn_kernel(const float* __restrict__ Q, const float* __restrict__ K,
                 const float* __restrict__ V, float* __restrict__ CTX) {
    extern __shared__ float sm[];
    float* s_sc = sm;                       // 64 * 516
    float* s_q  = s_sc + 64 * SC_STRIDE;    // 64 * 68  (Qs[q][d])
    float* s_kv = s_q + 64 * KV_PAD;        // 64 * 68  (Ks[d][t] then Vs[k][d])

    const int tid = threadIdx.x;
    const int w = tid >> 5, lane = tid & 31;
    const int qt = blockIdx.x, h = blockIdx.y, b = blockIdx.z;
    const int q0 = qt * 64;
    const int qb = w * 8;                   // this warp's 8 query rows

    const float* Qg = Q + (size_t)(b * LMAX + q0) * Dm + h * DH;
    const float* Kg = K + (size_t)(b * LTxt) * Dm + h * DH;
    const float* Vg = V + (size_t)(b * LTxt) * Dm + h * DH;

    const int ldr = tid >> 2;               // row 0..63 for tile loads
    const int ldf = tid & 3;                // which float4 group

    // ---- load Q tile (64 x 64) ----
    {
        const float* src = Qg + (size_t)ldr * Dm;
        float* dst = s_q + ldr * KV_PAD;
#pragma unroll
        for (int i = 0; i < 4; i++) {
            int c = (ldf + i * 4) * 4;
            *(float4*)(dst + c) = *(const float4*)(src + c);
        }
    }
    __syncthreads();

    // ---- score phase: scores[64][512] = Q K^T * 0.125 ----
    for (int kt = 0; kt < LTxt / 64; kt++) {
        {   // load K tile transposed: Ks[d][t]
            const float* src = Kg + (size_t)(kt * 64 + ldr) * Dm;
#pragma unroll
            for (int i = 0; i < 4; i++) {
                int c = (ldf + i * 4) * 4;
                float4 v = *(const float4*)(src + c);
                s_kv[(c + 0) * KV_PAD + ldr] = v.x;
                s_kv[(c + 1) * KV_PAD + ldr] = v.y;
                s_kv[(c + 2) * KV_PAD + ldr] = v.z;
                s_kv[(c + 3) * KV_PAD + ldr] = v.w;
            }
        }
        __syncthreads();

        float acc[8][2];
#pragma unroll
        for (int i = 0; i < 8; i++) { acc[i][0] = 0.f; acc[i][1] = 0.f; }

#pragma unroll 4
        for (int d = 0; d < 64; d++) {
            float2 kv = *(const float2*)(s_kv + d * KV_PAD + 2 * lane);
#pragma unroll
            for (int i = 0; i < 8; i++) {
                float qv = s_q[(qb + i) * KV_PAD + d];
                acc[i][0] += qv * kv.x;
                acc[i][1] += qv * kv.y;
            }
        }
#pragma unroll
        for (int i = 0; i < 8; i++) {
            float2 o = make_float2(acc[i][0] * 0.125f, acc[i][1] * 0.125f);
            *(float2*)(s_sc + (qb + i) * SC_STRIDE + kt * 64 + 2 * lane) = o;
        }
        __syncthreads();
    }

    // ---- softmax: 4 threads per row (quad) ----
    {
        int r = tid >> 2, j = tid & 3;
        float* row = s_sc + r * SC_STRIDE;
        float mx = -1e30f;
        for (int c = j; c < 512; c += 4) mx = fmaxf(mx, row[c]);
        mx = fmaxf(mx, __shfl_xor_sync(0xffffffffu, mx, 1));
        mx = fmaxf(mx, __shfl_xor_sync(0xffffffffu, mx, 2));
        float s = 0.f;
        for (int c = j; c < 512; c += 4) { float e = __expf(row[c] - mx); row[c] = e; s += e; }
        s += __shfl_xor_sync(0xffffffffu, s, 1);
        s += __shfl_xor_sync(0xffffffffu, s, 2);
        float inv = 1.f / s;
        for (int c = j; c < 512; c += 4) row[c] *= inv;
    }
    __syncthreads();

    // ---- ctx phase: ctx[64][64] = attn @ V ----
    float cacc[8][2];
#pragma unroll
    for (int i = 0; i < 8; i++) { cacc[i][0] = 0.f; cacc[i][1] = 0.f; }

    for (int kt = 0; kt < LTxt / 64; kt++) {
        {   // load V tile: Vs[k][d]
            const float* src = Vg + (size_t)(kt * 64 + ldr) * Dm;
            float* dst = s_kv + ldr * KV_PAD;
#pragma unroll
            for (int i = 0; i < 4; i++) {
                int c = (ldf + i * 4) * 4;
                *(float4*)(dst + c) = *(const float4*)(src + c);
            }
        }
        __syncthreads();
#pragma unroll 4
        for (int k = 0; k < 64; k++) {
            float2 vv = *(const float2*)(s_kv + k * KV_PAD + 2 * lane);
#pragma unroll
            for (int i = 0; i < 8; i++) {
                float a = s_sc[(qb + i) * SC_STRIDE + kt * 64 + k];
                cacc[i][0] += a * vv.x;
                cacc[i][1] += a * vv.y;
            }
        }
        __syncthreads();
    }

    float* Cg = CTX + (size_t)(b * LMAX + q0 + qb) * Dm + h * DH + 2 * lane;
#pragma unroll
    for (int i = 0; i < 8; i++)
        *(float2*)(Cg + (size_t)i * Dm) = make_float2(cacc[i][0], cacc[i][1]);
}

// ---------------- LayerNorm (in place, one CTA per row) --------------------------
__global__ __launch_bounds__(256)
void ln_kernel(float* __restrict__ X, const float* __restrict__ gw,
               const float* __restrict__ bw) {
    __shared__ float red[8];
    __shared__ float stat[2];
    const int tid = threadIdx.x;
    float* xp = X + (size_t)blockIdx.x * Dm + tid * 4;
    float4 v = *(const float4*)xp;

    float s = v.x + v.y + v.z + v.w;
#pragma unroll
    for (int o = 16; o; o >>= 1) s += __shfl_xor_sync(0xffffffffu, s, o);
    if ((tid & 31) == 0) red[tid >> 5] = s;
    __syncthreads();
    if (tid == 0) {
        float t = 0.f;
#pragma unroll
        for (int i = 0; i < 8; i++) t += red[i];
        stat[0] = t * (1.f / Dm);
    }
    __syncthreads();
    const float mu = stat[0];
    float d0 = v.x - mu, d1 = v.y - mu, d2 = v.z - mu, d3 = v.w - mu;

    float s2 = d0 * d0 + d1 * d1 + d2 * d2 + d3 * d3;
#pragma unroll
    for (int o = 16; o; o >>= 1) s2 += __shfl_xor_sync(0xffffffffu, s2, o);
    if ((tid & 31) == 0) red[tid >> 5] = s2;
    __syncthreads();
    if (tid == 0) {
        float t = 0.f;
#pragma unroll
        for (int i = 0; i < 8; i++) t += red[i];
        stat[1] = t * (1.f / Dm);
    }
    __syncthreads();
    const float rstd = rsqrtf(stat[1] + LN_EPS);

    float4 g4 = *(const float4*)(gw + tid * 4);
    float4 b4 = *(const float4*)(bw + tid * 4);
    v.x = d0 * rstd * g4.x + b4.x;
    v.y = d1 * rstd * g4.y + b4.y;
    v.z = d2 * rstd * g4.z + b4.z;
    v.w = d3 * rstd * g4.w + b4.w;
    *(float4*)xp = v;
}

// ---------------- segment mean: out[b][d] = mean_l f2[(b*256+l)][d] --------------
__global__ __launch_bounds__(256)
void seg_mean_kernel(const float* __restrict__ X, float* __restrict__ out) {
    const int b = blockIdx.y;
    const int d = blockIdx.x * 256 + threadIdx.x;
    const float* base = X + (size_t)(b * LMAX) * Dm + d;
    float s = 0.f;
#pragma unroll 8
    for (int l = 0; l < LMAX; l++) s += base[(size_t)l * Dm];
    out[b * Dm + d] = s * (1.f / (float)LMAX);
}

// ---------------- launch ---------------------------------------------------------
#define SMEM_ATTN ((64 * SC_STRIDE + 2 * 64 * KV_PAD) * (int)sizeof(float))

extern "C" void kernel_launch(void* const* d_in, const int* in_sizes, int n_in,
                              void* d_out, int out_size) {
    const float* struct_tok = (const float*)d_in[0];
    const float* text_tok   = (const float*)d_in[1];
    const float* in_proj_w  = (const float*)d_in[2];
    const float* in_proj_b  = (const float*)d_in[3];
    const float* attn_out_w = (const float*)d_in[4];
    const float* attn_out_b = (const float*)d_in[5];
    const float* ln_g       = (const float*)d_in[6];
    const float* ln_b       = (const float*)d_in[7];
    const float* proj_w     = (const float*)d_in[8];
    const float* proj_b     = (const float*)d_in[9];
    float* out = (float*)d_out;

    static float *pQ = nullptr, *pK = nullptr, *pV = nullptr,
                 *pCtx = nullptr, *pF1 = nullptr, *pF2 = nullptr;
    if (!pQ) {
        cudaGetSymbolAddress((void**)&pQ, g_Q);
        cudaGetSymbolAddress((void**)&pK, g_K);
        cudaGetSymbolAddress((void**)&pV, g_V);
        cudaGetSymbolAddress((void**)&pCtx, g_ctx);
        cudaGetSymbolAddress((void**)&pF1, g_f1);
        cudaGetSymbolAddress((void**)&pF2, g_f2);
        cudaFuncSetAttribute(attn_kernel,
                             cudaFuncAttributeMaxDynamicSharedMemorySize, SMEM_ATTN);
    }

    const dim3 gQ(Dm / 128, Ntok / 128);          // (8, 32)
    const dim3 gKV(Dm / 128, (Bq * LTxt) / 128);  // (8, 64)

    // QKV projections
    sgemm_nt<<<gQ, 256>>>(struct_tok, in_proj_w,            in_proj_b,          pQ,
                          Ntok, Dm, Dm);
    sgemm_nt<<<gKV, 256>>>(text_tok, in_proj_w + Dm * Dm,     in_proj_b + Dm,     pK,
                           Bq * LTxt, Dm, Dm);
    sgemm_nt<<<gKV, 256>>>(text_tok, in_proj_w + 2 * Dm * Dm, in_proj_b + 2 * Dm, pV,
                           Bq * LTxt, Dm, Dm);

    // attention
    attn_kernel<<<dim3(LMAX / 64, Hh, Bq), 256, SMEM_ATTN>>>(pQ, pK, pV, pCtx);

    // output projection + LN + final projection
    sgemm_nt<<<gQ, 256>>>(pCtx, attn_out_w, attn_out_b, pF1, Ntok, Dm, Dm);
    ln_kernel<<<Ntok, 256>>>(pF1, ln_g, ln_b);
    sgemm_nt<<<gQ, 256>>>(pF1, proj_w, proj_b, pF2, Ntok, Dm, Dm);

    // per-batch mean -> output (16, 1024)
    seg_mean_kernel<<<dim3(Dm / 256, Bq), 256>>>(pF2, out);

    (void)in_sizes; (void)n_in; (void)out_size;
}

// round 10
// speedup vs baseline: 1.7962x; 1.7962x over previous
#include <cuda_runtime.h>
#include <cuda_bf16.h>
#include <cstdint>

// Problem constants (fixed by setup_inputs)
#define Bq 16
#define LTxt 512
#define Dm 1024
#define Ntok 4096
#define Hh 16
#define DH 64
#define LMAX 256
#define LN_EPS 1e-5f

#define KEXP 3072          // expanded K = 3*Dm (hi,hi,lo / hi,lo,hi)
#define BK 64              // k-block: 64 bf16 = 128 bytes/row (SW128 atom)
#define NBLK 48            // KEXP / BK
#define STG 4              // pipeline stages
#define TILE_BYTES 16384   // 128 rows x 128 bytes
#define STAGE_BYTES 32768  // A tile + B tile
#define SMEM_GEMM (1024 + STG * STAGE_BYTES)

// ---------------- scratch (__device__ globals; no allocs allowed) ----------------
__device__ float g_Q[Ntok * Dm];
__device__ float g_K[Bq * LTxt * Dm];
__device__ float g_V[Bq * LTxt * Dm];
__device__ float g_ctx[Ntok * Dm];
__device__ float g_f1[Ntok * Dm];
__device__ float g_f2[Ntok * Dm];

__device__ __nv_bfloat16 g_Se[Ntok * KEXP];
__device__ __nv_bfloat16 g_Te[Bq * LTxt * KEXP];
__device__ __nv_bfloat16 g_Ce[Ntok * KEXP];
__device__ __nv_bfloat16 g_F1e[Ntok * KEXP];
__device__ __nv_bfloat16 g_Wqe[Dm * KEXP];
__device__ __nv_bfloat16 g_Wke[Dm * KEXP];
__device__ __nv_bfloat16 g_Wve[Dm * KEXP];
__device__ __nv_bfloat16 g_Woe[Dm * KEXP];
__device__ __nv_bfloat16 g_Wpe[Dm * KEXP];

// ---------------- helpers --------------------------------------------------------
__device__ __forceinline__ uint32_t smem_u32(const void* p) {
    uint32_t a;
    asm("{ .reg .u64 t; cvta.to.shared.u64 t, %1; cvt.u32.u64 %0, t; }"
        : "=r"(a) : "l"(p));
    return a;
}
__device__ __forceinline__ void cp16(uint32_t dst, const void* src) {
    asm volatile("cp.async.cg.shared.global [%0], [%1], 16;" :: "r"(dst), "l"(src));
}
#define CP_COMMIT() asm volatile("cp.async.commit_group;" ::: "memory")
#define CP_WAIT2()  asm volatile("cp.async.wait_group 2;" ::: "memory")

#define LDSM_X4(r0, r1, r2, r3, addr)                                            \
    asm volatile("ldmatrix.sync.aligned.m8n8.x4.shared.b16 {%0,%1,%2,%3}, [%4];" \
                 : "=r"(r0), "=r"(r1), "=r"(r2), "=r"(r3) : "r"(addr))

__device__ __forceinline__ void mma16816(float* c, const uint32_t* a,
                                         const uint32_t* b) {
    asm volatile(
        "mma.sync.aligned.m16n8k16.row.col.f32.bf16.bf16.f32 "
        "{%0,%1,%2,%3}, {%4,%5,%6,%7}, {%8,%9}, {%0,%1,%2,%3};"
        : "+f"(c[0]), "+f"(c[1]), "+f"(c[2]), "+f"(c[3])
        : "r"(a[0]), "r"(a[1]), "r"(a[2]), "r"(a[3]), "r"(b[0]), "r"(b[1]));
}

// ---------------- HMMA GEMM: C[Mx1024] = A'[Mx3072] @ B'[1024x3072]^T + bias -----
// 128x128 tile, 8 warps in 2(M) x 4(N), each warp 64x32. BK=64, 4-stage cp.async.
__global__ __launch_bounds__(256, 1)
void hmma_gemm(const __nv_bfloat16* __restrict__ A, const __nv_bfloat16* __restrict__ Bw,
               const float* __restrict__ bias, float* __restrict__ C) {
    extern __shared__ char dsm[];
    const uint32_t base = (smem_u32(dsm) + 1023u) & ~1023u;

    const int tid = threadIdx.x;
    const int wid = tid >> 5, lane = tid & 31;
    const int mw = wid & 1, nw = wid >> 1;
    const int bn = blockIdx.x * 128, bm = blockIdx.y * 128;

    const char* Ab = (const char*)(A + (size_t)bm * KEXP);
    const char* Bb = (const char*)(Bw + (size_t)bn * KEXP);

    // loader: 128 rows x 8 chunks of 16B per tile, 256 threads, 4 rounds
    const int crow = tid >> 3;
    const int cch = tid & 7;
#define LOAD_BLK(kb, st) do {                                                     \
        uint32_t tb = base + (st) * STAGE_BYTES;                                  \
        const char* asrc = Ab + (size_t)(kb) * 128;                               \
        const char* bsrc = Bb + (size_t)(kb) * 128;                               \
        _Pragma("unroll")                                                         \
        for (int t = 0; t < 4; t++) {                                             \
            int row = crow + t * 32;                                              \
            uint32_t off = row * 128 + cch * 16;                                  \
            uint32_t sw = off ^ ((off >> 3) & 0x70);                              \
            cp16(tb + sw, asrc + (size_t)row * (KEXP * 2) + cch * 16);            \
            cp16(tb + TILE_BYTES + sw, bsrc + (size_t)row * (KEXP * 2) + cch * 16); \
        }                                                                         \
    } while (0)

    // per-lane ldmatrix address components (swizzle: 16B-granule XOR by row&7)
    const int l7 = lane & 7;
    const uint32_t sx = l7 * 16;
    uint32_t aoff[4], boff[2];
#pragma unroll
    for (int mi = 0; mi < 4; mi++) {
        int r = mw * 64 + mi * 16 + l7 + ((lane >> 3) & 1) * 8;
        aoff[mi] = r * 128;
    }
#pragma unroll
    for (int j = 0; j < 2; j++) {
        int r = nw * 32 + j * 16 + l7 + ((lane >> 4) & 1) * 8;
        boff[j] = r * 128;
    }
    const uint32_t kbA = (lane >> 4) * 16;          // A: lanes16-31 -> k-hi half
    const uint32_t kbB = ((lane >> 3) & 1) * 16;    // B: lanes 8-15/24-31 -> k-hi

    float acc[4][4][4];
#pragma unroll
    for (int mi = 0; mi < 4; mi++)
#pragma unroll
        for (int ni = 0; ni < 4; ni++)
#pragma unroll
            for (int x = 0; x < 4; x++) acc[mi][ni][x] = 0.f;

    // prologue: fill 3 stages
#pragma unroll
    for (int s = 0; s < STG - 1; s++) { LOAD_BLK(s, s); CP_COMMIT(); }

    for (int i = 0; i < NBLK; i++) {
        CP_WAIT2();
        __syncthreads();
        if (i + STG - 1 < NBLK) LOAD_BLK(i + STG - 1, (i + STG - 1) % STG);
        CP_COMMIT();

        const uint32_t Abase = base + (i % STG) * STAGE_BYTES;
        const uint32_t Bbase = Abase + TILE_BYTES;
#pragma unroll
        for (int kk = 0; kk < 4; kk++) {
            const uint32_t ka = (kk * 32 + kbA) ^ sx;
            const uint32_t kb = (kk * 32 + kbB) ^ sx;
            uint32_t a[4][4];
#pragma unroll
            for (int mi = 0; mi < 4; mi++)
                LDSM_X4(a[mi][0], a[mi][1], a[mi][2], a[mi][3],
                        Abase + aoff[mi] + ka);
            uint32_t b[4][2];
#pragma unroll
            for (int j = 0; j < 2; j++) {
                uint32_t r0, r1, r2, r3;
                LDSM_X4(r0, r1, r2, r3, Bbase + boff[j] + kb);
                b[2 * j][0] = r0; b[2 * j][1] = r1;
                b[2 * j + 1][0] = r2; b[2 * j + 1][1] = r3;
            }
#pragma unroll
            for (int mi = 0; mi < 4; mi++)
#pragma unroll
                for (int ni = 0; ni < 4; ni++)
                    mma16816(acc[mi][ni], a[mi], b[ni]);
        }
    }

    // epilogue: fused bias, float2 stores
    const int g = lane >> 2, tg = lane & 3;
#pragma unroll
    for (int ni = 0; ni < 4; ni++) {
        const int col = bn + nw * 32 + ni * 8 + tg * 2;
        const float2 b2 = *(const float2*)(bias + col);
#pragma unroll
        for (int mi = 0; mi < 4; mi++) {
            const int row = bm + mw * 64 + mi * 16 + g;
            float* cp0 = C + (size_t)row * Dm + col;
            *(float2*)cp0 = make_float2(acc[mi][ni][0] + b2.x,
                                        acc[mi][ni][1] + b2.y);
            *(float2*)(cp0 + 8 * Dm) = make_float2(acc[mi][ni][2] + b2.x,
                                                   acc[mi][ni][3] + b2.y);
        }
    }
}

// ---------------- fp32 -> split-bf16 expansion -----------------------------------
// MODE 0 (A side): [hi, hi, lo]   MODE 1 (B side): [hi, lo, hi]
template <int MODE>
__global__ __launch_bounds__(256)
void cvt_expand(const float* __restrict__ X, __nv_bfloat16* __restrict__ Y, int n4) {
    int i = blockIdx.x * 256 + threadIdx.x;
    if (i >= n4) return;
    float4 v = ((const float4*)X)[i];
    float f[4] = {v.x, v.y, v.z, v.w};
    unsigned short o[12];
#pragma unroll
    for (int j = 0; j < 4; j++) {
        __nv_bfloat16 h = __float2bfloat16_rn(f[j]);
        __nv_bfloat16 l = __float2bfloat16_rn(f[j] - __bfloat162float(h));
        unsigned short hb = __bfloat16_as_ushort(h);
        unsigned short lb = __bfloat16_as_ushort(l);
        if (MODE == 0) { o[3 * j] = hb; o[3 * j + 1] = hb; o[3 * j + 2] = lb; }
        else           { o[3 * j] = hb; o[3 * j + 1] = lb; o[3 * j + 2] = hb; }
    }
    uint64_t* dst = (uint64_t*)(Y + (size_t)i * 12);
#pragma unroll
    for (int w = 0; w < 3; w++)
        dst[w] = (uint64_t)o[4 * w] | ((uint64_t)o[4 * w + 1] << 16) |
                 ((uint64_t)o[4 * w + 2] << 32) | ((uint64_t)o[4 * w + 3] << 48);
}

// ---------------- Attention: one CTA per (qtile=64, head, batch) -----------------
#define SC_STRIDE 516
#define KV_PAD 68

__global__ __launch_bounds__(256, 1)
void attn_kernel(const float* __restrict__ Q, const float* __restrict__ K,
                 const float* __restrict__ V, float* __restrict__ CTX) {
    extern __shared__ float sm[];
    float* s_sc = sm;
    float* s_q  = s_sc + 64 * SC_STRIDE;
    float* s_kv = s_q + 64 * KV_PAD;

    const int tid = threadIdx.x;
    const int w = tid >> 5, lane = tid & 31;
    const int qt = blockIdx.x, h = blockIdx.y, b = blockIdx.z;
    const int q0 = qt * 64;
    const int qb = w * 8;

    const float* Qg = Q + (size_t)(b * LMAX + q0) * Dm + h * DH;
    const float* Kg = K + (size_t)(b * LTxt) * Dm + h * DH;
    const float* Vg = V + (size_t)(b * LTxt) * Dm + h * DH;

    const int ldr = tid >> 2;
    const int ldf = tid & 3;

    {
        const float* src = Qg + (size_t)ldr * Dm;
        float* dst = s_q + ldr * KV_PAD;
#pragma unroll
        for (int i = 0; i < 4; i++) {
            int c = (ldf + i * 4) * 4;
            *(float4*)(dst + c) = *(const float4*)(src + c);
        }
    }
    __syncthreads();

    for (int kt = 0; kt < LTxt / 64; kt++) {
        {
            const float* src = Kg + (size_t)(kt * 64 + ldr) * Dm;
#pragma unroll
            for (int i = 0; i < 4; i++) {
                int c = (ldf + i * 4) * 4;
                float4 v = *(const float4*)(src + c);
                s_kv[(c + 0) * KV_PAD + ldr] = v.x;
                s_kv[(c + 1) * KV_PAD + ldr] = v.y;
                s_kv[(c + 2) * KV_PAD + ldr] = v.z;
                s_kv[(c + 3) * KV_PAD + ldr] = v.w;
            }
        }
        __syncthreads();

        float acc[8][2];
#pragma unroll
        for (int i = 0; i < 8; i++) { acc[i][0] = 0.f; acc[i][1] = 0.f; }
#pragma unroll 4
        for (int d = 0; d < 64; d++) {
            float2 kv = *(const float2*)(s_kv + d * KV_PAD + 2 * lane);
#pragma unroll
            for (int i = 0; i < 8; i++) {
                float qv = s_q[(qb + i) * KV_PAD + d];
                acc[i][0] += qv * kv.x;
                acc[i][1] += qv * kv.y;
            }
        }
#pragma unroll
        for (int i = 0; i < 8; i++) {
            float2 o = make_float2(acc[i][0] * 0.125f, acc[i][1] * 0.125f);
            *(float2*)(s_sc + (qb + i) * SC_STRIDE + kt * 64 + 2 * lane) = o;
        }
        __syncthreads();
    }

    {
        int r = tid >> 2, j = tid & 3;
        float* row = s_sc + r * SC_STRIDE;
        float mx = -1e30f;
        for (int c = j; c < 512; c += 4) mx = fmaxf(mx, row[c]);
        mx = fmaxf(mx, __shfl_xor_sync(0xffffffffu, mx, 1));
        mx = fmaxf(mx, __shfl_xor_sync(0xffffffffu, mx, 2));
        float s = 0.f;
        for (int c = j; c < 512; c += 4) { float e = __expf(row[c] - mx); row[c] = e; s += e; }
        s += __shfl_xor_sync(0xffffffffu, s, 1);
        s += __shfl_xor_sync(0xffffffffu, s, 2);
        float inv = 1.f / s;
        for (int c = j; c < 512; c += 4) row[c] *= inv;
    }
    __syncthreads();

    float cacc[8][2];
#pragma unroll
    for (int i = 0; i < 8; i++) { cacc[i][0] = 0.f; cacc[i][1] = 0.f; }

    for (int kt = 0; kt < LTxt / 64; kt++) {
        {
            const float* src = Vg + (size_t)(kt * 64 + ldr) * Dm;
            float* dst = s_kv + ldr * KV_PAD;
#pragma unroll
            for (int i = 0; i < 4; i++) {
                int c = (ldf + i * 4) * 4;
                *(float4*)(dst + c) = *(const float4*)(src + c);
            }
        }
        __syncthreads();
#pragma unroll 4
        for (int k = 0; k < 64; k++) {
            float2 vv = *(const float2*)(s_kv + k * KV_PAD + 2 * lane);
#pragma unroll
            for (int i = 0; i < 8; i++) {
                float a = s_sc[(qb + i) * SC_STRIDE + kt * 64 + k];
                cacc[i][0] += a * vv.x;
                cacc[i][1] += a * vv.y;
            }
        }
        __syncthreads();
    }

    float* Cg = CTX + (size_t)(b * LMAX + q0 + qb) * Dm + h * DH + 2 * lane;
#pragma unroll
    for (int i = 0; i < 8; i++)
        *(float2*)(Cg + (size_t)i * Dm) = make_float2(cacc[i][0], cacc[i][1]);
}

// ---------------- LayerNorm (in place) -------------------------------------------
__global__ __launch_bounds__(256)
void ln_kernel(float* __restrict__ X, const float* __restrict__ gw,
               const float* __restrict__ bw) {
    __shared__ float red[8];
    __shared__ float stat[2];
    const int tid = threadIdx.x;
    float* xp = X + (size_t)blockIdx.x * Dm + tid * 4;
    float4 v = *(const float4*)xp;

    float s = v.x + v.y + v.z + v.w;
#pragma unroll
    for (int o = 16; o; o >>= 1) s += __shfl_xor_sync(0xffffffffu, s, o);
    if ((tid & 31) == 0) red[tid >> 5] = s;
    __syncthreads();
    if (tid == 0) {
        float t = 0.f;
#pragma unroll
        for (int i = 0; i < 8; i++) t += red[i];
        stat[0] = t * (1.f / Dm);
    }
    __syncthreads();
    const float mu = stat[0];
    float d0 = v.x - mu, d1 = v.y - mu, d2 = v.z - mu, d3 = v.w - mu;

    float s2 = d0 * d0 + d1 * d1 + d2 * d2 + d3 * d3;
#pragma unroll
    for (int o = 16; o; o >>= 1) s2 += __shfl_xor_sync(0xffffffffu, s2, o);
    if ((tid & 31) == 0) red[tid >> 5] = s2;
    __syncthreads();
    if (tid == 0) {
        float t = 0.f;
#pragma unroll
        for (int i = 0; i < 8; i++) t += red[i];
        stat[1] = t * (1.f / Dm);
    }
    __syncthreads();
    const float rstd = rsqrtf(stat[1] + LN_EPS);

    float4 g4 = *(const float4*)(gw + tid * 4);
    float4 b4 = *(const float4*)(bw + tid * 4);
    v.x = d0 * rstd * g4.x + b4.x;
    v.y = d1 * rstd * g4.y + b4.y;
    v.z = d2 * rstd * g4.z + b4.z;
    v.w = d3 * rstd * g4.w + b4.w;
    *(float4*)xp = v;
}

// ---------------- segment mean ---------------------------------------------------
__global__ __launch_bounds__(256)
void seg_mean_kernel(const float* __restrict__ X, float* __restrict__ out) {
    const int b = blockIdx.y;
    const int d = blockIdx.x * 256 + threadIdx.x;
    const float* base = X + (size_t)(b * LMAX) * Dm + d;
    float s = 0.f;
#pragma unroll 8
    for (int l = 0; l < LMAX; l++) s += base[(size_t)l * Dm];
    out[b * Dm + d] = s * (1.f / (float)LMAX);
}

// ---------------- launch ---------------------------------------------------------
#define SMEM_ATTN ((64 * SC_STRIDE + 2 * 64 * KV_PAD) * (int)sizeof(float))

extern "C" void kernel_launch(void* const* d_in, const int* in_sizes, int n_in,
                              void* d_out, int out_size) {
    const float* struct_tok = (const float*)d_in[0];
    const float* text_tok   = (const float*)d_in[1];
    const float* in_proj_w  = (const float*)d_in[2];
    const float* in_proj_b  = (const float*)d_in[3];
    const float* attn_out_w = (const float*)d_in[4];
    const float* attn_out_b = (const float*)d_in[5];
    const float* ln_g       = (const float*)d_in[6];
    const float* ln_b       = (const float*)d_in[7];
    const float* proj_w     = (const float*)d_in[8];
    const float* proj_b     = (const float*)d_in[9];
    float* out = (float*)d_out;

    float *pQ, *pK, *pV, *pCtx, *pF1, *pF2;
    __nv_bfloat16 *pSe, *pTe, *pCe, *pF1e, *pWq, *pWk, *pWv, *pWo, *pWp;
    cudaGetSymbolAddress((void**)&pQ, g_Q);
    cudaGetSymbolAddress((void**)&pK, g_K);
    cudaGetSymbolAddress((void**)&pV, g_V);
    cudaGetSymbolAddress((void**)&pCtx, g_ctx);
    cudaGetSymbolAddress((void**)&pF1, g_f1);
    cudaGetSymbolAddress((void**)&pF2, g_f2);
    cudaGetSymbolAddress((void**)&pSe, g_Se);
    cudaGetSymbolAddress((void**)&pTe, g_Te);
    cudaGetSymbolAddress((void**)&pCe, g_Ce);
    cudaGetSymbolAddress((void**)&pF1e, g_F1e);
    cudaGetSymbolAddress((void**)&pWq, g_Wqe);
    cudaGetSymbolAddress((void**)&pWk, g_Wke);
    cudaGetSymbolAddress((void**)&pWv, g_Wve);
    cudaGetSymbolAddress((void**)&pWo, g_Woe);
    cudaGetSymbolAddress((void**)&pWp, g_Wpe);
    cudaFuncSetAttribute(attn_kernel,
                         cudaFuncAttributeMaxDynamicSharedMemorySize, SMEM_ATTN);
    cudaFuncSetAttribute(hmma_gemm,
                         cudaFuncAttributeMaxDynamicSharedMemorySize, SMEM_GEMM);

    const int n4S = Ntok * Dm / 4;
    const int n4T = Bq * LTxt * Dm / 4;
    const int n4W = Dm * Dm / 4;

    // expand operands to split-bf16
    cvt_expand<0><<<(n4S + 255) / 256, 256>>>(struct_tok, pSe, n4S);
    cvt_expand<0><<<(n4T + 255) / 256, 256>>>(text_tok, pTe, n4T);
    cvt_expand<1><<<(n4W + 255) / 256, 256>>>(in_proj_w, pWq, n4W);
    cvt_expand<1><<<(n4W + 255) / 256, 256>>>(in_proj_w + Dm * Dm, pWk, n4W);
    cvt_expand<1><<<(n4W + 255) / 256, 256>>>(in_proj_w + 2 * Dm * Dm, pWv, n4W);
    cvt_expand<1><<<(n4W + 255) / 256, 256>>>(attn_out_w, pWo, n4W);
    cvt_expand<1><<<(n4W + 255) / 256, 256>>>(proj_w, pWp, n4W);

    const dim3 gQ(Dm / 128, Ntok / 128);           // (8, 32)
    const dim3 gKV(Dm / 128, (Bq * LTxt) / 128);   // (8, 64)

    // QKV projections (HMMA tensor cores, split-bf16)
    hmma_gemm<<<gQ, 256, SMEM_GEMM>>>(pSe, pWq, in_proj_b, pQ);
    hmma_gemm<<<gKV, 256, SMEM_GEMM>>>(pTe, pWk, in_proj_b + Dm, pK);
    hmma_gemm<<<gKV, 256, SMEM_GEMM>>>(pTe, pWv, in_proj_b + 2 * Dm, pV);

    // attention (fp32)
    attn_kernel<<<dim3(LMAX / 64, Hh, Bq), 256, SMEM_ATTN>>>(pQ, pK, pV, pCtx);

    // attn_out GEMM + LN + proj GEMM
    cvt_expand<0><<<(n4S + 255) / 256, 256>>>(pCtx, pCe, n4S);
    hmma_gemm<<<gQ, 256, SMEM_GEMM>>>(pCe, pWo, attn_out_b, pF1);
    ln_kernel<<<Ntok, 256>>>(pF1, ln_g, ln_b);
    cvt_expand<0><<<(n4S + 255) / 256, 256>>>(pF1, pF1e, n4S);
    hmma_gemm<<<gQ, 256, SMEM_GEMM>>>(pF1e, pWp, proj_b, pF2);

    // per-batch mean -> output (16, 1024)
    seg_mean_kernel<<<dim3(Dm / 256, Bq), 256>>>(pF2, out);

    (void)in_sizes; (void)n_in; (void)out_size;
}

// round 11
// speedup vs baseline: 2.2200x; 1.2360x over previous
#include <cuda_runtime.h>
#include <cuda_bf16.h>
#include <cstdint>

// Problem constants (fixed by setup_inputs)
#define Bq 16
#define LTxt 512
#define Dm 1024
#define Ntok 4096
#define Hh 16
#define DH 64
#define LMAX 256
#define LN_EPS 1e-5f

#define KEXP 3072          // expanded K = 3*Dm (hi,hi,lo / hi,lo,hi)
#define NBLK 48            // KEXP / 64
#define STG 4              // gemm pipeline stages
#define TILE_BYTES 16384   // 128 rows x 128 bytes
#define STAGE_BYTES 32768
#define SMEM_GEMM (1024 + STG * STAGE_BYTES)

// ---------------- scratch (__device__ globals; no allocs allowed) ----------------
__device__ float g_V[Bq * LTxt * Dm];
__device__ float g_ctx[Ntok * Dm];
__device__ float g_f1[Ntok * Dm];
__device__ float g_f2[Ntok * Dm];

__device__ __nv_bfloat16 g_Qh[Ntok * Dm];
__device__ __nv_bfloat16 g_Ql[Ntok * Dm];
__device__ __nv_bfloat16 g_Kh[Bq * LTxt * Dm];
__device__ __nv_bfloat16 g_Kl[Bq * LTxt * Dm];
__device__ __nv_bfloat16 g_Vth[Bq * Dm * LTxt];   // [b][d][k]
__device__ __nv_bfloat16 g_Vtl[Bq * Dm * LTxt];

__device__ __nv_bfloat16 g_Se[Ntok * KEXP];
__device__ __nv_bfloat16 g_Te[Bq * LTxt * KEXP];
__device__ __nv_bfloat16 g_Ce[Ntok * KEXP];
__device__ __nv_bfloat16 g_F1e[Ntok * KEXP];
__device__ __nv_bfloat16 g_Wqe[Dm * KEXP];
__device__ __nv_bfloat16 g_Wke[Dm * KEXP];
__device__ __nv_bfloat16 g_Wve[Dm * KEXP];
__device__ __nv_bfloat16 g_Woe[Dm * KEXP];
__device__ __nv_bfloat16 g_Wpe[Dm * KEXP];

// ---------------- helpers --------------------------------------------------------
__device__ __forceinline__ uint32_t smem_u32(const void* p) {
    uint32_t a;
    asm("{ .reg .u64 t; cvta.to.shared.u64 t, %1; cvt.u32.u64 %0, t; }"
        : "=r"(a) : "l"(p));
    return a;
}
__device__ __forceinline__ void cp16(uint32_t dst, const void* src) {
    asm volatile("cp.async.cg.shared.global [%0], [%1], 16;" :: "r"(dst), "l"(src));
}
#define CP_COMMIT() asm volatile("cp.async.commit_group;" ::: "memory")
#define CP_WAIT2()  asm volatile("cp.async.wait_group 2;" ::: "memory")
#define CP_WAIT0()  asm volatile("cp.async.wait_group 0;" ::: "memory")

#define LDSM_X4(r0, r1, r2, r3, addr)                                            \
    asm volatile("ldmatrix.sync.aligned.m8n8.x4.shared.b16 {%0,%1,%2,%3}, [%4];" \
                 : "=r"(r0), "=r"(r1), "=r"(r2), "=r"(r3) : "r"(addr))

__device__ __forceinline__ void mma16816(float* c, const uint32_t* a,
                                         const uint32_t* b) {
    asm volatile(
        "mma.sync.aligned.m16n8k16.row.col.f32.bf16.bf16.f32 "
        "{%0,%1,%2,%3}, {%4,%5,%6,%7}, {%8,%9}, {%0,%1,%2,%3};"
        : "+f"(c[0]), "+f"(c[1]), "+f"(c[2]), "+f"(c[3])
        : "r"(a[0]), "r"(a[1]), "r"(a[2]), "r"(a[3]), "r"(b[0]), "r"(b[1]));
}

// A-fragment (m16k16) from a 64/128-row x 128B swizzled tile
__device__ __forceinline__ void ldA(uint32_t tb, int mrb, int kk, int lane,
                                    uint32_t* a) {
    int r = mrb + (lane & 7) + ((lane >> 3) & 1) * 8;
    uint32_t addr = tb + r * 128 +
                    (((uint32_t)(kk * 32 + (lane >> 4) * 16)) ^ ((lane & 7) * 16));
    LDSM_X4(a[0], a[1], a[2], a[3], addr);
}
// two B-fragments (n8k16 at nrb, nrb+8)
__device__ __forceinline__ void ldB(uint32_t tb, int nrb, int kk, int lane,
                                    uint32_t* b) {
    int r = nrb + (lane & 7) + ((lane >> 4) & 1) * 8;
    uint32_t addr = tb + r * 128 +
                    (((uint32_t)(kk * 32 + ((lane >> 3) & 1) * 16)) ^ ((lane & 7) * 16));
    LDSM_X4(b[0], b[1], b[2], b[3], addr);
}

__device__ __forceinline__ void split_bf16(float x, unsigned short& hi,
                                           unsigned short& lo) {
    __nv_bfloat16 h = __float2bfloat16_rn(x);
    __nv_bfloat16 l = __float2bfloat16_rn(x - __bfloat162float(h));
    hi = __bfloat16_as_ushort(h);
    lo = __bfloat16_as_ushort(l);
}

// ---------------- HMMA GEMM: C[Mx1024] = A'[Mx3072] @ B'[1024x3072]^T + bias -----
// SPLIT=0: fp32 C.  SPLIT=1: write hi/lo bf16 pair arrays (Ch, Cl).
template <int SPLIT>
__global__ __launch_bounds__(256, 1)
void hmma_gemm(const __nv_bfloat16* __restrict__ A, const __nv_bfloat16* __restrict__ Bw,
               const float* __restrict__ bias, float* __restrict__ C,
               __nv_bfloat16* __restrict__ Ch, __nv_bfloat16* __restrict__ Cl) {
    extern __shared__ char dsm[];
    const uint32_t base = (smem_u32(dsm) + 1023u) & ~1023u;

    const int tid = threadIdx.x;
    const int wid = tid >> 5, lane = tid & 31;
    const int mw = wid & 1, nw = wid >> 1;
    const int bn = blockIdx.x * 128, bm = blockIdx.y * 128;

    const char* Ab = (const char*)(A + (size_t)bm * KEXP);
    const char* Bb = (const char*)(Bw + (size_t)bn * KEXP);

    const int crow = tid >> 3;
    const int cch = tid & 7;
#define LOAD_BLK(kb, st) do {                                                     \
        uint32_t tb = base + (st) * STAGE_BYTES;                                  \
        const char* asrc = Ab + (size_t)(kb) * 128;                               \
        const char* bsrc = Bb + (size_t)(kb) * 128;                               \
        _Pragma("unroll")                                                         \
        for (int t = 0; t < 4; t++) {                                             \
            int row = crow + t * 32;                                              \
            uint32_t off = row * 128 + cch * 16;                                  \
            uint32_t sw = off ^ ((off >> 3) & 0x70);                              \
            cp16(tb + sw, asrc + (size_t)row * (KEXP * 2) + cch * 16);            \
            cp16(tb + TILE_BYTES + sw, bsrc + (size_t)row * (KEXP * 2) + cch * 16); \
        }                                                                         \
    } while (0)

    float acc[4][4][4];
#pragma unroll
    for (int mi = 0; mi < 4; mi++)
#pragma unroll
        for (int ni = 0; ni < 4; ni++)
#pragma unroll
            for (int x = 0; x < 4; x++) acc[mi][ni][x] = 0.f;

#pragma unroll
    for (int s = 0; s < STG - 1; s++) { LOAD_BLK(s, s); CP_COMMIT(); }

    for (int i = 0; i < NBLK; i++) {
        CP_WAIT2();
        __syncthreads();
        if (i + STG - 1 < NBLK) LOAD_BLK(i + STG - 1, (i + STG - 1) % STG);
        CP_COMMIT();

        const uint32_t Abase = base + (i % STG) * STAGE_BYTES;
        const uint32_t Bbase = Abase + TILE_BYTES;
#pragma unroll
        for (int kk = 0; kk < 4; kk++) {
            uint32_t a[4][4];
#pragma unroll
            for (int mi = 0; mi < 4; mi++)
                ldA(Abase, mw * 64 + mi * 16, kk, lane, a[mi]);
            uint32_t b[2][4];
#pragma unroll
            for (int j = 0; j < 2; j++)
                ldB(Bbase, nw * 32 + j * 16, kk, lane, b[j]);
#pragma unroll
            for (int mi = 0; mi < 4; mi++)
#pragma unroll
                for (int ni = 0; ni < 4; ni++)
                    mma16816(acc[mi][ni], a[mi], &b[ni >> 1][(ni & 1) * 2]);
        }
    }

    const int g = lane >> 2, tg = lane & 3;
#pragma unroll
    for (int ni = 0; ni < 4; ni++) {
        const int col = bn + nw * 32 + ni * 8 + tg * 2;
        const float2 b2 = *(const float2*)(bias + col);
#pragma unroll
        for (int mi = 0; mi < 4; mi++) {
            const int row = bm + mw * 64 + mi * 16 + g;
#pragma unroll
            for (int half = 0; half < 2; half++) {
                float x0 = acc[mi][ni][2 * half + 0] + b2.x;
                float x1 = acc[mi][ni][2 * half + 1] + b2.y;
                size_t o = (size_t)(row + 8 * half) * Dm + col;
                if (SPLIT) {
                    unsigned short h0, l0, h1, l1;
                    split_bf16(x0, h0, l0);
                    split_bf16(x1, h1, l1);
                    *(uint32_t*)(Ch + o) = (uint32_t)h0 | ((uint32_t)h1 << 16);
                    *(uint32_t*)(Cl + o) = (uint32_t)l0 | ((uint32_t)l1 << 16);
                } else {
                    *(float2*)(C + o) = make_float2(x0, x1);
                }
            }
        }
    }
}

// ---------------- fp32 -> split-bf16 3x expansion --------------------------------
// MODE 0 (A side): [hi, hi, lo]   MODE 1 (B side): [hi, lo, hi]
template <int MODE>
__global__ __launch_bounds__(256)
void cvt_expand(const float* __restrict__ X, __nv_bfloat16* __restrict__ Y, int n4) {
    int i = blockIdx.x * 256 + threadIdx.x;
    if (i >= n4) return;
    float4 v = ((const float4*)X)[i];
    float f[4] = {v.x, v.y, v.z, v.w};
    unsigned short o[12];
#pragma unroll
    for (int j = 0; j < 4; j++) {
        unsigned short hb, lb;
        split_bf16(f[j], hb, lb);
        if (MODE == 0) { o[3 * j] = hb; o[3 * j + 1] = hb; o[3 * j + 2] = lb; }
        else           { o[3 * j] = hb; o[3 * j + 1] = lb; o[3 * j + 2] = hb; }
    }
    uint64_t* dst = (uint64_t*)(Y + (size_t)i * 12);
#pragma unroll
    for (int w = 0; w < 3; w++)
        dst[w] = (uint64_t)o[4 * w] | ((uint64_t)o[4 * w + 1] << 16) |
                 ((uint64_t)o[4 * w + 2] << 32) | ((uint64_t)o[4 * w + 3] << 48);
}

// ---------------- V transpose + split: Vt[b][d][k] hi/lo -------------------------
__global__ __launch_bounds__(256)
void v_transpose_split(const float* __restrict__ V, __nv_bfloat16* __restrict__ Vth,
                       __nv_bfloat16* __restrict__ Vtl) {
    __shared__ float t[32][33];
    const int kt = blockIdx.x, dt = blockIdx.y, b = blockIdx.z;
    const int r = threadIdx.x >> 5, c = threadIdx.x & 31;
#pragma unroll
    for (int i = 0; i < 4; i++) {
        int kk = r + i * 8;
        t[c][kk] = V[(size_t)(b * LTxt + kt * 32 + kk) * Dm + dt * 32 + c];
    }
    __syncthreads();
#pragma unroll
    for (int i = 0; i < 4; i++) {
        int d = r + i * 8;
        float x = t[d][c];
        unsigned short hb, lb;
        split_bf16(x, hb, lb);
        size_t o = (size_t)(b * Dm + dt * 32 + d) * LTxt + kt * 32 + c;
        Vth[o] = __ushort_as_bfloat16(hb);
        Vtl[o] = __ushort_as_bfloat16(lb);
    }
}

// ---------------- HMMA attention: CTA per (qtile=64, head, batch) ----------------
#define NKB 8
#define SC_ST 520
#define A_OFF_SC 0
#define A_SZ_SC (64 * SC_ST * 4)            // 133120
#define A_OFF_Q (A_SZ_SC)                    // qh 8192 + ql 8192
#define A_OFF_KV (A_OFF_Q + 16384)           // 2 stages x (hi 8192 + lo 8192)
#define A_OFF_P (A_OFF_KV + 32768)           // ph 8192 + pl 8192
#define SMEM_ATTN2 (A_OFF_P + 16384)         // 198656

__global__ __launch_bounds__(256, 1)
void attn_mma(const __nv_bfloat16* __restrict__ Qh, const __nv_bfloat16* __restrict__ Ql,
              const __nv_bfloat16* __restrict__ Kh, const __nv_bfloat16* __restrict__ Kl,
              const __nv_bfloat16* __restrict__ Vth, const __nv_bfloat16* __restrict__ Vtl,
              float* __restrict__ CTX) {
    extern __shared__ char sm8[];
    float* s_sc = (float*)(sm8 + A_OFF_SC);
    const uint32_t base = smem_u32(sm8);
    const uint32_t qhB = base + A_OFF_Q, qlB = qhB + 8192;
    const uint32_t kvB = base + A_OFF_KV;
    const uint32_t phB = base + A_OFF_P, plB = phB + 8192;

    const int tid = threadIdx.x, wid = tid >> 5, lane = tid & 31;
    const int mw = wid & 1, nw = wid >> 1;
    const int qt = blockIdx.x, h = blockIdx.y, b = blockIdx.z;
    const int q0 = qt * 64;

    // ---- issue Q + K block 0 loads ----
#pragma unroll
    for (int i = 0; i < 4; i++) {
        int c = tid + i * 256;
        int half = c >> 9, rem = c & 511, row = rem >> 3, ch = rem & 7;
        uint32_t off = row * 128 + ch * 16;
        off ^= (off >> 3) & 0x70;
        const char* s = (const char*)(half ? Ql : Qh) +
                        ((size_t)(b * LMAX + q0 + row) * Dm + h * DH) * 2 + ch * 16;
        cp16(qhB + half * 8192 + off, s);
    }
#define LOAD_KBLK(kb, st) do {                                                    \
        _Pragma("unroll")                                                         \
        for (int i = 0; i < 4; i++) {                                             \
            int c = tid + i * 256;                                                \
            int half = c >> 9, rem = c & 511, row = rem >> 3, ch = rem & 7;       \
            uint32_t off = row * 128 + ch * 16;                                   \
            off ^= (off >> 3) & 0x70;                                             \
            const char* s = (const char*)(half ? Kl : Kh) +                       \
                ((size_t)(b * LTxt + (kb) * 64 + row) * Dm + h * DH) * 2 + ch * 16; \
            cp16(kvB + (st) * 16384 + half * 8192 + off, s);                      \
        } } while (0)
#define LOAD_VBLK(kb, st) do {                                                    \
        _Pragma("unroll")                                                         \
        for (int i = 0; i < 4; i++) {                                             \
            int c = tid + i * 256;                                                \
            int half = c >> 9, rem = c & 511, row = rem >> 3, ch = rem & 7;       \
            uint32_t off = row * 128 + ch * 16;                                   \
            off ^= (off >> 3) & 0x70;                                             \
            const char* s = (const char*)(half ? Vtl : Vth) +                     \
                ((size_t)(b * Dm + h * DH + row) * LTxt + (kb) * 64) * 2 + ch * 16; \
            cp16(kvB + (st) * 16384 + half * 8192 + off, s);                      \
        } } while (0)

    LOAD_KBLK(0, 0);
    CP_COMMIT();

    const int g = lane >> 2, tg = lane & 3;

    // ---- phase 1: scores ----
    for (int kb = 0; kb < NKB; kb++) {
        CP_WAIT0();
        __syncthreads();
        if (kb + 1 < NKB) { LOAD_KBLK(kb + 1, (kb + 1) & 1); CP_COMMIT(); }

        const uint32_t khB = kvB + (kb & 1) * 16384, klB = khB + 8192;
        float sacc[2][2][4];
#pragma unroll
        for (int mi = 0; mi < 2; mi++)
#pragma unroll
            for (int ni = 0; ni < 2; ni++)
#pragma unroll
                for (int x = 0; x < 4; x++) sacc[mi][ni][x] = 0.f;

#pragma unroll
        for (int kk = 0; kk < 4; kk++) {
            uint32_t ah[2][4], al2[2][4], bh[4], bl[4];
            ldA(qhB, mw * 32, kk, lane, ah[0]);
            ldA(qhB, mw * 32 + 16, kk, lane, ah[1]);
            ldA(qlB, mw * 32, kk, lane, al2[0]);
            ldA(qlB, mw * 32 + 16, kk, lane, al2[1]);
            ldB(khB, nw * 16, kk, lane, bh);
            ldB(klB, nw * 16, kk, lane, bl);
#pragma unroll
            for (int mi = 0; mi < 2; mi++)
#pragma unroll
                for (int ni = 0; ni < 2; ni++) {
                    mma16816(sacc[mi][ni], ah[mi], &bh[ni * 2]);
                    mma16816(sacc[mi][ni], ah[mi], &bl[ni * 2]);
                    mma16816(sacc[mi][ni], al2[mi], &bh[ni * 2]);
                }
        }
#pragma unroll
        for (int mi = 0; mi < 2; mi++)
#pragma unroll
            for (int ni = 0; ni < 2; ni++) {
                int row = mw * 32 + mi * 16 + g;
                int col = kb * 64 + nw * 16 + ni * 8 + 2 * tg;
                *(float2*)(s_sc + (size_t)row * SC_ST + col) =
                    make_float2(sacc[mi][ni][0] * 0.125f, sacc[mi][ni][1] * 0.125f);
                *(float2*)(s_sc + (size_t)(row + 8) * SC_ST + col) =
                    make_float2(sacc[mi][ni][2] * 0.125f, sacc[mi][ni][3] * 0.125f);
            }
    }
    __syncthreads();

    // prefetch V block 0 (overlaps softmax)
    LOAD_VBLK(0, 0);
    CP_COMMIT();

    // ---- softmax: 4 threads per row ----
    {
        int r = tid >> 2, j = tid & 3;
        float* row = s_sc + (size_t)r * SC_ST;
        float mx = -1e30f;
        for (int c = j; c < 512; c += 4) mx = fmaxf(mx, row[c]);
        mx = fmaxf(mx, __shfl_xor_sync(0xffffffffu, mx, 1));
        mx = fmaxf(mx, __shfl_xor_sync(0xffffffffu, mx, 2));
        float s = 0.f;
        for (int c = j; c < 512; c += 4) { float e = __expf(row[c] - mx); row[c] = e; s += e; }
        s += __shfl_xor_sync(0xffffffffu, s, 1);
        s += __shfl_xor_sync(0xffffffffu, s, 2);
        float inv = 1.f / s;
        for (int c = j; c < 512; c += 4) row[c] *= inv;
    }

    // ---- phase 2: ctx = P @ V ----
    float cacc[2][2][4];
#pragma unroll
    for (int mi = 0; mi < 2; mi++)
#pragma unroll
        for (int ni = 0; ni < 2; ni++)
#pragma unroll
            for (int x = 0; x < 4; x++) cacc[mi][ni][x] = 0.f;

    for (int kb = 0; kb < NKB; kb++) {
        CP_WAIT0();
        __syncthreads();
        if (kb + 1 < NKB) { LOAD_VBLK(kb + 1, (kb + 1) & 1); CP_COMMIT(); }

        // convert P tile (64 x 64) to hi/lo bf16, swizzled
#pragma unroll
        for (int i = 0; i < 2; i++) {
            int c = tid + i * 256;
            int row = c >> 3, ch = c & 7;
            const float* src = s_sc + (size_t)row * SC_ST + kb * 64 + ch * 8;
            uint32_t hw[4], lw[4];
#pragma unroll
            for (int j = 0; j < 4; j++) {
                unsigned short h0, l0, h1, l1;
                split_bf16(src[2 * j], h0, l0);
                split_bf16(src[2 * j + 1], h1, l1);
                hw[j] = (uint32_t)h0 | ((uint32_t)h1 << 16);
                lw[j] = (uint32_t)l0 | ((uint32_t)l1 << 16);
            }
            uint32_t off = row * 128 + ch * 16;
            off ^= (off >> 3) & 0x70;
            *(uint4*)(sm8 + A_OFF_P + off) = make_uint4(hw[0], hw[1], hw[2], hw[3]);
            *(uint4*)(sm8 + A_OFF_P + 8192 + off) = make_uint4(lw[0], lw[1], lw[2], lw[3]);
        }
        __syncthreads();

        const uint32_t vhB = kvB + (kb & 1) * 16384, vlB = vhB + 8192;
#pragma unroll
        for (int kk = 0; kk < 4; kk++) {
            uint32_t ap[2][4], apl[2][4], bv[4], bvl[4];
            ldA(phB, mw * 32, kk, lane, ap[0]);
            ldA(phB, mw * 32 + 16, kk, lane, ap[1]);
            ldA(plB, mw * 32, kk, lane, apl[0]);
            ldA(plB, mw * 32 + 16, kk, lane, apl[1]);
            ldB(vhB, nw * 16, kk, lane, bv);
            ldB(vlB, nw * 16, kk, lane, bvl);
#pragma unroll
            for (int mi = 0; mi < 2; mi++)
#pragma unroll
                for (int ni = 0; ni < 2; ni++) {
                    mma16816(cacc[mi][ni], ap[mi], &bv[ni * 2]);
                    mma16816(cacc[mi][ni], ap[mi], &bvl[ni * 2]);
                    mma16816(cacc[mi][ni], apl[mi], &bv[ni * 2]);
                }
        }
    }

    // ---- epilogue ----
#pragma unroll
    for (int mi = 0; mi < 2; mi++)
#pragma unroll
        for (int ni = 0; ni < 2; ni++) {
            int row = b * LMAX + q0 + mw * 32 + mi * 16 + g;
            int col = h * DH + nw * 16 + ni * 8 + 2 * tg;
            *(float2*)(CTX + (size_t)row * Dm + col) =
                make_float2(cacc[mi][ni][0], cacc[mi][ni][1]);
            *(float2*)(CTX + (size_t)(row + 8) * Dm + col) =
                make_float2(cacc[mi][ni][2], cacc[mi][ni][3]);
        }
}

// ---------------- LayerNorm (in place) -------------------------------------------
__global__ __launch_bounds__(256)
void ln_kernel(float* __restrict__ X, const float* __restrict__ gw,
               const float* __restrict__ bw) {
    __shared__ float red[8];
    __shared__ float stat[2];
    const int tid = threadIdx.x;
    float* xp = X + (size_t)blockIdx.x * Dm + tid * 4;
    float4 v = *(const float4*)xp;

    float s = v.x + v.y + v.z + v.w;
#pragma unroll
    for (int o = 16; o; o >>= 1) s += __shfl_xor_sync(0xffffffffu, s, o);
    if ((tid & 31) == 0) red[tid >> 5] = s;
    __syncthreads();
    if (tid == 0) {
        float t = 0.f;
#pragma unroll
        for (int i = 0; i < 8; i++) t += red[i];
        stat[0] = t * (1.f / Dm);
    }
    __syncthreads();
    const float mu = stat[0];
    float d0 = v.x - mu, d1 = v.y - mu, d2 = v.z - mu, d3 = v.w - mu;

    float s2 = d0 * d0 + d1 * d1 + d2 * d2 + d3 * d3;
#pragma unroll
    for (int o = 16; o; o >>= 1) s2 += __shfl_xor_sync(0xffffffffu, s2, o);
    if ((tid & 31) == 0) red[tid >> 5] = s2;
    __syncthreads();
    if (tid == 0) {
        float t = 0.f;
#pragma unroll
        for (int i = 0; i < 8; i++) t += red[i];
        stat[1] = t * (1.f / Dm);
    }
    __syncthreads();
    const float rstd = rsqrtf(stat[1] + LN_EPS);

    float4 g4 = *(const float4*)(gw + tid * 4);
    float4 b4 = *(const float4*)(bw + tid * 4);
    v.x = d0 * rstd * g4.x + b4.x;
    v.y = d1 * rstd * g4.y + b4.y;
    v.z = d2 * rstd * g4.z + b4.z;
    v.w = d3 * rstd * g4.w + b4.w;
    *(float4*)xp = v;
}

// ---------------- segment mean ---------------------------------------------------
__global__ __launch_bounds__(256)
void seg_mean_kernel(const float* __restrict__ X, float* __restrict__ out) {
    const int b = blockIdx.y;
    const int d = blockIdx.x * 256 + threadIdx.x;
    const float* base = X + (size_t)(b * LMAX) * Dm + d;
    float s = 0.f;
#pragma unroll 8
    for (int l = 0; l < LMAX; l++) s += base[(size_t)l * Dm];
    out[b * Dm + d] = s * (1.f / (float)LMAX);
}

// ---------------- launch ---------------------------------------------------------
extern "C" void kernel_launch(void* const* d_in, const int* in_sizes, int n_in,
                              void* d_out, int out_size) {
    const float* struct_tok = (const float*)d_in[0];
    const float* text_tok   = (const float*)d_in[1];
    const float* in_proj_w  = (const float*)d_in[2];
    const float* in_proj_b  = (const float*)d_in[3];
    const float* attn_out_w = (const float*)d_in[4];
    const float* attn_out_b = (const float*)d_in[5];
    const float* ln_g       = (const float*)d_in[6];
    const float* ln_b       = (const float*)d_in[7];
    const float* proj_w     = (const float*)d_in[8];
    const float* proj_b     = (const float*)d_in[9];
    float* out = (float*)d_out;

    float *pV, *pCtx, *pF1, *pF2;
    __nv_bfloat16 *pQh, *pQl, *pKh, *pKl, *pVth, *pVtl;
    __nv_bfloat16 *pSe, *pTe, *pCe, *pF1e, *pWq, *pWk, *pWv, *pWo, *pWp;
    cudaGetSymbolAddress((void**)&pV, g_V);
    cudaGetSymbolAddress((void**)&pCtx, g_ctx);
    cudaGetSymbolAddress((void**)&pF1, g_f1);
    cudaGetSymbolAddress((void**)&pF2, g_f2);
    cudaGetSymbolAddress((void**)&pQh, g_Qh);
    cudaGetSymbolAddress((void**)&pQl, g_Ql);
    cudaGetSymbolAddress((void**)&pKh, g_Kh);
    cudaGetSymbolAddress((void**)&pKl, g_Kl);
    cudaGetSymbolAddress((void**)&pVth, g_Vth);
    cudaGetSymbolAddress((void**)&pVtl, g_Vtl);
    cudaGetSymbolAddress((void**)&pSe, g_Se);
    cudaGetSymbolAddress((void**)&pTe, g_Te);
    cudaGetSymbolAddress((void**)&pCe, g_Ce);
    cudaGetSymbolAddress((void**)&pF1e, g_F1e);
    cudaGetSymbolAddress((void**)&pWq, g_Wqe);
    cudaGetSymbolAddress((void**)&pWk, g_Wke);
    cudaGetSymbolAddress((void**)&pWv, g_Wve);
    cudaGetSymbolAddress((void**)&pWo, g_Woe);
    cudaGetSymbolAddress((void**)&pWp, g_Wpe);
    cudaFuncSetAttribute(hmma_gemm<0>,
                         cudaFuncAttributeMaxDynamicSharedMemorySize, SMEM_GEMM);
    cudaFuncSetAttribute(hmma_gemm<1>,
                         cudaFuncAttributeMaxDynamicSharedMemorySize, SMEM_GEMM);
    cudaFuncSetAttribute(attn_mma,
                         cudaFuncAttributeMaxDynamicSharedMemorySize, SMEM_ATTN2);

    const int n4S = Ntok * Dm / 4;
    const int n4T = Bq * LTxt * Dm / 4;
    const int n4W = Dm * Dm / 4;

    // expand operands to split-bf16 (3x K)
    cvt_expand<0><<<(n4S + 255) / 256, 256>>>(struct_tok, pSe, n4S);
    cvt_expand<0><<<(n4T + 255) / 256, 256>>>(text_tok, pTe, n4T);
    cvt_expand<1><<<(n4W + 255) / 256, 256>>>(in_proj_w, pWq, n4W);
    cvt_expand<1><<<(n4W + 255) / 256, 256>>>(in_proj_w + Dm * Dm, pWk, n4W);
    cvt_expand<1><<<(n4W + 255) / 256, 256>>>(in_proj_w + 2 * Dm * Dm, pWv, n4W);
    cvt_expand<1><<<(n4W + 255) / 256, 256>>>(attn_out_w, pWo, n4W);
    cvt_expand<1><<<(n4W + 255) / 256, 256>>>(proj_w, pWp, n4W);

    const dim3 gQ(Dm / 128, Ntok / 128);           // (8, 32)
    const dim3 gKV(Dm / 128, (Bq * LTxt) / 128);   // (8, 64)

    // QKV projections; Q and K emit hi/lo bf16 directly
    hmma_gemm<1><<<gQ, 256, SMEM_GEMM>>>(pSe, pWq, in_proj_b, nullptr, pQh, pQl);
    hmma_gemm<1><<<gKV, 256, SMEM_GEMM>>>(pTe, pWk, in_proj_b + Dm, nullptr, pKh, pKl);
    hmma_gemm<0><<<gKV, 256, SMEM_GEMM>>>(pTe, pWv, in_proj_b + 2 * Dm, pV, nullptr, nullptr);
    v_transpose_split<<<dim3(LTxt / 32, Dm / 32, Bq), 256>>>(pV, pVth, pVtl);

    // attention (HMMA split-bf16)
    attn_mma<<<dim3(LMAX / 64, Hh, Bq), 256, SMEM_ATTN2>>>(pQh, pQl, pKh, pKl,
                                                           pVth, pVtl, pCtx);

    // attn_out GEMM + LN + proj GEMM
    cvt_expand<0><<<(n4S + 255) / 256, 256>>>(pCtx, pCe, n4S);
    hmma_gemm<0><<<gQ, 256, SMEM_GEMM>>>(pCe, pWo, attn_out_b, pF1, nullptr, nullptr);
    ln_kernel<<<Ntok, 256>>>(pF1, ln_g, ln_b);
    cvt_expand<0><<<(n4S + 255) / 256, 256>>>(pF1, pF1e, n4S);
    hmma_gemm<0><<<gQ, 256, SMEM_GEMM>>>(pF1e, pWp, proj_b, pF2, nullptr, nullptr);

    // per-batch mean -> output (16, 1024)
    seg_mean_kernel<<<dim3(Dm / 256, Bq), 256>>>(pF2, out);

    (void)in_sizes; (void)n_in; (void)out_size;
}

// round 12
// speedup vs baseline: 2.5797x; 1.1620x over previous
#include <cuda_runtime.h>
#include <cuda_bf16.h>
#include <cstdint>

// Problem constants (fixed by setup_inputs)
#define Bq 16
#define LTxt 512
#define Dm 1024
#define Ntok 4096
#define Hh 16
#define DH 64
#define LMAX 256
#define LN_EPS 1e-5f

#define NKBLK 16            // Dm / 64 real k-blocks
#define PSTG 3              // pipeline stages
#define PTILE 16384         // one 128x64 bf16 tile (128B rows)
#define PSTAGE 65536        // Ah + Al + Bh + Bl
#define SMEM_PGEMM (1024 + PSTG * PSTAGE)

// ---------------- scratch (__device__ globals; no allocs allowed) ----------------
__device__ float g_V[Bq * LTxt * Dm];
__device__ float g_f1[Ntok * Dm];
__device__ float g_f2[Ntok * Dm];

__device__ __nv_bfloat16 g_Sh[Ntok * Dm],        g_Sl[Ntok * Dm];
__device__ __nv_bfloat16 g_Th[Bq * LTxt * Dm],   g_Tl[Bq * LTxt * Dm];
__device__ __nv_bfloat16 g_Qh[Ntok * Dm],        g_Ql[Ntok * Dm];
__device__ __nv_bfloat16 g_Kh[Bq * LTxt * Dm],   g_Kl[Bq * LTxt * Dm];
__device__ __nv_bfloat16 g_Vth[Bq * Dm * LTxt],  g_Vtl[Bq * Dm * LTxt];   // [b][d][k]
__device__ __nv_bfloat16 g_Ch[Ntok * Dm],        g_Cl[Ntok * Dm];
__device__ __nv_bfloat16 g_F1h[Ntok * Dm],       g_F1l[Ntok * Dm];
__device__ __nv_bfloat16 g_Wqh[Dm * Dm], g_Wql[Dm * Dm];
__device__ __nv_bfloat16 g_Wkh[Dm * Dm], g_Wkl[Dm * Dm];
__device__ __nv_bfloat16 g_Wvh[Dm * Dm], g_Wvl[Dm * Dm];
__device__ __nv_bfloat16 g_Woh[Dm * Dm], g_Wol[Dm * Dm];
__device__ __nv_bfloat16 g_Wph[Dm * Dm], g_Wpl[Dm * Dm];

// ---------------- helpers --------------------------------------------------------
__device__ __forceinline__ uint32_t smem_u32(const void* p) {
    uint32_t a;
    asm("{ .reg .u64 t; cvta.to.shared.u64 t, %1; cvt.u32.u64 %0, t; }"
        : "=r"(a) : "l"(p));
    return a;
}
__device__ __forceinline__ void cp16(uint32_t dst, const void* src) {
    asm volatile("cp.async.cg.shared.global [%0], [%1], 16;" :: "r"(dst), "l"(src));
}
#define CP_COMMIT() asm volatile("cp.async.commit_group;" ::: "memory")
#define CP_WAIT1()  asm volatile("cp.async.wait_group 1;" ::: "memory")
#define CP_WAIT0()  asm volatile("cp.async.wait_group 0;" ::: "memory")

#define LDSM_X4(r0, r1, r2, r3, addr)                                            \
    asm volatile("ldmatrix.sync.aligned.m8n8.x4.shared.b16 {%0,%1,%2,%3}, [%4];" \
                 : "=r"(r0), "=r"(r1), "=r"(r2), "=r"(r3) : "r"(addr))

__device__ __forceinline__ void mma16816(float* c, const uint32_t* a,
                                         const uint32_t* b) {
    asm volatile(
        "mma.sync.aligned.m16n8k16.row.col.f32.bf16.bf16.f32 "
        "{%0,%1,%2,%3}, {%4,%5,%6,%7}, {%8,%9}, {%0,%1,%2,%3};"
        : "+f"(c[0]), "+f"(c[1]), "+f"(c[2]), "+f"(c[3])
        : "r"(a[0]), "r"(a[1]), "r"(a[2]), "r"(a[3]), "r"(b[0]), "r"(b[1]));
}

// A-fragment (m16k16) from a 128B-row swizzled tile
__device__ __forceinline__ void ldA(uint32_t tb, int mrb, int kk, int lane,
                                    uint32_t* a) {
    int r = mrb + (lane & 7) + ((lane >> 3) & 1) * 8;
    uint32_t addr = tb + r * 128 +
                    (((uint32_t)(kk * 32 + (lane >> 4) * 16)) ^ ((lane & 7) * 16));
    LDSM_X4(a[0], a[1], a[2], a[3], addr);
}
// two B-fragments (n8k16 at nrb, nrb+8)
__device__ __forceinline__ void ldB(uint32_t tb, int nrb, int kk, int lane,
                                    uint32_t* b) {
    int r = nrb + (lane & 7) + ((lane >> 4) & 1) * 8;
    uint32_t addr = tb + r * 128 +
                    (((uint32_t)(kk * 32 + ((lane >> 3) & 1) * 16)) ^ ((lane & 7) * 16));
    LDSM_X4(b[0], b[1], b[2], b[3], addr);
}

__device__ __forceinline__ void split_bf16(float x, unsigned short& hi,
                                           unsigned short& lo) {
    __nv_bfloat16 h = __float2bfloat16_rn(x);
    __nv_bfloat16 l = __float2bfloat16_rn(x - __bfloat162float(h));
    hi = __bfloat16_as_ushort(h);
    lo = __bfloat16_as_ushort(l);
}

// ---------------- paired HMMA GEMM ----------------------------------------------
// C[M x 1024] = (Ah+Al)[M x 1024] @ (Bh+Bl)[1024 x 1024]^T + bias
// computed as Ah*Bh + Ah*Bl + Al*Bh via fragment reuse (3 MMA / frag pair).
// SPLIT=0: fp32 C.  SPLIT=1: hi/lo bf16 pair output.
template <int SPLIT>
__global__ __launch_bounds__(256, 1)
void pair_gemm(const __nv_bfloat16* __restrict__ Ah, const __nv_bfloat16* __restrict__ Al,
               const __nv_bfloat16* __restrict__ Bh, const __nv_bfloat16* __restrict__ Bl,
               const float* __restrict__ bias, float* __restrict__ C,
               __nv_bfloat16* __restrict__ Ch, __nv_bfloat16* __restrict__ Cl) {
    extern __shared__ char dsm[];
    const uint32_t base = (smem_u32(dsm) + 1023u) & ~1023u;

    const int tid = threadIdx.x;
    const int wid = tid >> 5, lane = tid & 31;
    const int mw = wid & 1, nw = wid >> 1;
    const int bn = blockIdx.x * 128, bm = blockIdx.y * 128;

    const char* AhB = (const char*)(Ah + (size_t)bm * Dm);
    const char* AlB = (const char*)(Al + (size_t)bm * Dm);
    const char* BhB = (const char*)(Bh + (size_t)bn * Dm);
    const char* BlB = (const char*)(Bl + (size_t)bn * Dm);

    const int crow = tid >> 3;
    const int cch = tid & 7;
#define PLOAD(kb, st) do {                                                        \
        uint32_t tb = base + (st) * PSTAGE;                                       \
        _Pragma("unroll")                                                         \
        for (int t = 0; t < 4; t++) {                                             \
            int row = crow + t * 32;                                              \
            uint32_t off = row * 128 + cch * 16;                                  \
            uint32_t sw = off ^ ((off >> 3) & 0x70);                              \
            size_t gsrc = (size_t)row * 2048 + (size_t)(kb) * 128 + cch * 16;     \
            cp16(tb + sw,             AhB + gsrc);                                \
            cp16(tb + PTILE + sw,     AlB + gsrc);                                \
            cp16(tb + 2 * PTILE + sw, BhB + gsrc);                                \
            cp16(tb + 3 * PTILE + sw, BlB + gsrc);                                \
        }                                                                         \
    } while (0)

    float acc[4][4][4];
#pragma unroll
    for (int mi = 0; mi < 4; mi++)
#pragma unroll
        for (int ni = 0; ni < 4; ni++)
#pragma unroll
            for (int x = 0; x < 4; x++) acc[mi][ni][x] = 0.f;

#pragma unroll
    for (int s = 0; s < PSTG - 1; s++) { PLOAD(s, s); CP_COMMIT(); }

    for (int i = 0; i < NKBLK; i++) {
        CP_WAIT1();
        __syncthreads();
        if (i + PSTG - 1 < NKBLK) PLOAD(i + PSTG - 1, (i + PSTG - 1) % PSTG);
        CP_COMMIT();

        const uint32_t S = base + (i % PSTG) * PSTAGE;
#pragma unroll
        for (int kk = 0; kk < 4; kk++) {
            uint32_t ah[4][4], al[4][4];
#pragma unroll
            for (int mi = 0; mi < 4; mi++) {
                ldA(S,         mw * 64 + mi * 16, kk, lane, ah[mi]);
                ldA(S + PTILE, mw * 64 + mi * 16, kk, lane, al[mi]);
            }
            uint32_t bh[2][4], bl[2][4];
#pragma unroll
            for (int j = 0; j < 2; j++) {
                ldB(S + 2 * PTILE, nw * 32 + j * 16, kk, lane, bh[j]);
                ldB(S + 3 * PTILE, nw * 32 + j * 16, kk, lane, bl[j]);
            }
#pragma unroll
            for (int mi = 0; mi < 4; mi++)
#pragma unroll
                for (int ni = 0; ni < 4; ni++) {
                    const uint32_t* fh = &bh[ni >> 1][(ni & 1) * 2];
                    const uint32_t* fl = &bl[ni >> 1][(ni & 1) * 2];
                    mma16816(acc[mi][ni], ah[mi], fh);
                    mma16816(acc[mi][ni], ah[mi], fl);
                    mma16816(acc[mi][ni], al[mi], fh);
                }
        }
    }

    const int g = lane >> 2, tg = lane & 3;
#pragma unroll
    for (int ni = 0; ni < 4; ni++) {
        const int col = bn + nw * 32 + ni * 8 + tg * 2;
        const float2 b2 = *(const float2*)(bias + col);
#pragma unroll
        for (int mi = 0; mi < 4; mi++) {
            const int row = bm + mw * 64 + mi * 16 + g;
#pragma unroll
            for (int half = 0; half < 2; half++) {
                float x0 = acc[mi][ni][2 * half + 0] + b2.x;
                float x1 = acc[mi][ni][2 * half + 1] + b2.y;
                size_t o = (size_t)(row + 8 * half) * Dm + col;
                if (SPLIT) {
                    unsigned short h0, l0, h1, l1;
                    split_bf16(x0, h0, l0);
                    split_bf16(x1, h1, l1);
                    *(uint32_t*)(Ch + o) = (uint32_t)h0 | ((uint32_t)h1 << 16);
                    *(uint32_t*)(Cl + o) = (uint32_t)l0 | ((uint32_t)l1 << 16);
                } else {
                    *(float2*)(C + o) = make_float2(x0, x1);
                }
            }
        }
    }
}

// ---------------- fp32 -> hi/lo bf16 pair split ----------------------------------
__global__ __launch_bounds__(256)
void cvt_split(const float* __restrict__ X, __nv_bfloat16* __restrict__ H,
               __nv_bfloat16* __restrict__ L, int n4) {
    int i = blockIdx.x * 256 + threadIdx.x;
    if (i >= n4) return;
    float4 v = ((const float4*)X)[i];
    float f[4] = {v.x, v.y, v.z, v.w};
    uint64_t hw = 0, lw = 0;
#pragma unroll
    for (int j = 0; j < 4; j++) {
        unsigned short hb, lb;
        split_bf16(f[j], hb, lb);
        hw |= (uint64_t)hb << (16 * j);
        lw |= (uint64_t)lb << (16 * j);
    }
    ((uint64_t*)H)[i] = hw;
    ((uint64_t*)L)[i] = lw;
}

// ---------------- V transpose + split: Vt[b][d][k] hi/lo -------------------------
__global__ __launch_bounds__(256)
void v_transpose_split(const float* __restrict__ V, __nv_bfloat16* __restrict__ Vth,
                       __nv_bfloat16* __restrict__ Vtl) {
    __shared__ float t[32][33];
    const int kt = blockIdx.x, dt = blockIdx.y, b = blockIdx.z;
    const int r = threadIdx.x >> 5, c = threadIdx.x & 31;
#pragma unroll
    for (int i = 0; i < 4; i++) {
        int kk = r + i * 8;
        t[c][kk] = V[(size_t)(b * LTxt + kt * 32 + kk) * Dm + dt * 32 + c];
    }
    __syncthreads();
#pragma unroll
    for (int i = 0; i < 4; i++) {
        int d = r + i * 8;
        float x = t[d][c];
        unsigned short hb, lb;
        split_bf16(x, hb, lb);
        size_t o = (size_t)(b * Dm + dt * 32 + d) * LTxt + kt * 32 + c;
        Vth[o] = __ushort_as_bfloat16(hb);
        Vtl[o] = __ushort_as_bfloat16(lb);
    }
}

// ---------------- HMMA attention: CTA per (qtile=64, head, batch) ----------------
#define NKB 8
#define SC_ST 520
#define A_OFF_SC 0
#define A_SZ_SC (64 * SC_ST * 4)
#define A_OFF_Q (A_SZ_SC)
#define A_OFF_KV (A_OFF_Q + 16384)
#define A_OFF_P (A_OFF_KV + 32768)
#define SMEM_ATTN2 (A_OFF_P + 16384)

__global__ __launch_bounds__(256, 1)
void attn_mma(const __nv_bfloat16* __restrict__ Qh, const __nv_bfloat16* __restrict__ Ql,
              const __nv_bfloat16* __restrict__ Kh, const __nv_bfloat16* __restrict__ Kl,
              const __nv_bfloat16* __restrict__ Vth, const __nv_bfloat16* __restrict__ Vtl,
              __nv_bfloat16* __restrict__ Ch, __nv_bfloat16* __restrict__ Cl) {
    extern __shared__ char sm8[];
    float* s_sc = (float*)(sm8 + A_OFF_SC);
    const uint32_t base = smem_u32(sm8);
    const uint32_t qhB = base + A_OFF_Q, qlB = qhB + 8192;
    const uint32_t kvB = base + A_OFF_KV;
    const uint32_t phB = base + A_OFF_P, plB = phB + 8192;

    const int tid = threadIdx.x, wid = tid >> 5, lane = tid & 31;
    const int mw = wid & 1, nw = wid >> 1;
    const int qt = blockIdx.x, h = blockIdx.y, b = blockIdx.z;
    const int q0 = qt * 64;

#pragma unroll
    for (int i = 0; i < 4; i++) {
        int c = tid + i * 256;
        int half = c >> 9, rem = c & 511, row = rem >> 3, ch = rem & 7;
        uint32_t off = row * 128 + ch * 16;
        off ^= (off >> 3) & 0x70;
        const char* s = (const char*)(half ? Ql : Qh) +
                        ((size_t)(b * LMAX + q0 + row) * Dm + h * DH) * 2 + ch * 16;
        cp16(qhB + half * 8192 + off, s);
    }
#define LOAD_KBLK(kb, st) do {                                                    \
        _Pragma("unroll")                                                         \
        for (int i = 0; i < 4; i++) {                                             \
            int c = tid + i * 256;                                                \
            int half = c >> 9, rem = c & 511, row = rem >> 3, ch = rem & 7;       \
            uint32_t off = row * 128 + ch * 16;                                   \
            off ^= (off >> 3) & 0x70;                                             \
            const char* s = (const char*)(half ? Kl : Kh) +                       \
                ((size_t)(b * LTxt + (kb) * 64 + row) * Dm + h * DH) * 2 + ch * 16; \
            cp16(kvB + (st) * 16384 + half * 8192 + off, s);                      \
        } } while (0)
#define LOAD_VBLK(kb, st) do {                                                    \
        _Pragma("unroll")                                                         \
        for (int i = 0; i < 4; i++) {                                             \
            int c = tid + i * 256;                                                \
            int half = c >> 9, rem = c & 511, row = rem >> 3, ch = rem & 7;       \
            uint32_t off = row * 128 + ch * 16;                                   \
            off ^= (off >> 3) & 0x70;                                             \
            const char* s = (const char*)(half ? Vtl : Vth) +                     \
                ((size_t)(b * Dm + h * DH + row) * LTxt + (kb) * 64) * 2 + ch * 16; \
            cp16(kvB + (st) * 16384 + half * 8192 + off, s);                      \
        } } while (0)

    LOAD_KBLK(0, 0);
    CP_COMMIT();

    const int g = lane >> 2, tg = lane & 3;

    // ---- phase 1: scores ----
    for (int kb = 0; kb < NKB; kb++) {
        CP_WAIT0();
        __syncthreads();
        if (kb + 1 < NKB) { LOAD_KBLK(kb + 1, (kb + 1) & 1); CP_COMMIT(); }

        const uint32_t khB = kvB + (kb & 1) * 16384, klB = khB + 8192;
        float sacc[2][2][4];
#pragma unroll
        for (int mi = 0; mi < 2; mi++)
#pragma unroll
            for (int ni = 0; ni < 2; ni++)
#pragma unroll
                for (int x = 0; x < 4; x++) sacc[mi][ni][x] = 0.f;

#pragma unroll
        for (int kk = 0; kk < 4; kk++) {
            uint32_t ah[2][4], al2[2][4], bh[4], bl[4];
            ldA(qhB, mw * 32, kk, lane, ah[0]);
            ldA(qhB, mw * 32 + 16, kk, lane, ah[1]);
            ldA(qlB, mw * 32, kk, lane, al2[0]);
            ldA(qlB, mw * 32 + 16, kk, lane, al2[1]);
            ldB(khB, nw * 16, kk, lane, bh);
            ldB(klB, nw * 16, kk, lane, bl);
#pragma unroll
            for (int mi = 0; mi < 2; mi++)
#pragma unroll
                for (int ni = 0; ni < 2; ni++) {
                    mma16816(sacc[mi][ni], ah[mi], &bh[ni * 2]);
                    mma16816(sacc[mi][ni], ah[mi], &bl[ni * 2]);
                    mma16816(sacc[mi][ni], al2[mi], &bh[ni * 2]);
                }
        }
#pragma unroll
        for (int mi = 0; mi < 2; mi++)
#pragma unroll
            for (int ni = 0; ni < 2; ni++) {
                int row = mw * 32 + mi * 16 + g;
                int col = kb * 64 + nw * 16 + ni * 8 + 2 * tg;
                *(float2*)(s_sc + (size_t)row * SC_ST + col) =
                    make_float2(sacc[mi][ni][0] * 0.125f, sacc[mi][ni][1] * 0.125f);
                *(float2*)(s_sc + (size_t)(row + 8) * SC_ST + col) =
                    make_float2(sacc[mi][ni][2] * 0.125f, sacc[mi][ni][3] * 0.125f);
            }
    }
    __syncthreads();

    LOAD_VBLK(0, 0);
    CP_COMMIT();

    // ---- softmax ----
    {
        int r = tid >> 2, j = tid & 3;
        float* row = s_sc + (size_t)r * SC_ST;
        float mx = -1e30f;
        for (int c = j; c < 512; c += 4) mx = fmaxf(mx, row[c]);
        mx = fmaxf(mx, __shfl_xor_sync(0xffffffffu, mx, 1));
        mx = fmaxf(mx, __shfl_xor_sync(0xffffffffu, mx, 2));
        float s = 0.f;
        for (int c = j; c < 512; c += 4) { float e = __expf(row[c] - mx); row[c] = e; s += e; }
        s += __shfl_xor_sync(0xffffffffu, s, 1);
        s += __shfl_xor_sync(0xffffffffu, s, 2);
        float inv = 1.f / s;
        for (int c = j; c < 512; c += 4) row[c] *= inv;
    }

    // ---- phase 2: ctx = P @ V ----
    float cacc[2][2][4];
#pragma unroll
    for (int mi = 0; mi < 2; mi++)
#pragma unroll
        for (int ni = 0; ni < 2; ni++)
#pragma unroll
            for (int x = 0; x < 4; x++) cacc[mi][ni][x] = 0.f;

    for (int kb = 0; kb < NKB; kb++) {
        CP_WAIT0();
        __syncthreads();
        if (kb + 1 < NKB) { LOAD_VBLK(kb + 1, (kb + 1) & 1); CP_COMMIT(); }

#pragma unroll
        for (int i = 0; i < 2; i++) {
            int c = tid + i * 256;
            int row = c >> 3, ch = c & 7;
            const float* src = s_sc + (size_t)row * SC_ST + kb * 64 + ch * 8;
            uint32_t hw[4], lw[4];
#pragma unroll
            for (int j = 0; j < 4; j++) {
                unsigned short h0, l0, h1, l1;
                split_bf16(src[2 * j], h0, l0);
                split_bf16(src[2 * j + 1], h1, l1);
                hw[j] = (uint32_t)h0 | ((uint32_t)h1 << 16);
                lw[j] = (uint32_t)l0 | ((uint32_t)l1 << 16);
            }
            uint32_t off = row * 128 + ch * 16;
            off ^= (off >> 3) & 0x70;
            *(uint4*)(sm8 + A_OFF_P + off) = make_uint4(hw[0], hw[1], hw[2], hw[3]);
            *(uint4*)(sm8 + A_OFF_P + 8192 + off) = make_uint4(lw[0], lw[1], lw[2], lw[3]);
        }
        __syncthreads();

        const uint32_t vhB = kvB + (kb & 1) * 16384, vlB = vhB + 8192;
#pragma unroll
        for (int kk = 0; kk < 4; kk++) {
            uint32_t ap[2][4], apl[2][4], bv[4], bvl[4];
            ldA(phB, mw * 32, kk, lane, ap[0]);
            ldA(phB, mw * 32 + 16, kk, lane, ap[1]);
            ldA(plB, mw * 32, kk, lane, apl[0]);
            ldA(plB, mw * 32 + 16, kk, lane, apl[1]);
            ldB(vhB, nw * 16, kk, lane, bv);
            ldB(vlB, nw * 16, kk, lane, bvl);
#pragma unroll
            for (int mi = 0; mi < 2; mi++)
#pragma unroll
                for (int ni = 0; ni < 2; ni++) {
                    mma16816(cacc[mi][ni], ap[mi], &bv[ni * 2]);
                    mma16816(cacc[mi][ni], ap[mi], &bvl[ni * 2]);
                    mma16816(cacc[mi][ni], apl[mi], &bv[ni * 2]);
                }
        }
    }

    // ---- epilogue: emit ctx hi/lo bf16 directly ----
#pragma unroll
    for (int mi = 0; mi < 2; mi++)
#pragma unroll
        for (int ni = 0; ni < 2; ni++) {
            int row = b * LMAX + q0 + mw * 32 + mi * 16 + g;
            int col = h * DH + nw * 16 + ni * 8 + 2 * tg;
#pragma unroll
            for (int half = 0; half < 2; half++) {
                size_t o = (size_t)(row + 8 * half) * Dm + col;
                unsigned short h0, l0, h1, l1;
                split_bf16(cacc[mi][ni][2 * half + 0], h0, l0);
                split_bf16(cacc[mi][ni][2 * half + 1], h1, l1);
                *(uint32_t*)(Ch + o) = (uint32_t)h0 | ((uint32_t)h1 << 16);
                *(uint32_t*)(Cl + o) = (uint32_t)l0 | ((uint32_t)l1 << 16);
            }
        }
}

// ---------------- LayerNorm: fp32 in -> hi/lo bf16 pair out ----------------------
__global__ __launch_bounds__(256)
void ln_kernel(const float* __restrict__ X, const float* __restrict__ gw,
               const float* __restrict__ bw, __nv_bfloat16* __restrict__ H,
               __nv_bfloat16* __restrict__ L) {
    __shared__ float red[8];
    __shared__ float stat[2];
    const int tid = threadIdx.x;
    const float* xp = X + (size_t)blockIdx.x * Dm + tid * 4;
    float4 v = *(const float4*)xp;

    float s = v.x + v.y + v.z + v.w;
#pragma unroll
    for (int o = 16; o; o >>= 1) s += __shfl_xor_sync(0xffffffffu, s, o);
    if ((tid & 31) == 0) red[tid >> 5] = s;
    __syncthreads();
    if (tid == 0) {
        float t = 0.f;
#pragma unroll
        for (int i = 0; i < 8; i++) t += red[i];
        stat[0] = t * (1.f / Dm);
    }
    __syncthreads();
    const float mu = stat[0];
    float d0 = v.x - mu, d1 = v.y - mu, d2 = v.z - mu, d3 = v.w - mu;

    float s2 = d0 * d0 + d1 * d1 + d2 * d2 + d3 * d3;
#pragma unroll
    for (int o = 16; o; o >>= 1) s2 += __shfl_xor_sync(0xffffffffu, s2, o);
    if ((tid & 31) == 0) red[tid >> 5] = s2;
    __syncthreads();
    if (tid == 0) {
        float t = 0.f;
#pragma unroll
        for (int i = 0; i < 8; i++) t += red[i];
        stat[1] = t * (1.f / Dm);
    }
    __syncthreads();
    const float rstd = rsqrtf(stat[1] + LN_EPS);

    float4 g4 = *(const float4*)(gw + tid * 4);
    float4 b4 = *(const float4*)(bw + tid * 4);
    float y[4];
    y[0] = d0 * rstd * g4.x + b4.x;
    y[1] = d1 * rstd * g4.y + b4.y;
    y[2] = d2 * rstd * g4.z + b4.z;
    y[3] = d3 * rstd * g4.w + b4.w;

    uint64_t hw = 0, lw = 0;
#pragma unroll
    for (int j = 0; j < 4; j++) {
        unsigned short hb, lb;
        split_bf16(y[j], hb, lb);
        hw |= (uint64_t)hb << (16 * j);
        lw |= (uint64_t)lb << (16 * j);
    }
    size_t o = (size_t)blockIdx.x * Dm + tid * 4;
    *(uint64_t*)(H + o) = hw;
    *(uint64_t*)(L + o) = lw;
}

// ---------------- segment mean ---------------------------------------------------
__global__ __launch_bounds__(256)
void seg_mean_kernel(const float* __restrict__ X, float* __restrict__ out) {
    const int b = blockIdx.y;
    const int d = blockIdx.x * 256 + threadIdx.x;
    const float* base = X + (size_t)(b * LMAX) * Dm + d;
    float s = 0.f;
#pragma unroll 8
    for (int l = 0; l < LMAX; l++) s += base[(size_t)l * Dm];
    out[b * Dm + d] = s * (1.f / (float)LMAX);
}

// ---------------- launch ---------------------------------------------------------
extern "C" void kernel_launch(void* const* d_in, const int* in_sizes, int n_in,
                              void* d_out, int out_size) {
    const float* struct_tok = (const float*)d_in[0];
    const float* text_tok   = (const float*)d_in[1];
    const float* in_proj_w  = (const float*)d_in[2];
    const float* in_proj_b  = (const float*)d_in[3];
    const float* attn_out_w = (const float*)d_in[4];
    const float* attn_out_b = (const float*)d_in[5];
    const float* ln_g       = (const float*)d_in[6];
    const float* ln_b       = (const float*)d_in[7];
    const float* proj_w     = (const float*)d_in[8];
    const float* proj_b     = (const float*)d_in[9];
    float* out = (float*)d_out;

    float *pV, *pF1, *pF2;
    __nv_bfloat16 *pSh, *pSl, *pTh, *pTl, *pQh, *pQl, *pKh, *pKl, *pVth, *pVtl;
    __nv_bfloat16 *pCh, *pCl, *pF1h, *pF1l;
    __nv_bfloat16 *pWqh, *pWql, *pWkh, *pWkl, *pWvh, *pWvl, *pWoh, *pWol, *pWph, *pWpl;
    cudaGetSymbolAddress((void**)&pV, g_V);
    cudaGetSymbolAddress((void**)&pF1, g_f1);
    cudaGetSymbolAddress((void**)&pF2, g_f2);
    cudaGetSymbolAddress((void**)&pSh, g_Sh);
    cudaGetSymbolAddress((void**)&pSl, g_Sl);
    cudaGetSymbolAddress((void**)&pTh, g_Th);
    cudaGetSymbolAddress((void**)&pTl, g_Tl);
    cudaGetSymbolAddress((void**)&pQh, g_Qh);
    cudaGetSymbolAddress((void**)&pQl, g_Ql);
    cudaGetSymbolAddress((void**)&pKh, g_Kh);
    cudaGetSymbolAddress((void**)&pKl, g_Kl);
    cudaGetSymbolAddress((void**)&pVth, g_Vth);
    cudaGetSymbolAddress((void**)&pVtl, g_Vtl);
    cudaGetSymbolAddress((void**)&pCh, g_Ch);
    cudaGetSymbolAddress((void**)&pCl, g_Cl);
    cudaGetSymbolAddress((void**)&pF1h, g_F1h);
    cudaGetSymbolAddress((void**)&pF1l, g_F1l);
    cudaGetSymbolAddress((void**)&pWqh, g_Wqh);
    cudaGetSymbolAddress((void**)&pWql, g_Wql);
    cudaGetSymbolAddress((void**)&pWkh, g_Wkh);
    cudaGetSymbolAddress((void**)&pWkl, g_Wkl);
    cudaGetSymbolAddress((void**)&pWvh, g_Wvh);
    cudaGetSymbolAddress((void**)&pWvl, g_Wvl);
    cudaGetSymbolAddress((void**)&pWoh, g_Woh);
    cudaGetSymbolAddress((void**)&pWol, g_Wol);
    cudaGetSymbolAddress((void**)&pWph, g_Wph);
    cudaGetSymbolAddress((void**)&pWpl, g_Wpl);
    cudaFuncSetAttribute(pair_gemm<0>,
                         cudaFuncAttributeMaxDynamicSharedMemorySize, SMEM_PGEMM);
    cudaFuncSetAttribute(pair_gemm<1>,
                         cudaFuncAttributeMaxDynamicSharedMemorySize, SMEM_PGEMM);
    cudaFuncSetAttribute(attn_mma,
                         cudaFuncAttributeMaxDynamicSharedMemorySize, SMEM_ATTN2);

    const int n4S = Ntok * Dm / 4;
    const int n4T = Bq * LTxt * Dm / 4;
    const int n4W = Dm * Dm / 4;

    // split all fp32 operands into hi/lo bf16 pairs
    cvt_split<<<(n4S + 255) / 256, 256>>>(struct_tok, pSh, pSl, n4S);
    cvt_split<<<(n4T + 255) / 256, 256>>>(text_tok, pTh, pTl, n4T);
    cvt_split<<<(n4W + 255) / 256, 256>>>(in_proj_w, pWqh, pWql, n4W);
    cvt_split<<<(n4W + 255) / 256, 256>>>(in_proj_w + Dm * Dm, pWkh, pWkl, n4W);
    cvt_split<<<(n4W + 255) / 256, 256>>>(in_proj_w + 2 * Dm * Dm, pWvh, pWvl, n4W);
    cvt_split<<<(n4W + 255) / 256, 256>>>(attn_out_w, pWoh, pWol, n4W);
    cvt_split<<<(n4W + 255) / 256, 256>>>(proj_w, pWph, pWpl, n4W);

    const dim3 gQ(Dm / 128, Ntok / 128);           // (8, 32)
    const dim3 gKV(Dm / 128, (Bq * LTxt) / 128);   // (8, 64)

    // QKV projections; Q and K emit hi/lo bf16 directly
    pair_gemm<1><<<gQ, 256, SMEM_PGEMM>>>(pSh, pSl, pWqh, pWql, in_proj_b,
                                          nullptr, pQh, pQl);
    pair_gemm<1><<<gKV, 256, SMEM_PGEMM>>>(pTh, pTl, pWkh, pWkl, in_proj_b + Dm,
                                           nullptr, pKh, pKl);
    pair_gemm<0><<<gKV, 256, SMEM_PGEMM>>>(pTh, pTl, pWvh, pWvl, in_proj_b + 2 * Dm,
                                           pV, nullptr, nullptr);
    v_transpose_split<<<dim3(LTxt / 32, Dm / 32, Bq), 256>>>(pV, pVth, pVtl);

    // attention (HMMA split-bf16) -> ctx hi/lo
    attn_mma<<<dim3(LMAX / 64, Hh, Bq), 256, SMEM_ATTN2>>>(pQh, pQl, pKh, pKl,
                                                           pVth, pVtl, pCh, pCl);

    // attn_out GEMM + LN + proj GEMM
    pair_gemm<0><<<gQ, 256, SMEM_PGEMM>>>(pCh, pCl, pWoh, pWol, attn_out_b,
                                          pF1, nullptr, nullptr);
    ln_kernel<<<Ntok, 256>>>(pF1, ln_g, ln_b, pF1h, pF1l);
    pair_gemm<0><<<gQ, 256, SMEM_PGEMM>>>(pF1h, pF1l, pWph, pWpl, proj_b,
                                          pF2, nullptr, nullptr);

    // per-batch mean -> output (16, 1024)
    seg_mean_kernel<<<dim3(Dm / 256, Bq), 256>>>(pF2, out);

    (void)in_sizes; (void)n_in; (void)out_size;
}

// round 13
// speedup vs baseline: 2.5981x; 1.0072x over previous
#include <cuda_runtime.h>
#include <cuda_bf16.h>
#include <cstdint>

// Problem constants (fixed by setup_inputs)
#define Bq 16
#define LTxt 512
#define Dm 1024
#define Ntok 4096
#define Hh 16
#define DH 64
#define LMAX 256
#define LN_EPS 1e-5f

#define NKBLK 16            // Dm / 64 real k-blocks
#define PSTG 3              // pipeline stages
#define PTILE 16384         // one 128x64 bf16 tile (128B rows)
#define PSTAGE 65536        // Ah + Al + Bh + Bl
#define SMEM_PGEMM (1024 + PSTG * PSTAGE)

// ---------------- scratch (__device__ globals; no allocs allowed) ----------------
__device__ float g_V[Bq * LTxt * Dm];
__device__ float g_f1[Ntok * Dm];
__device__ float g_f2[Ntok * Dm];

__device__ __nv_bfloat16 g_Sh[Ntok * Dm],        g_Sl[Ntok * Dm];
__device__ __nv_bfloat16 g_Th[Bq * LTxt * Dm],   g_Tl[Bq * LTxt * Dm];
__device__ __nv_bfloat16 g_Qh[Ntok * Dm],        g_Ql[Ntok * Dm];
__device__ __nv_bfloat16 g_Kh[Bq * LTxt * Dm],   g_Kl[Bq * LTxt * Dm];
__device__ __nv_bfloat16 g_Vth[Bq * Dm * LTxt],  g_Vtl[Bq * Dm * LTxt];   // [b][d][k]
__device__ __nv_bfloat16 g_Ch[Ntok * Dm],        g_Cl[Ntok * Dm];
__device__ __nv_bfloat16 g_F1h[Ntok * Dm],       g_F1l[Ntok * Dm];
__device__ __nv_bfloat16 g_Wqh[Dm * Dm], g_Wql[Dm * Dm];
__device__ __nv_bfloat16 g_Wkh[Dm * Dm], g_Wkl[Dm * Dm];
__device__ __nv_bfloat16 g_Wvh[Dm * Dm], g_Wvl[Dm * Dm];
__device__ __nv_bfloat16 g_Woh[Dm * Dm], g_Wol[Dm * Dm];
__device__ __nv_bfloat16 g_Wph[Dm * Dm], g_Wpl[Dm * Dm];

// ---------------- helpers --------------------------------------------------------
__device__ __forceinline__ uint32_t smem_u32(const void* p) {
    uint32_t a;
    asm("{ .reg .u64 t; cvta.to.shared.u64 t, %1; cvt.u32.u64 %0, t; }"
        : "=r"(a) : "l"(p));
    return a;
}
__device__ __forceinline__ void cp16(uint32_t dst, const void* src) {
    asm volatile("cp.async.cg.shared.global [%0], [%1], 16;" :: "r"(dst), "l"(src));
}
#define CP_COMMIT() asm volatile("cp.async.commit_group;" ::: "memory")
#define CP_WAIT1()  asm volatile("cp.async.wait_group 1;" ::: "memory")
#define CP_WAIT0()  asm volatile("cp.async.wait_group 0;" ::: "memory")

#define LDSM_X4(r0, r1, r2, r3, addr)                                            \
    asm volatile("ldmatrix.sync.aligned.m8n8.x4.shared.b16 {%0,%1,%2,%3}, [%4];" \
                 : "=r"(r0), "=r"(r1), "=r"(r2), "=r"(r3) : "r"(addr))

__device__ __forceinline__ void mma16816(float* c, const uint32_t* a,
                                         const uint32_t* b) {
    asm volatile(
        "mma.sync.aligned.m16n8k16.row.col.f32.bf16.bf16.f32 "
        "{%0,%1,%2,%3}, {%4,%5,%6,%7}, {%8,%9}, {%0,%1,%2,%3};"
        : "+f"(c[0]), "+f"(c[1]), "+f"(c[2]), "+f"(c[3])
        : "r"(a[0]), "r"(a[1]), "r"(a[2]), "r"(a[3]), "r"(b[0]), "r"(b[1]));
}

// A-fragment (m16k16) from a 128B-row swizzled tile
__device__ __forceinline__ void ldA(uint32_t tb, int mrb, int kk, int lane,
                                    uint32_t* a) {
    int r = mrb + (lane & 7) + ((lane >> 3) & 1) * 8;
    uint32_t addr = tb + r * 128 +
                    (((uint32_t)(kk * 32 + (lane >> 4) * 16)) ^ ((lane & 7) * 16));
    LDSM_X4(a[0], a[1], a[2], a[3], addr);
}
// two B-fragments (n8k16 at nrb, nrb+8)
__device__ __forceinline__ void ldB(uint32_t tb, int nrb, int kk, int lane,
                                    uint32_t* b) {
    int r = nrb + (lane & 7) + ((lane >> 4) & 1) * 8;
    uint32_t addr = tb + r * 128 +
                    (((uint32_t)(kk * 32 + ((lane >> 3) & 1) * 16)) ^ ((lane & 7) * 16));
    LDSM_X4(b[0], b[1], b[2], b[3], addr);
}

__device__ __forceinline__ void split_bf16(float x, unsigned short& hi,
                                           unsigned short& lo) {
    __nv_bfloat16 h = __float2bfloat16_rn(x);
    __nv_bfloat16 l = __float2bfloat16_rn(x - __bfloat162float(h));
    hi = __bfloat16_as_ushort(h);
    lo = __bfloat16_as_ushort(l);
}

// ---------------- paired HMMA GEMM ----------------------------------------------
// C[M x 1024] = (Ah+Al)[M x 1024] @ (Bh+Bl)[1024 x 1024]^T + bias
// 3 terms (hh, hl, lh) issued TERM-MAJOR: 16 independent accumulators between
// reuses of the same acc -> no back-to-back RAW chains on HMMA.
template <int SPLIT>
__global__ __launch_bounds__(256, 1)
void pair_gemm(const __nv_bfloat16* __restrict__ Ah, const __nv_bfloat16* __restrict__ Al,
               const __nv_bfloat16* __restrict__ Bh, const __nv_bfloat16* __restrict__ Bl,
               const float* __restrict__ bias, float* __restrict__ C,
               __nv_bfloat16* __restrict__ Ch, __nv_bfloat16* __restrict__ Cl) {
    extern __shared__ char dsm[];
    const uint32_t base = (smem_u32(dsm) + 1023u) & ~1023u;

    const int tid = threadIdx.x;
    const int wid = tid >> 5, lane = tid & 31;
    const int mw = wid & 1, nw = wid >> 1;
    const int bn = blockIdx.x * 128, bm = blockIdx.y * 128;

    const char* AhB = (const char*)(Ah + (size_t)bm * Dm);
    const char* AlB = (const char*)(Al + (size_t)bm * Dm);
    const char* BhB = (const char*)(Bh + (size_t)bn * Dm);
    const char* BlB = (const char*)(Bl + (size_t)bn * Dm);

    const int crow = tid >> 3;
    const int cch = tid & 7;
#define PLOAD(kb, st) do {                                                        \
        uint32_t tb = base + (st) * PSTAGE;                                       \
        _Pragma("unroll")                                                         \
        for (int t = 0; t < 4; t++) {                                             \
            int row = crow + t * 32;                                              \
            uint32_t off = row * 128 + cch * 16;                                  \
            uint32_t sw = off ^ ((off >> 3) & 0x70);                              \
            size_t gsrc = (size_t)row * 2048 + (size_t)(kb) * 128 + cch * 16;     \
            cp16(tb + sw,             AhB + gsrc);                                \
            cp16(tb + PTILE + sw,     AlB + gsrc);                                \
            cp16(tb + 2 * PTILE + sw, BhB + gsrc);                                \
            cp16(tb + 3 * PTILE + sw, BlB + gsrc);                                \
        }                                                                         \
    } while (0)

    float acc[4][4][4];
#pragma unroll
    for (int mi = 0; mi < 4; mi++)
#pragma unroll
        for (int ni = 0; ni < 4; ni++)
#pragma unroll
            for (int x = 0; x < 4; x++) acc[mi][ni][x] = 0.f;

#pragma unroll
    for (int s = 0; s < PSTG - 1; s++) { PLOAD(s, s); CP_COMMIT(); }

    for (int i = 0; i < NKBLK; i++) {
        CP_WAIT1();
        __syncthreads();
        if (i + PSTG - 1 < NKBLK) PLOAD(i + PSTG - 1, (i + PSTG - 1) % PSTG);
        CP_COMMIT();

        const uint32_t S = base + (i % PSTG) * PSTAGE;
#pragma unroll
        for (int kk = 0; kk < 4; kk++) {
            uint32_t ah[4][4], al[4][4];
#pragma unroll
            for (int mi = 0; mi < 4; mi++) {
                ldA(S,         mw * 64 + mi * 16, kk, lane, ah[mi]);
                ldA(S + PTILE, mw * 64 + mi * 16, kk, lane, al[mi]);
            }
            uint32_t bh[2][4], bl[2][4];
#pragma unroll
            for (int j = 0; j < 2; j++) {
                ldB(S + 2 * PTILE, nw * 32 + j * 16, kk, lane, bh[j]);
                ldB(S + 3 * PTILE, nw * 32 + j * 16, kk, lane, bl[j]);
            }
            // term-major: hh over all 16 tiles, then hl, then lh
#pragma unroll
            for (int mi = 0; mi < 4; mi++)
#pragma unroll
                for (int ni = 0; ni < 4; ni++)
                    mma16816(acc[mi][ni], ah[mi], &bh[ni >> 1][(ni & 1) * 2]);
#pragma unroll
            for (int mi = 0; mi < 4; mi++)
#pragma unroll
                for (int ni = 0; ni < 4; ni++)
                    mma16816(acc[mi][ni], ah[mi], &bl[ni >> 1][(ni & 1) * 2]);
#pragma unroll
            for (int mi = 0; mi < 4; mi++)
#pragma unroll
                for (int ni = 0; ni < 4; ni++)
                    mma16816(acc[mi][ni], al[mi], &bh[ni >> 1][(ni & 1) * 2]);
        }
    }

    const int g = lane >> 2, tg = lane & 3;
#pragma unroll
    for (int ni = 0; ni < 4; ni++) {
        const int col = bn + nw * 32 + ni * 8 + tg * 2;
        const float2 b2 = *(const float2*)(bias + col);
#pragma unroll
        for (int mi = 0; mi < 4; mi++) {
            const int row = bm + mw * 64 + mi * 16 + g;
#pragma unroll
            for (int half = 0; half < 2; half++) {
                float x0 = acc[mi][ni][2 * half + 0] + b2.x;
                float x1 = acc[mi][ni][2 * half + 1] + b2.y;
                size_t o = (size_t)(row + 8 * half) * Dm + col;
                if (SPLIT) {
                    unsigned short h0, l0, h1, l1;
                    split_bf16(x0, h0, l0);
                    split_bf16(x1, h1, l1);
                    *(uint32_t*)(Ch + o) = (uint32_t)h0 | ((uint32_t)h1 << 16);
                    *(uint32_t*)(Cl + o) = (uint32_t)l0 | ((uint32_t)l1 << 16);
                } else {
                    *(float2*)(C + o) = make_float2(x0, x1);
                }
            }
        }
    }
}

// ---------------- fp32 -> hi/lo bf16 pair split ----------------------------------
__global__ __launch_bounds__(256)
void cvt_split(const float* __restrict__ X, __nv_bfloat16* __restrict__ H,
               __nv_bfloat16* __restrict__ L, int n4) {
    int i = blockIdx.x * 256 + threadIdx.x;
    if (i >= n4) return;
    float4 v = ((const float4*)X)[i];
    float f[4] = {v.x, v.y, v.z, v.w};
    uint64_t hw = 0, lw = 0;
#pragma unroll
    for (int j = 0; j < 4; j++) {
        unsigned short hb, lb;
        split_bf16(f[j], hb, lb);
        hw |= (uint64_t)hb << (16 * j);
        lw |= (uint64_t)lb << (16 * j);
    }
    ((uint64_t*)H)[i] = hw;
    ((uint64_t*)L)[i] = lw;
}

// fused weight splitter: blockIdx.y selects one of 5 weight matrices
__global__ __launch_bounds__(256)
void cvt_split_w(const float* __restrict__ w_in, const float* __restrict__ w_attn,
                 const float* __restrict__ w_proj,
                 __nv_bfloat16* __restrict__ qh, __nv_bfloat16* __restrict__ ql,
                 __nv_bfloat16* __restrict__ kh, __nv_bfloat16* __restrict__ kl,
                 __nv_bfloat16* __restrict__ vh, __nv_bfloat16* __restrict__ vl,
                 __nv_bfloat16* __restrict__ oh, __nv_bfloat16* __restrict__ ol,
                 __nv_bfloat16* __restrict__ ph, __nv_bfloat16* __restrict__ pl) {
    const int n4 = Dm * Dm / 4;
    int i = blockIdx.x * 256 + threadIdx.x;
    if (i >= n4) return;
    const float* src;
    __nv_bfloat16 *H, *L;
    switch (blockIdx.y) {
        case 0: src = w_in;               H = qh; L = ql; break;
        case 1: src = w_in + Dm * Dm;     H = kh; L = kl; break;
        case 2: src = w_in + 2 * Dm * Dm; H = vh; L = vl; break;
        case 3: src = w_attn;             H = oh; L = ol; break;
        default: src = w_proj;            H = ph; L = pl; break;
    }
    float4 v = ((const float4*)src)[i];
    float f[4] = {v.x, v.y, v.z, v.w};
    uint64_t hw = 0, lw = 0;
#pragma unroll
    for (int j = 0; j < 4; j++) {
        unsigned short hb, lb;
        split_bf16(f[j], hb, lb);
        hw |= (uint64_t)hb << (16 * j);
        lw |= (uint64_t)lb << (16 * j);
    }
    ((uint64_t*)H)[i] = hw;
    ((uint64_t*)L)[i] = lw;
}

// ---------------- V transpose + split: Vt[b][d][k] hi/lo -------------------------
__global__ __launch_bounds__(256)
void v_transpose_split(const float* __restrict__ V, __nv_bfloat16* __restrict__ Vth,
                       __nv_bfloat16* __restrict__ Vtl) {
    __shared__ float t[32][33];
    const int kt = blockIdx.x, dt = blockIdx.y, b = blockIdx.z;
    const int r = threadIdx.x >> 5, c = threadIdx.x & 31;
#pragma unroll
    for (int i = 0; i < 4; i++) {
        int kk = r + i * 8;
        t[c][kk] = V[(size_t)(b * LTxt + kt * 32 + kk) * Dm + dt * 32 + c];
    }
    __syncthreads();
#pragma unroll
    for (int i = 0; i < 4; i++) {
        int d = r + i * 8;
        float x = t[d][c];
        unsigned short hb, lb;
        split_bf16(x, hb, lb);
        size_t o = (size_t)(b * Dm + dt * 32 + d) * LTxt + kt * 32 + c;
        Vth[o] = __ushort_as_bfloat16(hb);
        Vtl[o] = __ushort_as_bfloat16(lb);
    }
}

// ---------------- HMMA attention: CTA per (qtile=64, head, batch) ----------------
#define NKB 8
#define SC_ST 520
#define A_OFF_SC 0
#define A_SZ_SC (64 * SC_ST * 4)
#define A_OFF_Q (A_SZ_SC)
#define A_OFF_KV (A_OFF_Q + 16384)
#define A_OFF_P (A_OFF_KV + 32768)
#define SMEM_ATTN2 (A_OFF_P + 16384)

__global__ __launch_bounds__(256, 1)
void attn_mma(const __nv_bfloat16* __restrict__ Qh, const __nv_bfloat16* __restrict__ Ql,
              const __nv_bfloat16* __restrict__ Kh, const __nv_bfloat16* __restrict__ Kl,
              const __nv_bfloat16* __restrict__ Vth, const __nv_bfloat16* __restrict__ Vtl,
              __nv_bfloat16* __restrict__ Ch, __nv_bfloat16* __restrict__ Cl) {
    extern __shared__ char sm8[];
    float* s_sc = (float*)(sm8 + A_OFF_SC);
    const uint32_t base = smem_u32(sm8);
    const uint32_t qhB = base + A_OFF_Q, qlB = qhB + 8192;
    const uint32_t kvB = base + A_OFF_KV;
    const uint32_t phB = base + A_OFF_P, plB = phB + 8192;

    const int tid = threadIdx.x, wid = tid >> 5, lane = tid & 31;
    const int mw = wid & 1, nw = wid >> 1;
    const int qt = blockIdx.x, h = blockIdx.y, b = blockIdx.z;
    const int q0 = qt * 64;

#pragma unroll
    for (int i = 0; i < 4; i++) {
        int c = tid + i * 256;
        int half = c >> 9, rem = c & 511, row = rem >> 3, ch = rem & 7;
        uint32_t off = row * 128 + ch * 16;
        off ^= (off >> 3) & 0x70;
        const char* s = (const char*)(half ? Ql : Qh) +
                        ((size_t)(b * LMAX + q0 + row) * Dm + h * DH) * 2 + ch * 16;
        cp16(qhB + half * 8192 + off, s);
    }
#define LOAD_KBLK(kb, st) do {                                                    \
        _Pragma("unroll")                                                         \
        for (int i = 0; i < 4; i++) {                                             \
            int c = tid + i * 256;                                                \
            int half = c >> 9, rem = c & 511, row = rem >> 3, ch = rem & 7;       \
            uint32_t off = row * 128 + ch * 16;                                   \
            off ^= (off >> 3) & 0x70;                                             \
            const char* s = (const char*)(half ? Kl : Kh) +                       \
                ((size_t)(b * LTxt + (kb) * 64 + row) * Dm + h * DH) * 2 + ch * 16; \
            cp16(kvB + (st) * 16384 + half * 8192 + off, s);                      \
        } } while (0)
#define LOAD_VBLK(kb, st) do {                                                    \
        _Pragma("unroll")                                                         \
        for (int i = 0; i < 4; i++) {                                             \
            int c = tid + i * 256;                                                \
            int half = c >> 9, rem = c & 511, row = rem >> 3, ch = rem & 7;       \
            uint32_t off = row * 128 + ch * 16;                                   \
            off ^= (off >> 3) & 0x70;                                             \
            const char* s = (const char*)(half ? Vtl : Vth) +                     \
                ((size_t)(b * Dm + h * DH + row) * LTxt + (kb) * 64) * 2 + ch * 16; \
            cp16(kvB + (st) * 16384 + half * 8192 + off, s);                      \
        } } while (0)

    LOAD_KBLK(0, 0);
    CP_COMMIT();

    const int g = lane >> 2, tg = lane & 3;

    // ---- phase 1: scores (term-major MMA) ----
    for (int kb = 0; kb < NKB; kb++) {
        CP_WAIT0();
        __syncthreads();
        if (kb + 1 < NKB) { LOAD_KBLK(kb + 1, (kb + 1) & 1); CP_COMMIT(); }

        const uint32_t khB = kvB + (kb & 1) * 16384, klB = khB + 8192;
        float sacc[2][2][4];
#pragma unroll
        for (int mi = 0; mi < 2; mi++)
#pragma unroll
            for (int ni = 0; ni < 2; ni++)
#pragma unroll
                for (int x = 0; x < 4; x++) sacc[mi][ni][x] = 0.f;

#pragma unroll
        for (int kk = 0; kk < 4; kk++) {
            uint32_t ah[2][4], al2[2][4], bh[4], bl[4];
            ldA(qhB, mw * 32, kk, lane, ah[0]);
            ldA(qhB, mw * 32 + 16, kk, lane, ah[1]);
            ldA(qlB, mw * 32, kk, lane, al2[0]);
            ldA(qlB, mw * 32 + 16, kk, lane, al2[1]);
            ldB(khB, nw * 16, kk, lane, bh);
            ldB(klB, nw * 16, kk, lane, bl);
#pragma unroll
            for (int mi = 0; mi < 2; mi++)
#pragma unroll
                for (int ni = 0; ni < 2; ni++)
                    mma16816(sacc[mi][ni], ah[mi], &bh[ni * 2]);
#pragma unroll
            for (int mi = 0; mi < 2; mi++)
#pragma unroll
                for (int ni = 0; ni < 2; ni++)
                    mma16816(sacc[mi][ni], ah[mi], &bl[ni * 2]);
#pragma unroll
            for (int mi = 0; mi < 2; mi++)
#pragma unroll
                for (int ni = 0; ni < 2; ni++)
                    mma16816(sacc[mi][ni], al2[mi], &bh[ni * 2]);
        }
#pragma unroll
        for (int mi = 0; mi < 2; mi++)
#pragma unroll
            for (int ni = 0; ni < 2; ni++) {
                int row = mw * 32 + mi * 16 + g;
                int col = kb * 64 + nw * 16 + ni * 8 + 2 * tg;
                *(float2*)(s_sc + (size_t)row * SC_ST + col) =
                    make_float2(sacc[mi][ni][0] * 0.125f, sacc[mi][ni][1] * 0.125f);
                *(float2*)(s_sc + (size_t)(row + 8) * SC_ST + col) =
                    make_float2(sacc[mi][ni][2] * 0.125f, sacc[mi][ni][3] * 0.125f);
            }
    }
    __syncthreads();

    LOAD_VBLK(0, 0);
    CP_COMMIT();

    // ---- softmax ----
    {
        int r = tid >> 2, j = tid & 3;
        float* row = s_sc + (size_t)r * SC_ST;
        float mx = -1e30f;
        for (int c = j; c < 512; c += 4) mx = fmaxf(mx, row[c]);
        mx = fmaxf(mx, __shfl_xor_sync(0xffffffffu, mx, 1));
        mx = fmaxf(mx, __shfl_xor_sync(0xffffffffu, mx, 2));
        float s = 0.f;
        for (int c = j; c < 512; c += 4) { float e = __expf(row[c] - mx); row[c] = e; s += e; }
        s += __shfl_xor_sync(0xffffffffu, s, 1);
        s += __shfl_xor_sync(0xffffffffu, s, 2);
        float inv = 1.f / s;
        for (int c = j; c < 512; c += 4) row[c] *= inv;
    }

    // ---- phase 2: ctx = P @ V (term-major MMA) ----
    float cacc[2][2][4];
#pragma unroll
    for (int mi = 0; mi < 2; mi++)
#pragma unroll
        for (int ni = 0; ni < 2; ni++)
#pragma unroll
            for (int x = 0; x < 4; x++) cacc[mi][ni][x] = 0.f;

    for (int kb = 0; kb < NKB; kb++) {
        CP_WAIT0();
        __syncthreads();
        if (kb + 1 < NKB) { LOAD_VBLK(kb + 1, (kb + 1) & 1); CP_COMMIT(); }

#pragma unroll
        for (int i = 0; i < 2; i++) {
            int c = tid + i * 256;
            int row = c >> 3, ch = c & 7;
            const float* src = s_sc + (size_t)row * SC_ST + kb * 64 + ch * 8;
            uint32_t hw[4], lw[4];
#pragma unroll
            for (int j = 0; j < 4; j++) {
                unsigned short h0, l0, h1, l1;
                split_bf16(src[2 * j], h0, l0);
                split_bf16(src[2 * j + 1], h1, l1);
                hw[j] = (uint32_t)h0 | ((uint32_t)h1 << 16);
                lw[j] = (uint32_t)l0 | ((uint32_t)l1 << 16);
            }
            uint32_t off = row * 128 + ch * 16;
            off ^= (off >> 3) & 0x70;
            *(uint4*)(sm8 + A_OFF_P + off) = make_uint4(hw[0], hw[1], hw[2], hw[3]);
            *(uint4*)(sm8 + A_OFF_P + 8192 + off) = make_uint4(lw[0], lw[1], lw[2], lw[3]);
        }
        __syncthreads();

        const uint32_t vhB = kvB + (kb & 1) * 16384, vlB = vhB + 8192;
#pragma unroll
        for (int kk = 0; kk < 4; kk++) {
            uint32_t ap[2][4], apl[2][4], bv[4], bvl[4];
            ldA(phB, mw * 32, kk, lane, ap[0]);
            ldA(phB, mw * 32 + 16, kk, lane, ap[1]);
            ldA(plB, mw * 32, kk, lane, apl[0]);
            ldA(plB, mw * 32 + 16, kk, lane, apl[1]);
            ldB(vhB, nw * 16, kk, lane, bv);
            ldB(vlB, nw * 16, kk, lane, bvl);
#pragma unroll
            for (int mi = 0; mi < 2; mi++)
#pragma unroll
                for (int ni = 0; ni < 2; ni++)
                    mma16816(cacc[mi][ni], ap[mi], &bv[ni * 2]);
#pragma unroll
            for (int mi = 0; mi < 2; mi++)
#pragma unroll
                for (int ni = 0; ni < 2; ni++)
                    mma16816(cacc[mi][ni], ap[mi], &bvl[ni * 2]);
#pragma unroll
            for (int mi = 0; mi < 2; mi++)
#pragma unroll
                for (int ni = 0; ni < 2; ni++)
                    mma16816(cacc[mi][ni], apl[mi], &bv[ni * 2]);
        }
    }

    // ---- epilogue: emit ctx hi/lo bf16 directly ----
#pragma unroll
    for (int mi = 0; mi < 2; mi++)
#pragma unroll
        for (int ni = 0; ni < 2; ni++) {
            int row = b * LMAX + q0 + mw * 32 + mi * 16 + g;
            int col = h * DH + nw * 16 + ni * 8 + 2 * tg;
#pragma unroll
            for (int half = 0; half < 2; half++) {
                size_t o = (size_t)(row + 8 * half) * Dm + col;
                unsigned short h0, l0, h1, l1;
                split_bf16(cacc[mi][ni][2 * half + 0], h0, l0);
                split_bf16(cacc[mi][ni][2 * half + 1], h1, l1);
                *(uint32_t*)(Ch + o) = (uint32_t)h0 | ((uint32_t)h1 << 16);
                *(uint32_t*)(Cl + o) = (uint32_t)l0 | ((uint32_t)l1 << 16);
            }
        }
}

// ---------------- LayerNorm: fp32 in -> hi/lo bf16 pair out ----------------------
__global__ __launch_bounds__(256)
void ln_kernel(const float* __restrict__ X, const float* __restrict__ gw,
               const float* __restrict__ bw, __nv_bfloat16* __restrict__ H,
               __nv_bfloat16* __restrict__ L) {
    __shared__ float red[8];
    __shared__ float stat[2];
    const int tid = threadIdx.x;
    const float* xp = X + (size_t)blockIdx.x * Dm + tid * 4;
    float4 v = *(const float4*)xp;

    float s = v.x + v.y + v.z + v.w;
#pragma unroll
    for (int o = 16; o; o >>= 1) s += __shfl_xor_sync(0xffffffffu, s, o);
    if ((tid & 31) == 0) red[tid >> 5] = s;
    __syncthreads();
    if (tid == 0) {
        float t = 0.f;
#pragma unroll
        for (int i = 0; i < 8; i++) t += red[i];
        stat[0] = t * (1.f / Dm);
    }
    __syncthreads();
    const float mu = stat[0];
    float d0 = v.x - mu, d1 = v.y - mu, d2 = v.z - mu, d3 = v.w - mu;

    float s2 = d0 * d0 + d1 * d1 + d2 * d2 + d3 * d3;
#pragma unroll
    for (int o = 16; o; o >>= 1) s2 += __shfl_xor_sync(0xffffffffu, s2, o);
    if ((tid & 31) == 0) red[tid >> 5] = s2;
    __syncthreads();
    if (tid == 0) {
        float t = 0.f;
#pragma unroll
        for (int i = 0; i < 8; i++) t += red[i];
        stat[1] = t * (1.f / Dm);
    }
    __syncthreads();
    const float rstd = rsqrtf(stat[1] + LN_EPS);

    float4 g4 = *(const float4*)(gw + tid * 4);
    float4 b4 = *(const float4*)(bw + tid * 4);
    float y[4];
    y[0] = d0 * rstd * g4.x + b4.x;
    y[1] = d1 * rstd * g4.y + b4.y;
    y[2] = d2 * rstd * g4.z + b4.z;
    y[3] = d3 * rstd * g4.w + b4.w;

    uint64_t hw = 0, lw = 0;
#pragma unroll
    for (int j = 0; j < 4; j++) {
        unsigned short hb, lb;
        split_bf16(y[j], hb, lb);
        hw |= (uint64_t)hb << (16 * j);
        lw |= (uint64_t)lb << (16 * j);
    }
    size_t o = (size_t)blockIdx.x * Dm + tid * 4;
    *(uint64_t*)(H + o) = hw;
    *(uint64_t*)(L + o) = lw;
}

// ---------------- segment mean ---------------------------------------------------
__global__ __launch_bounds__(256)
void seg_mean_kernel(const float* __restrict__ X, float* __restrict__ out) {
    const int b = blockIdx.y;
    const int d = blockIdx.x * 256 + threadIdx.x;
    const float* base = X + (size_t)(b * LMAX) * Dm + d;
    float s = 0.f;
#pragma unroll 8
    for (int l = 0; l < LMAX; l++) s += base[(size_t)l * Dm];
    out[b * Dm + d] = s * (1.f / (float)LMAX);
}

// ---------------- launch ---------------------------------------------------------
extern "C" void kernel_launch(void* const* d_in, const int* in_sizes, int n_in,
                              void* d_out, int out_size) {
    const float* struct_tok = (const float*)d_in[0];
    const float* text_tok   = (const float*)d_in[1];
    const float* in_proj_w  = (const float*)d_in[2];
    const float* in_proj_b  = (const float*)d_in[3];
    const float* attn_out_w = (const float*)d_in[4];
    const float* attn_out_b = (const float*)d_in[5];
    const float* ln_g       = (const float*)d_in[6];
    const float* ln_b       = (const float*)d_in[7];
    const float* proj_w     = (const float*)d_in[8];
    const float* proj_b     = (const float*)d_in[9];
    float* out = (float*)d_out;

    float *pV, *pF1, *pF2;
    __nv_bfloat16 *pSh, *pSl, *pTh, *pTl, *pQh, *pQl, *pKh, *pKl, *pVth, *pVtl;
    __nv_bfloat16 *pCh, *pCl, *pF1h, *pF1l;
    __nv_bfloat16 *pWqh, *pWql, *pWkh, *pWkl, *pWvh, *pWvl, *pWoh, *pWol, *pWph, *pWpl;
    cudaGetSymbolAddress((void**)&pV, g_V);
    cudaGetSymbolAddress((void**)&pF1, g_f1);
    cudaGetSymbolAddress((void**)&pF2, g_f2);
    cudaGetSymbolAddress((void**)&pSh, g_Sh);
    cudaGetSymbolAddress((void**)&pSl, g_Sl);
    cudaGetSymbolAddress((void**)&pTh, g_Th);
    cudaGetSymbolAddress((void**)&pTl, g_Tl);
    cudaGetSymbolAddress((void**)&pQh, g_Qh);
    cudaGetSymbolAddress((void**)&pQl, g_Ql);
    cudaGetSymbolAddress((void**)&pKh, g_Kh);
    cudaGetSymbolAddress((void**)&pKl, g_Kl);
    cudaGetSymbolAddress((void**)&pVth, g_Vth);
    cudaGetSymbolAddress((void**)&pVtl, g_Vtl);
    cudaGetSymbolAddress((void**)&pCh, g_Ch);
    cudaGetSymbolAddress((void**)&pCl, g_Cl);
    cudaGetSymbolAddress((void**)&pF1h, g_F1h);
    cudaGetSymbolAddress((void**)&pF1l, g_F1l);
    cudaGetSymbolAddress((void**)&pWqh, g_Wqh);
    cudaGetSymbolAddress((void**)&pWql, g_Wql);
    cudaGetSymbolAddress((void**)&pWkh, g_Wkh);
    cudaGetSymbolAddress((void**)&pWkl, g_Wkl);
    cudaGetSymbolAddress((void**)&pWvh, g_Wvh);
    cudaGetSymbolAddress((void**)&pWvl, g_Wvl);
    cudaGetSymbolAddress((void**)&pWoh, g_Woh);
    cudaGetSymbolAddress((void**)&pWol, g_Wol);
    cudaGetSymbolAddress((void**)&pWph, g_Wph);
    cudaGetSymbolAddress((void**)&pWpl, g_Wpl);
    cudaFuncSetAttribute(pair_gemm<0>,
                         cudaFuncAttributeMaxDynamicSharedMemorySize, SMEM_PGEMM);
    cudaFuncSetAttribute(pair_gemm<1>,
                         cudaFuncAttributeMaxDynamicSharedMemorySize, SMEM_PGEMM);
    cudaFuncSetAttribute(attn_mma,
                         cudaFuncAttributeMaxDynamicSharedMemorySize, SMEM_ATTN2);

    const int n4S = Ntok * Dm / 4;
    const int n4T = Bq * LTxt * Dm / 4;
    const int n4W = Dm * Dm / 4;

    const dim3 gQ(Dm / 128, Ntok / 128);           // (8, 32)
    const dim3 gKV(Dm / 128, (Bq * LTxt) / 128);   // (8, 64)

    // launches 0-2: operand splits (weights fused into one launch)
    cvt_split<<<(n4T + 255) / 256, 256>>>(text_tok, pTh, pTl, n4T);      // 0
    cvt_split<<<(n4S + 255) / 256, 256>>>(struct_tok, pSh, pSl, n4S);    // 1
    cvt_split_w<<<dim3((n4W + 255) / 256, 5), 256>>>(                    // 2
        in_proj_w, attn_out_w, proj_w,
        pWqh, pWql, pWkh, pWkl, pWvh, pWvl, pWoh, pWol, pWph, pWpl);

    // launches 3-5: QKV projections (launch 5 = K GEMM is the ncu target)
    pair_gemm<1><<<gQ, 256, SMEM_PGEMM>>>(pSh, pSl, pWqh, pWql, in_proj_b,   // 3
                                          nullptr, pQh, pQl);
    pair_gemm<0><<<gKV, 256, SMEM_PGEMM>>>(pTh, pTl, pWvh, pWvl,             // 4
                                           in_proj_b + 2 * Dm, pV, nullptr, nullptr);
    pair_gemm<1><<<gKV, 256, SMEM_PGEMM>>>(pTh, pTl, pWkh, pWkl,             // 5 <- ncu
                                           in_proj_b + Dm, nullptr, pKh, pKl);

    v_transpose_split<<<dim3(LTxt / 32, Dm / 32, Bq), 256>>>(pV, pVth, pVtl);

    // attention (HMMA split-bf16) -> ctx hi/lo
    attn_mma<<<dim3(LMAX / 64, Hh, Bq), 256, SMEM_ATTN2>>>(pQh, pQl, pKh, pKl,
                                                           pVth, pVtl, pCh, pCl);

    // attn_out GEMM + LN + proj GEMM
    pair_gemm<0><<<gQ, 256, SMEM_PGEMM>>>(pCh, pCl, pWoh, pWol, attn_out_b,
                                          pF1, nullptr, nullptr);
    ln_kernel<<<Ntok, 256>>>(pF1, ln_g, ln_b, pF1h, pF1l);
    pair_gemm<0><<<gQ, 256, SMEM_PGEMM>>>(pF1h, pF1l, pWph, pWpl, proj_b,
                                          pF2, nullptr, nullptr);

    // per-batch mean -> output (16, 1024)
    seg_mean_kernel<<<dim3(Dm / 256, Bq), 256>>>(pF2, out);

    (void)in_sizes; (void)n_in; (void)out_size;
}

// round 16
// speedup vs baseline: 2.7433x; 1.0559x over previous
#include <cuda_runtime.h>
#include <cuda_bf16.h>
#include <cstdint>

// Problem constants (fixed by setup_inputs)
#define Bq 16
#define LTxt 512
#define Dm 1024
#define Ntok 4096
#define Hh 16
#define DH 64
#define LMAX 256
#define LN_EPS 1e-5f

#define NKBLK 16            // Dm / 64 real k-blocks
#define PSTG 3              // pipeline stages
#define PTILE 16384         // one 128x64 bf16 tile (128B rows)
#define PSTAGE 65536        // Ah + Al + Bh + Bl
#define SMEM_PGEMM (1024 + PSTG * PSTAGE)

// ---------------- scratch (__device__ globals; no allocs allowed) ----------------
__device__ float g_V[Bq * LTxt * Dm];
__device__ float g_f1[Ntok * Dm];
__device__ float g_f2[Ntok * Dm];

__device__ __nv_bfloat16 g_Sh[Ntok * Dm],        g_Sl[Ntok * Dm];
__device__ __nv_bfloat16 g_Th[Bq * LTxt * Dm],   g_Tl[Bq * LTxt * Dm];
__device__ __nv_bfloat16 g_Qh[Ntok * Dm],        g_Ql[Ntok * Dm];
__device__ __nv_bfloat16 g_Kh[Bq * LTxt * Dm],   g_Kl[Bq * LTxt * Dm];
__device__ __nv_bfloat16 g_Vth[Bq * Dm * LTxt],  g_Vtl[Bq * Dm * LTxt];   // [b][d][k]
__device__ __nv_bfloat16 g_Ch[Ntok * Dm],        g_Cl[Ntok * Dm];
__device__ __nv_bfloat16 g_F1h[Ntok * Dm],       g_F1l[Ntok * Dm];
__device__ __nv_bfloat16 g_Wqh[Dm * Dm], g_Wql[Dm * Dm];
__device__ __nv_bfloat16 g_Wkh[Dm * Dm], g_Wkl[Dm * Dm];
__device__ __nv_bfloat16 g_Wvh[Dm * Dm], g_Wvl[Dm * Dm];
__device__ __nv_bfloat16 g_Woh[Dm * Dm], g_Wol[Dm * Dm];
__device__ __nv_bfloat16 g_Wph[Dm * Dm], g_Wpl[Dm * Dm];

// ---------------- helpers --------------------------------------------------------
__device__ __forceinline__ uint32_t smem_u32(const void* p) {
    uint32_t a;
    asm("{ .reg .u64 t; cvta.to.shared.u64 t, %1; cvt.u32.u64 %0, t; }"
        : "=r"(a) : "l"(p));
    return a;
}
__device__ __forceinline__ void cp16(uint32_t dst, const void* src) {
    asm volatile("cp.async.cg.shared.global [%0], [%1], 16;" :: "r"(dst), "l"(src));
}
#define CP_COMMIT() asm volatile("cp.async.commit_group;" ::: "memory")
#define CP_WAIT1()  asm volatile("cp.async.wait_group 1;" ::: "memory")
#define CP_WAIT0()  asm volatile("cp.async.wait_group 0;" ::: "memory")

#define LDSM_X4(r0, r1, r2, r3, addr)                                            \
    asm volatile("ldmatrix.sync.aligned.m8n8.x4.shared.b16 {%0,%1,%2,%3}, [%4];" \
                 : "=r"(r0), "=r"(r1), "=r"(r2), "=r"(r3) : "r"(addr))

__device__ __forceinline__ void mma16816(float* c, const uint32_t* a,
                                         const uint32_t* b) {
    asm volatile(
        "mma.sync.aligned.m16n8k16.row.col.f32.bf16.bf16.f32 "
        "{%0,%1,%2,%3}, {%4,%5,%6,%7}, {%8,%9}, {%0,%1,%2,%3};"
        : "+f"(c[0]), "+f"(c[1]), "+f"(c[2]), "+f"(c[3])
        : "r"(a[0]), "r"(a[1]), "r"(a[2]), "r"(a[3]), "r"(b[0]), "r"(b[1]));
}

// A-fragment (m16k16) from a 128B-row swizzled tile
__device__ __forceinline__ void ldA(uint32_t tb, int mrb, int kk, int lane,
                                    uint32_t* a) {
    int r = mrb + (lane & 7) + ((lane >> 3) & 1) * 8;
    uint32_t addr = tb + r * 128 +
                    (((uint32_t)(kk * 32 + (lane >> 4) * 16)) ^ ((lane & 7) * 16));
    LDSM_X4(a[0], a[1], a[2], a[3], addr);
}
// two B-fragments (n8k16 at nrb, nrb+8)
__device__ __forceinline__ void ldB(uint32_t tb, int nrb, int kk, int lane,
                                    uint32_t* b) {
    int r = nrb + (lane & 7) + ((lane >> 4) & 1) * 8;
    uint32_t addr = tb + r * 128 +
                    (((uint32_t)(kk * 32 + ((lane >> 3) & 1) * 16)) ^ ((lane & 7) * 16));
    LDSM_X4(b[0], b[1], b[2], b[3], addr);
}

__device__ __forceinline__ void split_bf16(float x, unsigned short& hi,
                                           unsigned short& lo) {
    __nv_bfloat16 h = __float2bfloat16_rn(x);
    __nv_bfloat16 l = __float2bfloat16_rn(x - __bfloat162float(h));
    hi = __bfloat16_as_ushort(h);
    lo = __bfloat16_as_ushort(l);
}

// ---------------- shared GEMM body: EXACT R13 structure --------------------------
// C[128 x 128 tile] = (Ah+Al)[128 x 1024] @ (Bh+Bl)[128 x 1024]^T + bias
// 3 terms (hh, hl, lh), term-major. Full-stage PLOAD at top of each iteration,
// commit before the kk loop, CP_WAIT1 / PSTG=3 — identical to the 688us kernel.
template <int SPLIT>
__device__ __forceinline__ void gemm_body(
    char* dsm,
    const __nv_bfloat16* __restrict__ Ah, const __nv_bfloat16* __restrict__ Al,
    const __nv_bfloat16* __restrict__ Bh, const __nv_bfloat16* __restrict__ Bl,
    const float* __restrict__ bias, float* __restrict__ C,
    __nv_bfloat16* __restrict__ Ch, __nv_bfloat16* __restrict__ Cl,
    int bm, int bn) {
    const uint32_t base = (smem_u32(dsm) + 1023u) & ~1023u;

    const int tid = threadIdx.x;
    const int wid = tid >> 5, lane = tid & 31;
    const int mw = wid & 1, nw = wid >> 1;

    const char* AhB = (const char*)(Ah + (size_t)bm * Dm);
    const char* AlB = (const char*)(Al + (size_t)bm * Dm);
    const char* BhB = (const char*)(Bh + (size_t)bn * Dm);
    const char* BlB = (const char*)(Bl + (size_t)bn * Dm);

    const int crow = tid >> 3;
    const int cch = tid & 7;
#define PLOAD(kb, st) do {                                                        \
        uint32_t tb = base + (st) * PSTAGE;                                       \
        _Pragma("unroll")                                                         \
        for (int t = 0; t < 4; t++) {                                             \
            int row = crow + t * 32;                                              \
            uint32_t off = row * 128 + cch * 16;                                  \
            uint32_t sw = off ^ ((off >> 3) & 0x70);                              \
            size_t gsrc = (size_t)row * 2048 + (size_t)(kb) * 128 + cch * 16;     \
            cp16(tb + sw,             AhB + gsrc);                                \
            cp16(tb + PTILE + sw,     AlB + gsrc);                                \
            cp16(tb + 2 * PTILE + sw, BhB + gsrc);                                \
            cp16(tb + 3 * PTILE + sw, BlB + gsrc);                                \
        }                                                                         \
    } while (0)

    float acc[4][4][4];
#pragma unroll
    for (int mi = 0; mi < 4; mi++)
#pragma unroll
        for (int ni = 0; ni < 4; ni++)
#pragma unroll
            for (int x = 0; x < 4; x++) acc[mi][ni][x] = 0.f;

#pragma unroll
    for (int s = 0; s < PSTG - 1; s++) { PLOAD(s, s); CP_COMMIT(); }

    for (int i = 0; i < NKBLK; i++) {
        CP_WAIT1();
        __syncthreads();
        if (i + PSTG - 1 < NKBLK) PLOAD(i + PSTG - 1, (i + PSTG - 1) % PSTG);
        CP_COMMIT();

        const uint32_t S = base + (i % PSTG) * PSTAGE;
#pragma unroll
        for (int kk = 0; kk < 4; kk++) {
            uint32_t ah[4][4], al[4][4];
#pragma unroll
            for (int mi = 0; mi < 4; mi++) {
                ldA(S,         mw * 64 + mi * 16, kk, lane, ah[mi]);
                ldA(S + PTILE, mw * 64 + mi * 16, kk, lane, al[mi]);
            }
            uint32_t bh[2][4], bl[2][4];
#pragma unroll
            for (int j = 0; j < 2; j++) {
                ldB(S + 2 * PTILE, nw * 32 + j * 16, kk, lane, bh[j]);
                ldB(S + 3 * PTILE, nw * 32 + j * 16, kk, lane, bl[j]);
            }
            // term-major: hh over all 16 tiles, then hl, then lh
#pragma unroll
            for (int mi = 0; mi < 4; mi++)
#pragma unroll
                for (int ni = 0; ni < 4; ni++)
                    mma16816(acc[mi][ni], ah[mi], &bh[ni >> 1][(ni & 1) * 2]);
#pragma unroll
            for (int mi = 0; mi < 4; mi++)
#pragma unroll
                for (int ni = 0; ni < 4; ni++)
                    mma16816(acc[mi][ni], ah[mi], &bl[ni >> 1][(ni & 1) * 2]);
#pragma unroll
            for (int mi = 0; mi < 4; mi++)
#pragma unroll
                for (int ni = 0; ni < 4; ni++)
                    mma16816(acc[mi][ni], al[mi], &bh[ni >> 1][(ni & 1) * 2]);
        }
    }
#undef PLOAD

    const int g = lane >> 2, tg = lane & 3;
#pragma unroll
    for (int ni = 0; ni < 4; ni++) {
        const int col = bn + nw * 32 + ni * 8 + tg * 2;
        const float2 b2 = *(const float2*)(bias + col);
#pragma unroll
        for (int mi = 0; mi < 4; mi++) {
            const int row = bm + mw * 64 + mi * 16 + g;
#pragma unroll
            for (int half = 0; half < 2; half++) {
                float x0 = acc[mi][ni][2 * half + 0] + b2.x;
                float x1 = acc[mi][ni][2 * half + 1] + b2.y;
                size_t o = (size_t)(row + 8 * half) * Dm + col;
                if (SPLIT) {
                    unsigned short h0, l0, h1, l1;
                    split_bf16(x0, h0, l0);
                    split_bf16(x1, h1, l1);
                    *(uint32_t*)(Ch + o) = (uint32_t)h0 | ((uint32_t)h1 << 16);
                    *(uint32_t*)(Cl + o) = (uint32_t)l0 | ((uint32_t)l1 << 16);
                } else {
                    *(float2*)(C + o) = make_float2(x0, x1);
                }
            }
        }
    }
}

// ---------------- fused QKV GEMM: 1280 CTAs, flat job decode ---------------------
// CTAs [0,512): K gemm (split out), [512,1024): V gemm (fp32 out), [1024,1280): Q.
__global__ __launch_bounds__(256, 1)
void qkv_gemm(const __nv_bfloat16* __restrict__ Sh, const __nv_bfloat16* __restrict__ Sl,
              const __nv_bfloat16* __restrict__ Th, const __nv_bfloat16* __restrict__ Tl,
              const __nv_bfloat16* __restrict__ Wqh, const __nv_bfloat16* __restrict__ Wql,
              const __nv_bfloat16* __restrict__ Wkh, const __nv_bfloat16* __restrict__ Wkl,
              const __nv_bfloat16* __restrict__ Wvh, const __nv_bfloat16* __restrict__ Wvl,
              const float* __restrict__ ipb, float* __restrict__ V,
              __nv_bfloat16* __restrict__ Qh, __nv_bfloat16* __restrict__ Ql,
              __nv_bfloat16* __restrict__ Kh, __nv_bfloat16* __restrict__ Kl) {
    extern __shared__ char dsm[];
    const int cta = blockIdx.x;
    if (cta < 512) {
        int r = cta;
        gemm_body<1>(dsm, Th, Tl, Wkh, Wkl, ipb + Dm, nullptr, Kh, Kl,
                     (r >> 3) * 128, (r & 7) * 128);
    } else if (cta < 1024) {
        int r = cta - 512;
        gemm_body<0>(dsm, Th, Tl, Wvh, Wvl, ipb + 2 * Dm, V, nullptr, nullptr,
                     (r >> 3) * 128, (r & 7) * 128);
    } else {
        int r = cta - 1024;
        gemm_body<1>(dsm, Sh, Sl, Wqh, Wql, ipb, nullptr, Qh, Ql,
                     (r >> 3) * 128, (r & 7) * 128);
    }
}

// ---------------- standalone paired GEMM (O and P projections, fp32 out) ---------
__global__ __launch_bounds__(256, 1)
void pair_gemm(const __nv_bfloat16* __restrict__ Ah, const __nv_bfloat16* __restrict__ Al,
               const __nv_bfloat16* __restrict__ Bh, const __nv_bfloat16* __restrict__ Bl,
               const float* __restrict__ bias, float* __restrict__ C) {
    extern __shared__ char dsm[];
    gemm_body<0>(dsm, Ah, Al, Bh, Bl, bias, C, nullptr, nullptr,
                 blockIdx.y * 128, blockIdx.x * 128);
}

// ---------------- fp32 -> hi/lo bf16 pair split ----------------------------------
__global__ __launch_bounds__(256)
void cvt_split(const float* __restrict__ X, __nv_bfloat16* __restrict__ H,
               __nv_bfloat16* __restrict__ L, int n4) {
    int i = blockIdx.x * 256 + threadIdx.x;
    if (i >= n4) return;
    float4 v = ((const float4*)X)[i];
    float f[4] = {v.x, v.y, v.z, v.w};
    uint64_t hw = 0, lw = 0;
#pragma unroll
    for (int j = 0; j < 4; j++) {
        unsigned short hb, lb;
        split_bf16(f[j], hb, lb);
        hw |= (uint64_t)hb << (16 * j);
        lw |= (uint64_t)lb << (16 * j);
    }
    ((uint64_t*)H)[i] = hw;
    ((uint64_t*)L)[i] = lw;
}

// fused weight splitter: blockIdx.y selects one of 5 weight matrices
__global__ __launch_bounds__(256)
void cvt_split_w(const float* __restrict__ w_in, const float* __restrict__ w_attn,
                 const float* __restrict__ w_proj,
                 __nv_bfloat16* __restrict__ qh, __nv_bfloat16* __restrict__ ql,
                 __nv_bfloat16* __restrict__ kh, __nv_bfloat16* __restrict__ kl,
                 __nv_bfloat16* __restrict__ vh, __nv_bfloat16* __restrict__ vl,
                 __nv_bfloat16* __restrict__ oh, __nv_bfloat16* __restrict__ ol,
                 __nv_bfloat16* __restrict__ ph, __nv_bfloat16* __restrict__ pl) {
    const int n4 = Dm * Dm / 4;
    int i = blockIdx.x * 256 + threadIdx.x;
    if (i >= n4) return;
    const float* src;
    __nv_bfloat16 *H, *L;
    switch (blockIdx.y) {
        case 0: src = w_in;               H = qh; L = ql; break;
        case 1: src = w_in + Dm * Dm;     H = kh; L = kl; break;
        case 2: src = w_in + 2 * Dm * Dm; H = vh; L = vl; break;
        case 3: src = w_attn;             H = oh; L = ol; break;
        default: src = w_proj;            H = ph; L = pl; break;
    }
    float4 v = ((const float4*)src)[i];
    float f[4] = {v.x, v.y, v.z, v.w};
    uint64_t hw = 0, lw = 0;
#pragma unroll
    for (int j = 0; j < 4; j++) {
        unsigned short hb, lb;
        split_bf16(f[j], hb, lb);
        hw |= (uint64_t)hb << (16 * j);
        lw |= (uint64_t)lb << (16 * j);
    }
    ((uint64_t*)H)[i] = hw;
    ((uint64_t*)L)[i] = lw;
}

// ---------------- V transpose + split: Vt[b][d][k] hi/lo -------------------------
__global__ __launch_bounds__(256)
void v_transpose_split(const float* __restrict__ V, __nv_bfloat16* __restrict__ Vth,
                       __nv_bfloat16* __restrict__ Vtl) {
    __shared__ float t[32][33];
    const int kt = blockIdx.x, dt = blockIdx.y, b = blockIdx.z;
    const int r = threadIdx.x >> 5, c = threadIdx.x & 31;
#pragma unroll
    for (int i = 0; i < 4; i++) {
        int kk = r + i * 8;
        t[c][kk] = V[(size_t)(b * LTxt + kt * 32 + kk) * Dm + dt * 32 + c];
    }
    __syncthreads();
#pragma unroll
    for (int i = 0; i < 4; i++) {
        int d = r + i * 8;
        float x = t[d][c];
        unsigned short hb, lb;
        split_bf16(x, hb, lb);
        size_t o = (size_t)(b * Dm + dt * 32 + d) * LTxt + kt * 32 + c;
        Vth[o] = __ushort_as_bfloat16(hb);
        Vtl[o] = __ushort_as_bfloat16(lb);
    }
}

// ---------------- HMMA attention: CTA per (qtile=64, head, batch) ----------------
#define NKB 8
#define SC_ST 520
#define A_OFF_SC 0
#define A_SZ_SC (64 * SC_ST * 4)
#define A_OFF_Q (A_SZ_SC)
#define A_OFF_KV (A_OFF_Q + 16384)
#define A_OFF_P (A_OFF_KV + 32768)
#define SMEM_ATTN2 (A_OFF_P + 16384)

__global__ __launch_bounds__(256, 1)
void attn_mma(const __nv_bfloat16* __restrict__ Qh, const __nv_bfloat16* __restrict__ Ql,
              const __nv_bfloat16* __restrict__ Kh, const __nv_bfloat16* __restrict__ Kl,
              const __nv_bfloat16* __restrict__ Vth, const __nv_bfloat16* __restrict__ Vtl,
              __nv_bfloat16* __restrict__ Ch, __nv_bfloat16* __restrict__ Cl) {
    extern __shared__ char sm8[];
    float* s_sc = (float*)(sm8 + A_OFF_SC);
    const uint32_t base = smem_u32(sm8);
    const uint32_t qhB = base + A_OFF_Q, qlB = qhB + 8192;
    const uint32_t kvB = base + A_OFF_KV;
    const uint32_t phB = base + A_OFF_P, plB = phB + 8192;

    const int tid = threadIdx.x, wid = tid >> 5, lane = tid & 31;
    const int mw = wid & 1, nw = wid >> 1;
    const int qt = blockIdx.x, h = blockIdx.y, b = blockIdx.z;
    const int q0 = qt * 64;

#pragma unroll
    for (int i = 0; i < 4; i++) {
        int c = tid + i * 256;
        int half = c >> 9, rem = c & 511, row = rem >> 3, ch = rem & 7;
        uint32_t off = row * 128 + ch * 16;
        off ^= (off >> 3) & 0x70;
        const char* s = (const char*)(half ? Ql : Qh) +
                        ((size_t)(b * LMAX + q0 + row) * Dm + h * DH) * 2 + ch * 16;
        cp16(qhB + half * 8192 + off, s);
    }
#define LOAD_KBLK(kb, st) do {                                                    \
        _Pragma("unroll")                                                         \
        for (int i = 0; i < 4; i++) {                                             \
            int c = tid + i * 256;                                                \
            int half = c >> 9, rem = c & 511, row = rem >> 3, ch = rem & 7;       \
            uint32_t off = row * 128 + ch * 16;                                   \
            off ^= (off >> 3) & 0x70;                                             \
            const char* s = (const char*)(half ? Kl : Kh) +                       \
                ((size_t)(b * LTxt + (kb) * 64 + row) * Dm + h * DH) * 2 + ch * 16; \
            cp16(kvB + (st) * 16384 + half * 8192 + off, s);                      \
        } } while (0)
#define LOAD_VBLK(kb, st) do {                                                    \
        _Pragma("unroll")                                                         \
        for (int i = 0; i < 4; i++) {                                             \
            int c = tid + i * 256;                                                \
            int half = c >> 9, rem = c & 511, row = rem >> 3, ch = rem & 7;       \
            uint32_t off = row * 128 + ch * 16;                                   \
            off ^= (off >> 3) & 0x70;                                             \
            const char* s = (const char*)(half ? Vtl : Vth) +                     \
                ((size_t)(b * Dm + h * DH + row) * LTxt + (kb) * 64) * 2 + ch * 16; \
            cp16(kvB + (st) * 16384 + half * 8192 + off, s);                      \
        } } while (0)

    LOAD_KBLK(0, 0);
    CP_COMMIT();

    const int g = lane >> 2, tg = lane & 3;

    // ---- phase 1: scores ----
    for (int kb = 0; kb < NKB; kb++) {
        CP_WAIT0();
        __syncthreads();
        if (kb + 1 < NKB) { LOAD_KBLK(kb + 1, (kb + 1) & 1); CP_COMMIT(); }

        const uint32_t khB = kvB + (kb & 1) * 16384, klB = khB + 8192;
        float sacc[2][2][4];
#pragma unroll
        for (int mi = 0; mi < 2; mi++)
#pragma unroll
            for (int ni = 0; ni < 2; ni++)
#pragma unroll
                for (int x = 0; x < 4; x++) sacc[mi][ni][x] = 0.f;

#pragma unroll
        for (int kk = 0; kk < 4; kk++) {
            uint32_t ah[2][4], al2[2][4], bh[4], bl[4];
            ldA(qhB, mw * 32, kk, lane, ah[0]);
            ldA(qhB, mw * 32 + 16, kk, lane, ah[1]);
            ldA(qlB, mw * 32, kk, lane, al2[0]);
            ldA(qlB, mw * 32 + 16, kk, lane, al2[1]);
            ldB(khB, nw * 16, kk, lane, bh);
            ldB(klB, nw * 16, kk, lane, bl);
#pragma unroll
            for (int mi = 0; mi < 2; mi++)
#pragma unroll
                for (int ni = 0; ni < 2; ni++)
                    mma16816(sacc[mi][ni], ah[mi], &bh[ni * 2]);
#pragma unroll
            for (int mi = 0; mi < 2; mi++)
#pragma unroll
                for (int ni = 0; ni < 2; ni++)
                    mma16816(sacc[mi][ni], ah[mi], &bl[ni * 2]);
#pragma unroll
            for (int mi = 0; mi < 2; mi++)
#pragma unroll
                for (int ni = 0; ni < 2; ni++)
                    mma16816(sacc[mi][ni], al2[mi], &bh[ni * 2]);
        }
#pragma unroll
        for (int mi = 0; mi < 2; mi++)
#pragma unroll
            for (int ni = 0; ni < 2; ni++) {
                int row = mw * 32 + mi * 16 + g;
                int col = kb * 64 + nw * 16 + ni * 8 + 2 * tg;
                *(float2*)(s_sc + (size_t)row * SC_ST + col) =
                    make_float2(sacc[mi][ni][0] * 0.125f, sacc[mi][ni][1] * 0.125f);
                *(float2*)(s_sc + (size_t)(row + 8) * SC_ST + col) =
                    make_float2(sacc[mi][ni][2] * 0.125f, sacc[mi][ni][3] * 0.125f);
            }
    }
    __syncthreads();

    LOAD_VBLK(0, 0);
    CP_COMMIT();

    // ---- softmax ----
    {
        int r = tid >> 2, j = tid & 3;
        float* row = s_sc + (size_t)r * SC_ST;
        float mx = -1e30f;
        for (int c = j; c < 512; c += 4) mx = fmaxf(mx, row[c]);
        mx = fmaxf(mx, __shfl_xor_sync(0xffffffffu, mx, 1));
        mx = fmaxf(mx, __shfl_xor_sync(0xffffffffu, mx, 2));
        float s = 0.f;
        for (int c = j; c < 512; c += 4) { float e = __expf(row[c] - mx); row[c] = e; s += e; }
        s += __shfl_xor_sync(0xffffffffu, s, 1);
        s += __shfl_xor_sync(0xffffffffu, s, 2);
        float inv = 1.f / s;
        for (int c = j; c < 512; c += 4) row[c] *= inv;
    }

    // ---- phase 2: ctx = P @ V ----
    float cacc[2][2][4];
#pragma unroll
    for (int mi = 0; mi < 2; mi++)
#pragma unroll
        for (int ni = 0; ni < 2; ni++)
#pragma unroll
            for (int x = 0; x < 4; x++) cacc[mi][ni][x] = 0.f;

    for (int kb = 0; kb < NKB; kb++) {
        CP_WAIT0();
        __syncthreads();
        if (kb + 1 < NKB) { LOAD_VBLK(kb + 1, (kb + 1) & 1); CP_COMMIT(); }

#pragma unroll
        for (int i = 0; i < 2; i++) {
            int c = tid + i * 256;
            int row = c >> 3, ch = c & 7;
            const float* src = s_sc + (size_t)row * SC_ST + kb * 64 + ch * 8;
            uint32_t hw[4], lw[4];
#pragma unroll
            for (int j = 0; j < 4; j++) {
                unsigned short h0, l0, h1, l1;
                split_bf16(src[2 * j], h0, l0);
                split_bf16(src[2 * j + 1], h1, l1);
                hw[j] = (uint32_t)h0 | ((uint32_t)h1 << 16);
                lw[j] = (uint32_t)l0 | ((uint32_t)l1 << 16);
            }
            uint32_t off = row * 128 + ch * 16;
            off ^= (off >> 3) & 0x70;
            *(uint4*)(sm8 + A_OFF_P + off) = make_uint4(hw[0], hw[1], hw[2], hw[3]);
            *(uint4*)(sm8 + A_OFF_P + 8192 + off) = make_uint4(lw[0], lw[1], lw[2], lw[3]);
        }
        __syncthreads();

        const uint32_t vhB = kvB + (kb & 1) * 16384, vlB = vhB + 8192;
#pragma unroll
        for (int kk = 0; kk < 4; kk++) {
            uint32_t ap[2][4], apl[2][4], bv[4], bvl[4];
            ldA(phB, mw * 32, kk, lane, ap[0]);
            ldA(phB, mw * 32 + 16, kk, lane, ap[1]);
            ldA(plB, mw * 32, kk, lane, apl[0]);
            ldA(plB, mw * 32 + 16, kk, lane, apl[1]);
            ldB(vhB, nw * 16, kk, lane, bv);
            ldB(vlB, nw * 16, kk, lane, bvl);
#pragma unroll
            for (int mi = 0; mi < 2; mi++)
#pragma unroll
                for (int ni = 0; ni < 2; ni++)
                    mma16816(cacc[mi][ni], ap[mi], &bv[ni * 2]);
#pragma unroll
            for (int mi = 0; mi < 2; mi++)
#pragma unroll
                for (int ni = 0; ni < 2; ni++)
                    mma16816(cacc[mi][ni], ap[mi], &bvl[ni * 2]);
#pragma unroll
            for (int mi = 0; mi < 2; mi++)
#pragma unroll
                for (int ni = 0; ni < 2; ni++)
                    mma16816(cacc[mi][ni], apl[mi], &bv[ni * 2]);
        }
    }

    // ---- epilogue: emit ctx hi/lo bf16 directly ----
#pragma unroll
    for (int mi = 0; mi < 2; mi++)
#pragma unroll
        for (int ni = 0; ni < 2; ni++) {
            int row = b * LMAX + q0 + mw * 32 + mi * 16 + g;
            int col = h * DH + nw * 16 + ni * 8 + 2 * tg;
#pragma unroll
            for (int half = 0; half < 2; half++) {
                size_t o = (size_t)(row + 8 * half) * Dm + col;
                unsigned short h0, l0, h1, l1;
                split_bf16(cacc[mi][ni][2 * half + 0], h0, l0);
                split_bf16(cacc[mi][ni][2 * half + 1], h1, l1);
                *(uint32_t*)(Ch + o) = (uint32_t)h0 | ((uint32_t)h1 << 16);
                *(uint32_t*)(Cl + o) = (uint32_t)l0 | ((uint32_t)l1 << 16);
            }
        }
}

// ---------------- LayerNorm: fp32 in -> hi/lo bf16 pair out ----------------------
__global__ __launch_bounds__(256)
void ln_kernel(const float* __restrict__ X, const float* __restrict__ gw,
               const float* __restrict__ bw, __nv_bfloat16* __restrict__ H,
               __nv_bfloat16* __restrict__ L) {
    __shared__ float red[8];
    __shared__ float stat[2];
    const int tid = threadIdx.x;
    const float* xp = X + (size_t)blockIdx.x * Dm + tid * 4;
    float4 v = *(const float4*)xp;

    float s = v.x + v.y + v.z + v.w;
#pragma unroll
    for (int o = 16; o; o >>= 1) s += __shfl_xor_sync(0xffffffffu, s, o);
    if ((tid & 31) == 0) red[tid >> 5] = s;
    __syncthreads();
    if (tid == 0) {
        float t = 0.f;
#pragma unroll
        for (int i = 0; i < 8; i++) t += red[i];
        stat[0] = t * (1.f / Dm);
    }
    __syncthreads();
    const float mu = stat[0];
    float d0 = v.x - mu, d1 = v.y - mu, d2 = v.z - mu, d3 = v.w - mu;

    float s2 = d0 * d0 + d1 * d1 + d2 * d2 + d3 * d3;
#pragma unroll
    for (int o = 16; o; o >>= 1) s2 += __shfl_xor_sync(0xffffffffu, s2, o);
    if ((tid & 31) == 0) red[tid >> 5] = s2;
    __syncthreads();
    if (tid == 0) {
        float t = 0.f;
#pragma unroll
        for (int i = 0; i < 8; i++) t += red[i];
        stat[1] = t * (1.f / Dm);
    }
    __syncthreads();
    const float rstd = rsqrtf(stat[1] + LN_EPS);

    float4 g4 = *(const float4*)(gw + tid * 4);
    float4 b4 = *(const float4*)(bw + tid * 4);
    float y[4];
    y[0] = d0 * rstd * g4.x + b4.x;
    y[1] = d1 * rstd * g4.y + b4.y;
    y[2] = d2 * rstd * g4.z + b4.z;
    y[3] = d3 * rstd * g4.w + b4.w;

    uint64_t hw = 0, lw = 0;
#pragma unroll
    for (int j = 0; j < 4; j++) {
        unsigned short hb, lb;
        split_bf16(y[j], hb, lb);
        hw |= (uint64_t)hb << (16 * j);
        lw |= (uint64_t)lb << (16 * j);
    }
    size_t o = (size_t)blockIdx.x * Dm + tid * 4;
    *(uint64_t*)(H + o) = hw;
    *(uint64_t*)(L + o) = lw;
}

// ---------------- segment mean ---------------------------------------------------
__global__ __launch_bounds__(256)
void seg_mean_kernel(const float* __restrict__ X, float* __restrict__ out) {
    const int b = blockIdx.y;
    const int d = blockIdx.x * 256 + threadIdx.x;
    const float* base = X + (size_t)(b * LMAX) * Dm + d;
    float s = 0.f;
#pragma unroll 8
    for (int l = 0; l < LMAX; l++) s += base[(size_t)l * Dm];
    out[b * Dm + d] = s * (1.f / (float)LMAX);
}

// ---------------- launch ---------------------------------------------------------
extern "C" void kernel_launch(void* const* d_in, const int* in_sizes, int n_in,
                              void* d_out, int out_size) {
    const float* struct_tok = (const float*)d_in[0];
    const float* text_tok   = (const float*)d_in[1];
    const float* in_proj_w  = (const float*)d_in[2];
    const float* in_proj_b  = (const float*)d_in[3];
    const float* attn_out_w = (const float*)d_in[4];
    const float* attn_out_b = (const float*)d_in[5];
    const float* ln_g       = (const float*)d_in[6];
    const float* ln_b       = (const float*)d_in[7];
    const float* proj_w     = (const float*)d_in[8];
    const float* proj_b     = (const float*)d_in[9];
    float* out = (float*)d_out;

    float *pV, *pF1, *pF2;
    __nv_bfloat16 *pSh, *pSl, *pTh, *pTl, *pQh, *pQl, *pKh, *pKl, *pVth, *pVtl;
    __nv_bfloat16 *pCh, *pCl, *pF1h, *pF1l;
    __nv_bfloat16 *pWqh, *pWql, *pWkh, *pWkl, *pWvh, *pWvl, *pWoh, *pWol, *pWph, *pWpl;
    cudaGetSymbolAddress((void**)&pV, g_V);
    cudaGetSymbolAddress((void**)&pF1, g_f1);
    cudaGetSymbolAddress((void**)&pF2, g_f2);
    cudaGetSymbolAddress((void**)&pSh, g_Sh);
    cudaGetSymbolAddress((void**)&pSl, g_Sl);
    cudaGetSymbolAddress((void**)&pTh, g_Th);
    cudaGetSymbolAddress((void**)&pTl, g_Tl);
    cudaGetSymbolAddress((void**)&pQh, g_Qh);
    cudaGetSymbolAddress((void**)&pQl, g_Ql);
    cudaGetSymbolAddress((void**)&pKh, g_Kh);
    cudaGetSymbolAddress((void**)&pKl, g_Kl);
    cudaGetSymbolAddress((void**)&pVth, g_Vth);
    cudaGetSymbolAddress((void**)&pVtl, g_Vtl);
    cudaGetSymbolAddress((void**)&pCh, g_Ch);
    cudaGetSymbolAddress((void**)&pCl, g_Cl);
    cudaGetSymbolAddress((void**)&pF1h, g_F1h);
    cudaGetSymbolAddress((void**)&pF1l, g_F1l);
    cudaGetSymbolAddress((void**)&pWqh, g_Wqh);
    cudaGetSymbolAddress((void**)&pWql, g_Wql);
    cudaGetSymbolAddress((void**)&pWkh, g_Wkh);
    cudaGetSymbolAddress((void**)&pWkl, g_Wkl);
    cudaGetSymbolAddress((void**)&pWvh, g_Wvh);
    cudaGetSymbolAddress((void**)&pWvl, g_Wvl);
    cudaGetSymbolAddress((void**)&pWoh, g_Woh);
    cudaGetSymbolAddress((void**)&pWol, g_Wol);
    cudaGetSymbolAddress((void**)&pWph, g_Wph);
    cudaGetSymbolAddress((void**)&pWpl, g_Wpl);
    cudaFuncSetAttribute(qkv_gemm,
                         cudaFuncAttributeMaxDynamicSharedMemorySize, SMEM_PGEMM);
    cudaFuncSetAttribute(pair_gemm,
                         cudaFuncAttributeMaxDynamicSharedMemorySize, SMEM_PGEMM);
    cudaFuncSetAttribute(attn_mma,
                         cudaFuncAttributeMaxDynamicSharedMemorySize, SMEM_ATTN2);

    const int n4S = Ntok * Dm / 4;
    const int n4T = Bq * LTxt * Dm / 4;
    const int n4W = Dm * Dm / 4;

    const dim3 gQ(Dm / 128, Ntok / 128);           // (8, 32)

    // operand splits
    cvt_split<<<(n4T + 255) / 256, 256>>>(text_tok, pTh, pTl, n4T);
    cvt_split<<<(n4S + 255) / 256, 256>>>(struct_tok, pSh, pSl, n4S);
    cvt_split_w<<<dim3((n4W + 255) / 256, 5), 256>>>(
        in_proj_w, attn_out_w, proj_w,
        pWqh, pWql, pWkh, pWkl, pWvh, pWvl, pWoh, pWol, pWph, pWpl);

    // fused QKV projections: one 1280-CTA launch (R13 gemm body inside)
    qkv_gemm<<<1280, 256, SMEM_PGEMM>>>(pSh, pSl, pTh, pTl,
                                        pWqh, pWql, pWkh, pWkl, pWvh, pWvl,
                                        in_proj_b, pV, pQh, pQl, pKh, pKl);

    v_transpose_split<<<dim3(LTxt / 32, Dm / 32, Bq), 256>>>(pV, pVth, pVtl);

    // attention (HMMA split-bf16) -> ctx hi/lo
    attn_mma<<<dim3(LMAX / 64, Hh, Bq), 256, SMEM_ATTN2>>>(pQh, pQl, pKh, pKl,
                                                           pVth, pVtl, pCh, pCl);

    // attn_out GEMM + LN + proj GEMM
    pair_gemm<<<gQ, 256, SMEM_PGEMM>>>(pCh, pCl, pWoh, pWol, attn_out_b, pF1);
    ln_kernel<<<Ntok, 256>>>(pF1, ln_g, ln_b, pF1h, pF1l);
    pair_gemm<<<gQ, 256, SMEM_PGEMM>>>(pF1h, pF1l, pWph, pWpl, proj_b, pF2);

    // per-batch mean -> output (16, 1024)
    seg_mean_kernel<<<dim3(Dm / 256, Bq), 256>>>(pF2, out);

    (void)in_sizes; (void)n_in; (void)out_size;
}

// round 17
// speedup vs baseline: 2.8162x; 1.0266x over previous
#include <cuda_runtime.h>
#include <cuda_bf16.h>
#include <cstdint>

// Problem constants (fixed by setup_inputs)
#define Bq 16
#define LTxt 512
#define Dm 1024
#define Ntok 4096
#define Hh 16
#define DH 64
#define LMAX 256
#define LN_EPS 1e-5f

#define NKBLK 16            // Dm / 64 real k-blocks
#define PSTG 3              // pipeline stages
#define PTILE 16384         // one 128x64 bf16 tile (128B rows)
#define PSTAGE 65536        // Ah + Al + Bh + Bl
#define SMEM_PGEMM (1024 + PSTG * PSTAGE)

// ---------------- scratch (__device__ globals; no allocs allowed) ----------------
__device__ float g_V[Bq * LTxt * Dm];
__device__ float g_f1[Ntok * Dm];
__device__ float g_f2[Ntok * Dm];

__device__ __nv_bfloat16 g_Sh[Ntok * Dm],        g_Sl[Ntok * Dm];
__device__ __nv_bfloat16 g_Th[Bq * LTxt * Dm],   g_Tl[Bq * LTxt * Dm];
__device__ __nv_bfloat16 g_Qh[Ntok * Dm],        g_Ql[Ntok * Dm];
__device__ __nv_bfloat16 g_Kh[Bq * LTxt * Dm],   g_Kl[Bq * LTxt * Dm];
__device__ __nv_bfloat16 g_Vth[Bq * Dm * LTxt],  g_Vtl[Bq * Dm * LTxt];   // [b][d][k]
__device__ __nv_bfloat16 g_Ch[Ntok * Dm],        g_Cl[Ntok * Dm];
__device__ __nv_bfloat16 g_F1h[Ntok * Dm],       g_F1l[Ntok * Dm];
__device__ __nv_bfloat16 g_Wqh[Dm * Dm], g_Wql[Dm * Dm];
__device__ __nv_bfloat16 g_Wkh[Dm * Dm], g_Wkl[Dm * Dm];
__device__ __nv_bfloat16 g_Wvh[Dm * Dm], g_Wvl[Dm * Dm];
__device__ __nv_bfloat16 g_Woh[Dm * Dm], g_Wol[Dm * Dm];
__device__ __nv_bfloat16 g_Wph[Dm * Dm], g_Wpl[Dm * Dm];

// ---------------- helpers --------------------------------------------------------
__device__ __forceinline__ uint32_t smem_u32(const void* p) {
    uint32_t a;
    asm("{ .reg .u64 t; cvta.to.shared.u64 t, %1; cvt.u32.u64 %0, t; }"
        : "=r"(a) : "l"(p));
    return a;
}
__device__ __forceinline__ void cp16(uint32_t dst, const void* src) {
    asm volatile("cp.async.cg.shared.global [%0], [%1], 16;" :: "r"(dst), "l"(src));
}
#define CP_COMMIT() asm volatile("cp.async.commit_group;" ::: "memory")
#define CP_WAIT1()  asm volatile("cp.async.wait_group 1;" ::: "memory")
#define CP_WAIT0()  asm volatile("cp.async.wait_group 0;" ::: "memory")

#define LDSM_X4(r0, r1, r2, r3, addr)                                            \
    asm volatile("ldmatrix.sync.aligned.m8n8.x4.shared.b16 {%0,%1,%2,%3}, [%4];" \
                 : "=r"(r0), "=r"(r1), "=r"(r2), "=r"(r3) : "r"(addr))

__device__ __forceinline__ void mma16816(float* c, const uint32_t* a,
                                         const uint32_t* b) {
    asm volatile(
        "mma.sync.aligned.m16n8k16.row.col.f32.bf16.bf16.f32 "
        "{%0,%1,%2,%3}, {%4,%5,%6,%7}, {%8,%9}, {%0,%1,%2,%3};"
        : "+f"(c[0]), "+f"(c[1]), "+f"(c[2]), "+f"(c[3])
        : "r"(a[0]), "r"(a[1]), "r"(a[2]), "r"(a[3]), "r"(b[0]), "r"(b[1]));
}

// A-fragment (m16k16) from a 128B-row swizzled tile
__device__ __forceinline__ void ldA(uint32_t tb, int mrb, int kk, int lane,
                                    uint32_t* a) {
    int r = mrb + (lane & 7) + ((lane >> 3) & 1) * 8;
    uint32_t addr = tb + r * 128 +
                    (((uint32_t)(kk * 32 + (lane >> 4) * 16)) ^ ((lane & 7) * 16));
    LDSM_X4(a[0], a[1], a[2], a[3], addr);
}
// two B-fragments (n8k16 at nrb, nrb+8)
__device__ __forceinline__ void ldB(uint32_t tb, int nrb, int kk, int lane,
                                    uint32_t* b) {
    int r = nrb + (lane & 7) + ((lane >> 4) & 1) * 8;
    uint32_t addr = tb + r * 128 +
                    (((uint32_t)(kk * 32 + ((lane >> 3) & 1) * 16)) ^ ((lane & 7) * 16));
    LDSM_X4(b[0], b[1], b[2], b[3], addr);
}

__device__ __forceinline__ void split_bf16(float x, unsigned short& hi,
                                           unsigned short& lo) {
    __nv_bfloat16 h = __float2bfloat16_rn(x);
    __nv_bfloat16 l = __float2bfloat16_rn(x - __bfloat162float(h));
    hi = __bfloat16_as_ushort(h);
    lo = __bfloat16_as_ushort(l);
}

// one kk-step of the 128x128 pair GEMM: 12 ldsm + 48 MMA (term-major hh, hl, lh)
__device__ __forceinline__ void gemm_kk(uint32_t S, int kk, int mw, int nw,
                                        int lane, float (*acc)[4][4]) {
    uint32_t ah[4][4], al[4][4];
#pragma unroll
    for (int mi = 0; mi < 4; mi++) {
        ldA(S,         mw * 64 + mi * 16, kk, lane, ah[mi]);
        ldA(S + PTILE, mw * 64 + mi * 16, kk, lane, al[mi]);
    }
    uint32_t bh[2][4], bl[2][4];
#pragma unroll
    for (int j = 0; j < 2; j++) {
        ldB(S + 2 * PTILE, nw * 32 + j * 16, kk, lane, bh[j]);
        ldB(S + 3 * PTILE, nw * 32 + j * 16, kk, lane, bl[j]);
    }
#pragma unroll
    for (int mi = 0; mi < 4; mi++)
#pragma unroll
        for (int ni = 0; ni < 4; ni++)
            mma16816(acc[mi][ni], ah[mi], &bh[ni >> 1][(ni & 1) * 2]);
#pragma unroll
    for (int mi = 0; mi < 4; mi++)
#pragma unroll
        for (int ni = 0; ni < 4; ni++)
            mma16816(acc[mi][ni], ah[mi], &bl[ni >> 1][(ni & 1) * 2]);
#pragma unroll
    for (int mi = 0; mi < 4; mi++)
#pragma unroll
        for (int ni = 0; ni < 4; ni++)
            mma16816(acc[mi][ni], al[mi], &bh[ni >> 1][(ni & 1) * 2]);
}

// ---------------- shared GEMM body -----------------------------------------------
// Same pipeline accounting as the passing R16 kernel (full PLOAD, one commit per
// iteration, CP_WAIT1, PSTG=3). Only change: PLOAD+COMMIT issued AFTER the kk=0
// fragment/MMA block, so the tensor pipe starts right at the barrier and the
// load burst overlaps kk=1..3 MMA issue.
template <int SPLIT>
__device__ __forceinline__ void gemm_body(
    char* dsm,
    const __nv_bfloat16* __restrict__ Ah, const __nv_bfloat16* __restrict__ Al,
    const __nv_bfloat16* __restrict__ Bh, const __nv_bfloat16* __restrict__ Bl,
    const float* __restrict__ bias, float* __restrict__ C,
    __nv_bfloat16* __restrict__ Ch, __nv_bfloat16* __restrict__ Cl,
    int bm, int bn) {
    const uint32_t base = (smem_u32(dsm) + 1023u) & ~1023u;

    const int tid = threadIdx.x;
    const int wid = tid >> 5, lane = tid & 31;
    const int mw = wid & 1, nw = wid >> 1;

    const char* AhB = (const char*)(Ah + (size_t)bm * Dm);
    const char* AlB = (const char*)(Al + (size_t)bm * Dm);
    const char* BhB = (const char*)(Bh + (size_t)bn * Dm);
    const char* BlB = (const char*)(Bl + (size_t)bn * Dm);

    const int crow = tid >> 3;
    const int cch = tid & 7;
#define PLOAD(kb, st) do {                                                        \
        uint32_t tb = base + (st) * PSTAGE;                                       \
        _Pragma("unroll")                                                         \
        for (int t = 0; t < 4; t++) {                                             \
            int row = crow + t * 32;                                              \
            uint32_t off = row * 128 + cch * 16;                                  \
            uint32_t sw = off ^ ((off >> 3) & 0x70);                              \
            size_t gsrc = (size_t)row * 2048 + (size_t)(kb) * 128 + cch * 16;     \
            cp16(tb + sw,             AhB + gsrc);                                \
            cp16(tb + PTILE + sw,     AlB + gsrc);                                \
            cp16(tb + 2 * PTILE + sw, BhB + gsrc);                                \
            cp16(tb + 3 * PTILE + sw, BlB + gsrc);                                \
        }                                                                         \
    } while (0)

    float acc[4][4][4];
#pragma unroll
    for (int mi = 0; mi < 4; mi++)
#pragma unroll
        for (int ni = 0; ni < 4; ni++)
#pragma unroll
            for (int x = 0; x < 4; x++) acc[mi][ni][x] = 0.f;

#pragma unroll
    for (int s = 0; s < PSTG - 1; s++) { PLOAD(s, s); CP_COMMIT(); }

    for (int i = 0; i < NKBLK; i++) {
        CP_WAIT1();
        __syncthreads();
        const uint32_t S = base + (i % PSTG) * PSTAGE;

        // kk = 0 on resident data first — tensor pipe starts immediately
        gemm_kk(S, 0, mw, nw, lane, acc);

        // stage fill for block i+2, overlapping kk = 1..3
        if (i + PSTG - 1 < NKBLK) PLOAD(i + PSTG - 1, (i + PSTG - 1) % PSTG);
        CP_COMMIT();

#pragma unroll
        for (int kk = 1; kk < 4; kk++)
            gemm_kk(S, kk, mw, nw, lane, acc);
    }
#undef PLOAD

    const int g = lane >> 2, tg = lane & 3;
#pragma unroll
    for (int ni = 0; ni < 4; ni++) {
        const int col = bn + nw * 32 + ni * 8 + tg * 2;
        const float2 b2 = *(const float2*)(bias + col);
#pragma unroll
        for (int mi = 0; mi < 4; mi++) {
            const int row = bm + mw * 64 + mi * 16 + g;
#pragma unroll
            for (int half = 0; half < 2; half++) {
                float x0 = acc[mi][ni][2 * half + 0] + b2.x;
                float x1 = acc[mi][ni][2 * half + 1] + b2.y;
                size_t o = (size_t)(row + 8 * half) * Dm + col;
                if (SPLIT) {
                    unsigned short h0, l0, h1, l1;
                    split_bf16(x0, h0, l0);
                    split_bf16(x1, h1, l1);
                    *(uint32_t*)(Ch + o) = (uint32_t)h0 | ((uint32_t)h1 << 16);
                    *(uint32_t*)(Cl + o) = (uint32_t)l0 | ((uint32_t)l1 << 16);
                } else {
                    *(float2*)(C + o) = make_float2(x0, x1);
                }
            }
        }
    }
}

// ---------------- fused QKV GEMM: 1280 CTAs, flat job decode ---------------------
// CTAs [0,512): K gemm (split out), [512,1024): V gemm (fp32 out), [1024,1280): Q.
__global__ __launch_bounds__(256, 1)
void qkv_gemm(const __nv_bfloat16* __restrict__ Sh, const __nv_bfloat16* __restrict__ Sl,
              const __nv_bfloat16* __restrict__ Th, const __nv_bfloat16* __restrict__ Tl,
              const __nv_bfloat16* __restrict__ Wqh, const __nv_bfloat16* __restrict__ Wql,
              const __nv_bfloat16* __restrict__ Wkh, const __nv_bfloat16* __restrict__ Wkl,
              const __nv_bfloat16* __restrict__ Wvh, const __nv_bfloat16* __restrict__ Wvl,
              const float* __restrict__ ipb, float* __restrict__ V,
              __nv_bfloat16* __restrict__ Qh, __nv_bfloat16* __restrict__ Ql,
              __nv_bfloat16* __restrict__ Kh, __nv_bfloat16* __restrict__ Kl) {
    extern __shared__ char dsm[];
    const int cta = blockIdx.x;
    if (cta < 512) {
        int r = cta;
        gemm_body<1>(dsm, Th, Tl, Wkh, Wkl, ipb + Dm, nullptr, Kh, Kl,
                     (r >> 3) * 128, (r & 7) * 128);
    } else if (cta < 1024) {
        int r = cta - 512;
        gemm_body<0>(dsm, Th, Tl, Wvh, Wvl, ipb + 2 * Dm, V, nullptr, nullptr,
                     (r >> 3) * 128, (r & 7) * 128);
    } else {
        int r = cta - 1024;
        gemm_body<1>(dsm, Sh, Sl, Wqh, Wql, ipb, nullptr, Qh, Ql,
                     (r >> 3) * 128, (r & 7) * 128);
    }
}

// ---------------- standalone paired GEMM (O and P projections, fp32 out) ---------
__global__ __launch_bounds__(256, 1)
void pair_gemm(const __nv_bfloat16* __restrict__ Ah, const __nv_bfloat16* __restrict__ Al,
               const __nv_bfloat16* __restrict__ Bh, const __nv_bfloat16* __restrict__ Bl,
               const float* __restrict__ bias, float* __restrict__ C) {
    extern __shared__ char dsm[];
    gemm_body<0>(dsm, Ah, Al, Bh, Bl, bias, C, nullptr, nullptr,
                 blockIdx.y * 128, blockIdx.x * 128);
}

// ---------------- fp32 -> hi/lo bf16 pair split ----------------------------------
__global__ __launch_bounds__(256)
void cvt_split(const float* __restrict__ X, __nv_bfloat16* __restrict__ H,
               __nv_bfloat16* __restrict__ L, int n4) {
    int i = blockIdx.x * 256 + threadIdx.x;
    if (i >= n4) return;
    float4 v = ((const float4*)X)[i];
    float f[4] = {v.x, v.y, v.z, v.w};
    uint64_t hw = 0, lw = 0;
#pragma unroll
    for (int j = 0; j < 4; j++) {
        unsigned short hb, lb;
        split_bf16(f[j], hb, lb);
        hw |= (uint64_t)hb << (16 * j);
        lw |= (uint64_t)lb << (16 * j);
    }
    ((uint64_t*)H)[i] = hw;
    ((uint64_t*)L)[i] = lw;
}

// fused weight splitter: blockIdx.y selects one of 5 weight matrices
__global__ __launch_bounds__(256)
void cvt_split_w(const float* __restrict__ w_in, const float* __restrict__ w_attn,
                 const float* __restrict__ w_proj,
                 __nv_bfloat16* __restrict__ qh, __nv_bfloat16* __restrict__ ql,
                 __nv_bfloat16* __restrict__ kh, __nv_bfloat16* __restrict__ kl,
                 __nv_bfloat16* __restrict__ vh, __nv_bfloat16* __restrict__ vl,
                 __nv_bfloat16* __restrict__ oh, __nv_bfloat16* __restrict__ ol,
                 __nv_bfloat16* __restrict__ ph, __nv_bfloat16* __restrict__ pl) {
    const int n4 = Dm * Dm / 4;
    int i = blockIdx.x * 256 + threadIdx.x;
    if (i >= n4) return;
    const float* src;
    __nv_bfloat16 *H, *L;
    switch (blockIdx.y) {
        case 0: src = w_in;               H = qh; L = ql; break;
        case 1: src = w_in + Dm * Dm;     H = kh; L = kl; break;
        case 2: src = w_in + 2 * Dm * Dm; H = vh; L = vl; break;
        case 3: src = w_attn;             H = oh; L = ol; break;
        default: src = w_proj;            H = ph; L = pl; break;
    }
    float4 v = ((const float4*)src)[i];
    float f[4] = {v.x, v.y, v.z, v.w};
    uint64_t hw = 0, lw = 0;
#pragma unroll
    for (int j = 0; j < 4; j++) {
        unsigned short hb, lb;
        split_bf16(f[j], hb, lb);
        hw |= (uint64_t)hb << (16 * j);
        lw |= (uint64_t)lb << (16 * j);
    }
    ((uint64_t*)H)[i] = hw;
    ((uint64_t*)L)[i] = lw;
}

// ---------------- V transpose + split: Vt[b][d][k] hi/lo -------------------------
__global__ __launch_bounds__(256)
void v_transpose_split(const float* __restrict__ V, __nv_bfloat16* __restrict__ Vth,
                       __nv_bfloat16* __restrict__ Vtl) {
    __shared__ float t[32][33];
    const int kt = blockIdx.x, dt = blockIdx.y, b = blockIdx.z;
    const int r = threadIdx.x >> 5, c = threadIdx.x & 31;
#pragma unroll
    for (int i = 0; i < 4; i++) {
        int kk = r + i * 8;
        t[c][kk] = V[(size_t)(b * LTxt + kt * 32 + kk) * Dm + dt * 32 + c];
    }
    __syncthreads();
#pragma unroll
    for (int i = 0; i < 4; i++) {
        int d = r + i * 8;
        float x = t[d][c];
        unsigned short hb, lb;
        split_bf16(x, hb, lb);
        size_t o = (size_t)(b * Dm + dt * 32 + d) * LTxt + kt * 32 + c;
        Vth[o] = __ushort_as_bfloat16(hb);
        Vtl[o] = __ushort_as_bfloat16(lb);
    }
}

// ---------------- HMMA attention: CTA per (qtile=64, head, batch) ----------------
#define NKB 8
#define SC_ST 520
#define A_OFF_SC 0
#define A_SZ_SC (64 * SC_ST * 4)
#define A_OFF_Q (A_SZ_SC)
#define A_OFF_KV (A_OFF_Q + 16384)
#define A_OFF_P (A_OFF_KV + 32768)
#define SMEM_ATTN2 (A_OFF_P + 16384)

__global__ __launch_bounds__(256, 1)
void attn_mma(const __nv_bfloat16* __restrict__ Qh, const __nv_bfloat16* __restrict__ Ql,
              const __nv_bfloat16* __restrict__ Kh, const __nv_bfloat16* __restrict__ Kl,
              const __nv_bfloat16* __restrict__ Vth, const __nv_bfloat16* __restrict__ Vtl,
              __nv_bfloat16* __restrict__ Ch, __nv_bfloat16* __restrict__ Cl) {
    extern __shared__ char sm8[];
    float* s_sc = (float*)(sm8 + A_OFF_SC);
    const uint32_t base = smem_u32(sm8);
    const uint32_t qhB = base + A_OFF_Q, qlB = qhB + 8192;
    const uint32_t kvB = base + A_OFF_KV;
    const uint32_t phB = base + A_OFF_P, plB = phB + 8192;

    const int tid = threadIdx.x, wid = tid >> 5, lane = tid & 31;
    const int mw = wid & 1, nw = wid >> 1;
    const int qt = blockIdx.x, h = blockIdx.y, b = blockIdx.z;
    const int q0 = qt * 64;

#pragma unroll
    for (int i = 0; i < 4; i++) {
        int c = tid + i * 256;
        int half = c >> 9, rem = c & 511, row = rem >> 3, ch = rem & 7;
        uint32_t off = row * 128 + ch * 16;
        off ^= (off >> 3) & 0x70;
        const char* s = (const char*)(half ? Ql : Qh) +
                        ((size_t)(b * LMAX + q0 + row) * Dm + h * DH) * 2 + ch * 16;
        cp16(qhB + half * 8192 + off, s);
    }
#define LOAD_KBLK(kb, st) do {                                                    \
        _Pragma("unroll")                                                         \
        for (int i = 0; i < 4; i++) {                                             \
            int c = tid + i * 256;                                                \
            int half = c >> 9, rem = c & 511, row = rem >> 3, ch = rem & 7;       \
            uint32_t off = row * 128 + ch * 16;                                   \
            off ^= (off >> 3) & 0x70;                                             \
            const char* s = (const char*)(half ? Kl : Kh) +                       \
                ((size_t)(b * LTxt + (kb) * 64 + row) * Dm + h * DH) * 2 + ch * 16; \
            cp16(kvB + (st) * 16384 + half * 8192 + off, s);                      \
        } } while (0)
#define LOAD_VBLK(kb, st) do {                                                    \
        _Pragma("unroll")                                                         \
        for (int i = 0; i < 4; i++) {                                             \
            int c = tid + i * 256;                                                \
            int half = c >> 9, rem = c & 511, row = rem >> 3, ch = rem & 7;       \
            uint32_t off = row * 128 + ch * 16;                                   \
            off ^= (off >> 3) & 0x70;                                             \
            const char* s = (const char*)(half ? Vtl : Vth) +                     \
                ((size_t)(b * Dm + h * DH + row) * LTxt + (kb) * 64) * 2 + ch * 16; \
            cp16(kvB + (st) * 16384 + half * 8192 + off, s);                      \
        } } while (0)

    LOAD_KBLK(0, 0);
    CP_COMMIT();

    const int g = lane >> 2, tg = lane & 3;

    // ---- phase 1: scores ----
    for (int kb = 0; kb < NKB; kb++) {
        CP_WAIT0();
        __syncthreads();
        if (kb + 1 < NKB) { LOAD_KBLK(kb + 1, (kb + 1) & 1); CP_COMMIT(); }

        const uint32_t khB = kvB + (kb & 1) * 16384, klB = khB + 8192;
        float sacc[2][2][4];
#pragma unroll
        for (int mi = 0; mi < 2; mi++)
#pragma unroll
            for (int ni = 0; ni < 2; ni++)
#pragma unroll
                for (int x = 0; x < 4; x++) sacc[mi][ni][x] = 0.f;

#pragma unroll
        for (int kk = 0; kk < 4; kk++) {
            uint32_t ah[2][4], al2[2][4], bh[4], bl[4];
            ldA(qhB, mw * 32, kk, lane, ah[0]);
            ldA(qhB, mw * 32 + 16, kk, lane, ah[1]);
            ldA(qlB, mw * 32, kk, lane, al2[0]);
            ldA(qlB, mw * 32 + 16, kk, lane, al2[1]);
            ldB(khB, nw * 16, kk, lane, bh);
            ldB(klB, nw * 16, kk, lane, bl);
#pragma unroll
            for (int mi = 0; mi < 2; mi++)
#pragma unroll
                for (int ni = 0; ni < 2; ni++)
                    mma16816(sacc[mi][ni], ah[mi], &bh[ni * 2]);
#pragma unroll
            for (int mi = 0; mi < 2; mi++)
#pragma unroll
                for (int ni = 0; ni < 2; ni++)
                    mma16816(sacc[mi][ni], ah[mi], &bl[ni * 2]);
#pragma unroll
            for (int mi = 0; mi < 2; mi++)
#pragma unroll
                for (int ni = 0; ni < 2; ni++)
                    mma16816(sacc[mi][ni], al2[mi], &bh[ni * 2]);
        }
#pragma unroll
        for (int mi = 0; mi < 2; mi++)
#pragma unroll
            for (int ni = 0; ni < 2; ni++) {
                int row = mw * 32 + mi * 16 + g;
                int col = kb * 64 + nw * 16 + ni * 8 + 2 * tg;
                *(float2*)(s_sc + (size_t)row * SC_ST + col) =
                    make_float2(sacc[mi][ni][0] * 0.125f, sacc[mi][ni][1] * 0.125f);
                *(float2*)(s_sc + (size_t)(row + 8) * SC_ST + col) =
                    make_float2(sacc[mi][ni][2] * 0.125f, sacc[mi][ni][3] * 0.125f);
            }
    }
    __syncthreads();

    LOAD_VBLK(0, 0);
    CP_COMMIT();

    // ---- softmax ----
    {
        int r = tid >> 2, j = tid & 3;
        float* row = s_sc + (size_t)r * SC_ST;
        float mx = -1e30f;
        for (int c = j; c < 512; c += 4) mx = fmaxf(mx, row[c]);
        mx = fmaxf(mx, __shfl_xor_sync(0xffffffffu, mx, 1));
        mx = fmaxf(mx, __shfl_xor_sync(0xffffffffu, mx, 2));
        float s = 0.f;
        for (int c = j; c < 512; c += 4) { float e = __expf(row[c] - mx); row[c] = e; s += e; }
        s += __shfl_xor_sync(0xffffffffu, s, 1);
        s += __shfl_xor_sync(0xffffffffu, s, 2);
        float inv = 1.f / s;
        for (int c = j; c < 512; c += 4) row[c] *= inv;
    }

    // ---- phase 2: ctx = P @ V ----
    float cacc[2][2][4];
#pragma unroll
    for (int mi = 0; mi < 2; mi++)
#pragma unroll
        for (int ni = 0; ni < 2; ni++)
#pragma unroll
            for (int x = 0; x < 4; x++) cacc[mi][ni][x] = 0.f;

    for (int kb = 0; kb < NKB; kb++) {
        CP_WAIT0();
        __syncthreads();
        if (kb + 1 < NKB) { LOAD_VBLK(kb + 1, (kb + 1) & 1); CP_COMMIT(); }

#pragma unroll
        for (int i = 0; i < 2; i++) {
            int c = tid + i * 256;
            int row = c >> 3, ch = c & 7;
            const float* src = s_sc + (size_t)row * SC_ST + kb * 64 + ch * 8;
            uint32_t hw[4], lw[4];
#pragma unroll
            for (int j = 0; j < 4; j++) {
                unsigned short h0, l0, h1, l1;
                split_bf16(src[2 * j], h0, l0);
                split_bf16(src[2 * j + 1], h1, l1);
                hw[j] = (uint32_t)h0 | ((uint32_t)h1 << 16);
                lw[j] = (uint32_t)l0 | ((uint32_t)l1 << 16);
            }
            uint32_t off = row * 128 + ch * 16;
            off ^= (off >> 3) & 0x70;
            *(uint4*)(sm8 + A_OFF_P + off) = make_uint4(hw[0], hw[1], hw[2], hw[3]);
            *(uint4*)(sm8 + A_OFF_P + 8192 + off) = make_uint4(lw[0], lw[1], lw[2], lw[3]);
        }
        __syncthreads();

        const uint32_t vhB = kvB + (kb & 1) * 16384, vlB = vhB + 8192;
#pragma unroll
        for (int kk = 0; kk < 4; kk++) {
            uint32_t ap[2][4], apl[2][4], bv[4], bvl[4];
            ldA(phB, mw * 32, kk, lane, ap[0]);
            ldA(phB, mw * 32 + 16, kk, lane, ap[1]);
            ldA(plB, mw * 32, kk, lane, apl[0]);
            ldA(plB, mw * 32 + 16, kk, lane, apl[1]);
            ldB(vhB, nw * 16, kk, lane, bv);
            ldB(vlB, nw * 16, kk, lane, bvl);
#pragma unroll
            for (int mi = 0; mi < 2; mi++)
#pragma unroll
                for (int ni = 0; ni < 2; ni++)
                    mma16816(cacc[mi][ni], ap[mi], &bv[ni * 2]);
#pragma unroll
            for (int mi = 0; mi < 2; mi++)
#pragma unroll
                for (int ni = 0; ni < 2; ni++)
                    mma16816(cacc[mi][ni], ap[mi], &bvl[ni * 2]);
#pragma unroll
            for (int mi = 0; mi < 2; mi++)
#pragma unroll
                for (int ni = 0; ni < 2; ni++)
                    mma16816(cacc[mi][ni], apl[mi], &bv[ni * 2]);
        }
    }

    // ---- epilogue: emit ctx hi/lo bf16 directly ----
#pragma unroll
    for (int mi = 0; mi < 2; mi++)
#pragma unroll
        for (int ni = 0; ni < 2; ni++) {
            int row = b * LMAX + q0 + mw * 32 + mi * 16 + g;
            int col = h * DH + nw * 16 + ni * 8 + 2 * tg;
#pragma unroll
            for (int half = 0; half < 2; half++) {
                size_t o = (size_t)(row + 8 * half) * Dm + col;
                unsigned short h0, l0, h1, l1;
                split_bf16(cacc[mi][ni][2 * half + 0], h0, l0);
                split_bf16(cacc[mi][ni][2 * half + 1], h1, l1);
                *(uint32_t*)(Ch + o) = (uint32_t)h0 | ((uint32_t)h1 << 16);
                *(uint32_t*)(Cl + o) = (uint32_t)l0 | ((uint32_t)l1 << 16);
            }
        }
}

// ---------------- LayerNorm: fp32 in -> hi/lo bf16 pair out ----------------------
__global__ __launch_bounds__(256)
void ln_kernel(const float* __restrict__ X, const float* __restrict__ gw,
               const float* __restrict__ bw, __nv_bfloat16* __restrict__ H,
               __nv_bfloat16* __restrict__ L) {
    __shared__ float red[8];
    __shared__ float stat[2];
    const int tid = threadIdx.x;
    const float* xp = X + (size_t)blockIdx.x * Dm + tid * 4;
    float4 v = *(const float4*)xp;

    float s = v.x + v.y + v.z + v.w;
#pragma unroll
    for (int o = 16; o; o >>= 1) s += __shfl_xor_sync(0xffffffffu, s, o);
    if ((tid & 31) == 0) red[tid >> 5] = s;
    __syncthreads();
    if (tid == 0) {
        float t = 0.f;
#pragma unroll
        for (int i = 0; i < 8; i++) t += red[i];
        stat[0] = t * (1.f / Dm);
    }
    __syncthreads();
    const float mu = stat[0];
    float d0 = v.x - mu, d1 = v.y - mu, d2 = v.z - mu, d3 = v.w - mu;

    float s2 = d0 * d0 + d1 * d1 + d2 * d2 + d3 * d3;
#pragma unroll
    for (int o = 16; o; o >>= 1) s2 += __shfl_xor_sync(0xffffffffu, s2, o);
    if ((tid & 31) == 0) red[tid >> 5] = s2;
    __syncthreads();
    if (tid == 0) {
        float t = 0.f;
#pragma unroll
        for (int i = 0; i < 8; i++) t += red[i];
        stat[1] = t * (1.f / Dm);
    }
    __syncthreads();
    const float rstd = rsqrtf(stat[1] + LN_EPS);

    float4 g4 = *(const float4*)(gw + tid * 4);
    float4 b4 = *(const float4*)(bw + tid * 4);
    float y[4];
    y[0] = d0 * rstd * g4.x + b4.x;
    y[1] = d1 * rstd * g4.y + b4.y;
    y[2] = d2 * rstd * g4.z + b4.z;
    y[3] = d3 * rstd * g4.w + b4.w;

    uint64_t hw = 0, lw = 0;
#pragma unroll
    for (int j = 0; j < 4; j++) {
        unsigned short hb, lb;
        split_bf16(y[j], hb, lb);
        hw |= (uint64_t)hb << (16 * j);
        lw |= (uint64_t)lb << (16 * j);
    }
    size_t o = (size_t)blockIdx.x * Dm + tid * 4;
    *(uint64_t*)(H + o) = hw;
    *(uint64_t*)(L + o) = lw;
}

// ---------------- segment mean ---------------------------------------------------
__global__ __launch_bounds__(256)
void seg_mean_kernel(const float* __restrict__ X, float* __restrict__ out) {
    const int b = blockIdx.y;
    const int d = blockIdx.x * 256 + threadIdx.x;
    const float* base = X + (size_t)(b * LMAX) * Dm + d;
    float s = 0.f;
#pragma unroll 8
    for (int l = 0; l < LMAX; l++) s += base[(size_t)l * Dm];
    out[b * Dm + d] = s * (1.f / (float)LMAX);
}

// ---------------- launch ---------------------------------------------------------
extern "C" void kernel_launch(void* const* d_in, const int* in_sizes, int n_in,
                              void* d_out, int out_size) {
    const float* struct_tok = (const float*)d_in[0];
    const float* text_tok   = (const float*)d_in[1];
    const float* in_proj_w  = (const float*)d_in[2];
    const float* in_proj_b  = (const float*)d_in[3];
    const float* attn_out_w = (const float*)d_in[4];
    const float* attn_out_b = (const float*)d_in[5];
    const float* ln_g       = (const float*)d_in[6];
    const float* ln_b       = (const float*)d_in[7];
    const float* proj_w     = (const float*)d_in[8];
    const float* proj_b     = (const float*)d_in[9];
    float* out = (float*)d_out;

    float *pV, *pF1, *pF2;
    __nv_bfloat16 *pSh, *pSl, *pTh, *pTl, *pQh, *pQl, *pKh, *pKl, *pVth, *pVtl;
    __nv_bfloat16 *pCh, *pCl, *pF1h, *pF1l;
    __nv_bfloat16 *pWqh, *pWql, *pWkh, *pWkl, *pWvh, *pWvl, *pWoh, *pWol, *pWph, *pWpl;
    cudaGetSymbolAddress((void**)&pV, g_V);
    cudaGetSymbolAddress((void**)&pF1, g_f1);
    cudaGetSymbolAddress((void**)&pF2, g_f2);
    cudaGetSymbolAddress((void**)&pSh, g_Sh);
    cudaGetSymbolAddress((void**)&pSl, g_Sl);
    cudaGetSymbolAddress((void**)&pTh, g_Th);
    cudaGetSymbolAddress((void**)&pTl, g_Tl);
    cudaGetSymbolAddress((void**)&pQh, g_Qh);
    cudaGetSymbolAddress((void**)&pQl, g_Ql);
    cudaGetSymbolAddress((void**)&pKh, g_Kh);
    cudaGetSymbolAddress((void**)&pKl, g_Kl);
    cudaGetSymbolAddress((void**)&pVth, g_Vth);
    cudaGetSymbolAddress((void**)&pVtl, g_Vtl);
    cudaGetSymbolAddress((void**)&pCh, g_Ch);
    cudaGetSymbolAddress((void**)&pCl, g_Cl);
    cudaGetSymbolAddress((void**)&pF1h, g_F1h);
    cudaGetSymbolAddress((void**)&pF1l, g_F1l);
    cudaGetSymbolAddress((void**)&pWqh, g_Wqh);
    cudaGetSymbolAddress((void**)&pWql, g_Wql);
    cudaGetSymbolAddress((void**)&pWkh, g_Wkh);
    cudaGetSymbolAddress((void**)&pWkl, g_Wkl);
    cudaGetSymbolAddress((void**)&pWvh, g_Wvh);
    cudaGetSymbolAddress((void**)&pWvl, g_Wvl);
    cudaGetSymbolAddress((void**)&pWoh, g_Woh);
    cudaGetSymbolAddress((void**)&pWol, g_Wol);
    cudaGetSymbolAddress((void**)&pWph, g_Wph);
    cudaGetSymbolAddress((void**)&pWpl, g_Wpl);
    cudaFuncSetAttribute(qkv_gemm,
                         cudaFuncAttributeMaxDynamicSharedMemorySize, SMEM_PGEMM);
    cudaFuncSetAttribute(pair_gemm,
                         cudaFuncAttributeMaxDynamicSharedMemorySize, SMEM_PGEMM);
    cudaFuncSetAttribute(attn_mma,
                         cudaFuncAttributeMaxDynamicSharedMemorySize, SMEM_ATTN2);

    const int n4S = Ntok * Dm / 4;
    const int n4T = Bq * LTxt * Dm / 4;
    const int n4W = Dm * Dm / 4;

    const dim3 gQ(Dm / 128, Ntok / 128);           // (8, 32)

    // operand splits
    cvt_split<<<(n4T + 255) / 256, 256>>>(text_tok, pTh, pTl, n4T);
    cvt_split<<<(n4S + 255) / 256, 256>>>(struct_tok, pSh, pSl, n4S);
    cvt_split_w<<<dim3((n4W + 255) / 256, 5), 256>>>(
        in_proj_w, attn_out_w, proj_w,
        pWqh, pWql, pWkh, pWkl, pWvh, pWvl, pWoh, pWol, pWph, pWpl);

    // fused QKV projections: one 1280-CTA launch
    qkv_gemm<<<1280, 256, SMEM_PGEMM>>>(pSh, pSl, pTh, pTl,
                                        pWqh, pWql, pWkh, pWkl, pWvh, pWvl,
                                        in_proj_b, pV, pQh, pQl, pKh, pKl);

    v_transpose_split<<<dim3(LTxt / 32, Dm / 32, Bq), 256>>>(pV, pVth, pVtl);

    // attention (HMMA split-bf16) -> ctx hi/lo
    attn_mma<<<dim3(LMAX / 64, Hh, Bq), 256, SMEM_ATTN2>>>(pQh, pQl, pKh, pKl,
                                                           pVth, pVtl, pCh, pCl);

    // attn_out GEMM + LN + proj GEMM
    pair_gemm<<<gQ, 256, SMEM_PGEMM>>>(pCh, pCl, pWoh, pWol, attn_out_b, pF1);
    ln_kernel<<<Ntok, 256>>>(pF1, ln_g, ln_b, pF1h, pF1l);
    pair_gemm<<<gQ, 256, SMEM_PGEMM>>>(pF1h, pF1l, pWph, pWpl, proj_b, pF2);

    // per-batch mean -> output (16, 1024)
    seg_mean_kernel<<<dim3(Dm / 256, Bq), 256>>>(pF2, out);

    (void)in_sizes; (void)n_in; (void)out_size;
}